// round 1
// baseline (speedup 1.0000x reference)
#include <cuda_runtime.h>
#include <math.h>

#define B_   64
#define S_   256
#define H_   1024
#define ENC_ 1024
#define E_   512
#define V_   32000
#define XDIM_ (E_ + ENC_)        // 1536
#define FDIM_ (H_ + ENC_ + E_)   // 2560
#define G4H_  (4 * H_)           // 4096

// ---------------- scratch (device globals; no allocation allowed) ----------
// layout: query | x0 | feat | gates | h0 | energy
#define OFF_QUERY  0
#define OFF_X0     (OFF_QUERY + B_ * H_)
#define OFF_FEAT   (OFF_X0 + B_ * XDIM_)
#define OFF_GATES  (OFF_FEAT + B_ * FDIM_)
#define OFF_H0     (OFF_GATES + B_ * G4H_)
#define OFF_ENERGY (OFF_H0 + B_ * H_)
#define SCRATCH_TOTAL (OFF_ENERGY + B_ * S_)

__device__ float g_scratch[SCRATCH_TOTAL];

// ---------------- generic fp32 GEMM: C[64,N] = A[64,K] @ W[N,K]^T ----------
// block tile 64 x BN, BK=16, threads 256 (16x16), micro-tile 4 x TN.
template<int BN, int TN, bool ACC>
__global__ void gemm_m64(const float* __restrict__ A,
                         const float* __restrict__ W,
                         float* __restrict__ C,
                         const float* __restrict__ bias1,
                         const float* __restrict__ bias2,
                         int N, int K) {
    constexpr int BK = 16;
    __shared__ float As[BK][64 + 4];
    __shared__ float Ws[BK][BN + 4];

    const int tid = threadIdx.x;
    const int tx = tid & 15;
    const int ty = tid >> 4;
    const int n0 = blockIdx.x * BN;

    float acc[4][TN];
#pragma unroll
    for (int i = 0; i < 4; i++)
#pragma unroll
        for (int j = 0; j < TN; j++) acc[i][j] = 0.f;

    for (int k0 = 0; k0 < K; k0 += BK) {
        __syncthreads();
        // load A chunk: 64 rows x 16 k  (one float4 per thread)
        {
            int m  = tid >> 2;
            int k4 = tid & 3;
            float4 a = *reinterpret_cast<const float4*>(A + (long)m * K + k0 + k4 * 4);
            As[k4 * 4 + 0][m] = a.x;
            As[k4 * 4 + 1][m] = a.y;
            As[k4 * 4 + 2][m] = a.z;
            As[k4 * 4 + 3][m] = a.w;
        }
        // load W chunk: BN rows x 16 k
        for (int idx = tid; idx < BN * 4; idx += 256) {
            int n  = idx >> 2;
            int k4 = idx & 3;
            float4 w = *reinterpret_cast<const float4*>(W + (long)(n0 + n) * K + k0 + k4 * 4);
            Ws[k4 * 4 + 0][n] = w.x;
            Ws[k4 * 4 + 1][n] = w.y;
            Ws[k4 * 4 + 2][n] = w.z;
            Ws[k4 * 4 + 3][n] = w.w;
        }
        __syncthreads();

#pragma unroll
        for (int k = 0; k < BK; k++) {
            float4 a = *reinterpret_cast<const float4*>(&As[k][ty * 4]);
            float av[4] = {a.x, a.y, a.z, a.w};
            float wv[TN];
            if constexpr (TN == 1) {
                wv[0] = Ws[k][tx];
            } else {
#pragma unroll
                for (int jj = 0; jj < TN; jj += 4) {
                    float4 w = *reinterpret_cast<const float4*>(&Ws[k][tx * TN + jj]);
                    wv[jj + 0] = w.x; wv[jj + 1] = w.y;
                    wv[jj + 2] = w.z; wv[jj + 3] = w.w;
                }
            }
#pragma unroll
            for (int i = 0; i < 4; i++)
#pragma unroll
                for (int j = 0; j < TN; j++)
                    acc[i][j] = fmaf(av[i], wv[j], acc[i][j]);
        }
    }

    // epilogue
#pragma unroll
    for (int i = 0; i < 4; i++) {
        int m = ty * 4 + i;
#pragma unroll
        for (int j = 0; j < TN; j++) {
            int n = n0 + tx * TN + j;
            float val = acc[i][j];
            if (bias1) val += bias1[n];
            if (bias2) val += bias2[n];
            if (ACC)   val += C[(long)m * N + n];
            C[(long)m * N + n] = val;
        }
    }
}

// ---------------- fused keys + energy -------------------------------------
// energy[b,s] = sum_h v[h] * tanh(query[b,h] + sum_e Wk[h,e]*enc[b,s,e])
// block = (s-tile of 64, b); loops over h in tiles of 128 kept in registers.
__global__ void energy_kernel(const float* __restrict__ enc,
                              const float* __restrict__ Wk,
                              const float* __restrict__ vvec,
                              const float* __restrict__ query,
                              float* __restrict__ energy) {
    constexpr int BK = 16, BN = 128;
    __shared__ float As[BK][64 + 4];
    __shared__ float Ws[BK][BN + 4];
    __shared__ float esum[64];

    const int b  = blockIdx.y;
    const int s0 = blockIdx.x * 64;
    const float* A = enc + ((long)b * S_ + s0) * ENC_;

    const int tid = threadIdx.x;
    const int tx = tid & 15;
    const int ty = tid >> 4;

    if (tid < 64) esum[tid] = 0.f;

    for (int ht = 0; ht < H_ / BN; ht++) {
        float acc[4][8];
#pragma unroll
        for (int i = 0; i < 4; i++)
#pragma unroll
            for (int j = 0; j < 8; j++) acc[i][j] = 0.f;

        const float* W = Wk + (long)ht * BN * ENC_;

        for (int k0 = 0; k0 < ENC_; k0 += BK) {
            __syncthreads();
            {
                int m  = tid >> 2;
                int k4 = tid & 3;
                float4 a = *reinterpret_cast<const float4*>(A + (long)m * ENC_ + k0 + k4 * 4);
                As[k4 * 4 + 0][m] = a.x;
                As[k4 * 4 + 1][m] = a.y;
                As[k4 * 4 + 2][m] = a.z;
                As[k4 * 4 + 3][m] = a.w;
            }
#pragma unroll
            for (int r = 0; r < 2; r++) {
                int idx = tid + r * 256;
                int n  = idx >> 2;
                int k4 = idx & 3;
                float4 w = *reinterpret_cast<const float4*>(W + (long)n * ENC_ + k0 + k4 * 4);
                Ws[k4 * 4 + 0][n] = w.x;
                Ws[k4 * 4 + 1][n] = w.y;
                Ws[k4 * 4 + 2][n] = w.z;
                Ws[k4 * 4 + 3][n] = w.w;
            }
            __syncthreads();

#pragma unroll
            for (int k = 0; k < BK; k++) {
                float4 a = *reinterpret_cast<const float4*>(&As[k][ty * 4]);
                float av[4] = {a.x, a.y, a.z, a.w};
                float4 w0 = *reinterpret_cast<const float4*>(&Ws[k][tx * 8]);
                float4 w1 = *reinterpret_cast<const float4*>(&Ws[k][tx * 8 + 4]);
                float wv[8] = {w0.x, w0.y, w0.z, w0.w, w1.x, w1.y, w1.z, w1.w};
#pragma unroll
                for (int i = 0; i < 4; i++)
#pragma unroll
                    for (int j = 0; j < 8; j++)
                        acc[i][j] = fmaf(av[i], wv[j], acc[i][j]);
            }
        }

        // epilogue for this h-tile: reduce v[h]*tanh(q+k) into esum[s]
        float vv[8], qv[8];
#pragma unroll
        for (int j = 0; j < 8; j++) {
            int h = ht * BN + tx * 8 + j;
            vv[j] = vvec[h];
            qv[j] = query[b * H_ + h];
        }
#pragma unroll
        for (int i = 0; i < 4; i++) {
            float p = 0.f;
#pragma unroll
            for (int j = 0; j < 8; j++)
                p += vv[j] * tanhf(qv[j] + acc[i][j]);
            atomicAdd(&esum[ty * 4 + i], p);
        }
    }

    __syncthreads();
    if (tid < 64) energy[b * S_ + s0 + tid] = esum[tid];
}

// ---------------- softmax over S with masking -------------------------------
__global__ void softmax_kernel(const float* __restrict__ energy,
                               const int* __restrict__ mask,
                               float* __restrict__ out_attn) {
    __shared__ float red[256];
    const int b = blockIdx.x;
    const int s = threadIdx.x;

    float val = energy[b * S_ + s];
    if (mask[b * S_ + s] == 0) val = -1e10f;

    red[s] = val;
    __syncthreads();
#pragma unroll
    for (int off = 128; off > 0; off >>= 1) {
        if (s < off) red[s] = fmaxf(red[s], red[s + off]);
        __syncthreads();
    }
    float mx = red[0];
    __syncthreads();

    float ex = expf(val - mx);
    red[s] = ex;
    __syncthreads();
#pragma unroll
    for (int off = 128; off > 0; off >>= 1) {
        if (s < off) red[s] += red[s + off];
        __syncthreads();
    }
    float w = ex / red[0];
    out_attn[b * S_ + s] = w;
}

// ---------------- context = attn @ enc; scatter into x0 and feat ------------
__global__ void context_kernel(const float* __restrict__ enc,
                               const float* __restrict__ attn,
                               float* __restrict__ x0,
                               float* __restrict__ feat) {
    __shared__ float w[S_];
    const int b = blockIdx.x;
    const int tid = threadIdx.x;
    w[tid] = attn[b * S_ + tid];
    __syncthreads();

    const float* eb = enc + (long)b * S_ * ENC_;
    for (int e = tid; e < ENC_; e += 256) {
        float acc = 0.f;
#pragma unroll 8
        for (int s = 0; s < S_; s++)
            acc = fmaf(w[s], eb[(long)s * ENC_ + e], acc);
        x0[b * XDIM_ + E_ + e]  = acc;
        feat[b * FDIM_ + H_ + e] = acc;
    }
}

// ---------------- embedding gather into x0 and feat -------------------------
__global__ void embed_kernel(const int* __restrict__ tok,
                             const float* __restrict__ emb,
                             float* __restrict__ x0,
                             float* __restrict__ feat) {
    const int b = blockIdx.x;
    const int t = tok[b];
    for (int j = threadIdx.x; j < E_; j += 128) {
        float val = emb[(long)t * E_ + j];
        x0[b * XDIM_ + j] = val;
        feat[b * FDIM_ + (H_ + ENC_) + j] = val;
    }
}

// ---------------- LSTM pointwise --------------------------------------------
__global__ void lstm_kernel(const float* __restrict__ gates,
                            const float* __restrict__ c_prev,
                            float* __restrict__ c_out,
                            float* __restrict__ h_out_a,   // stride H
                            float* __restrict__ h_out_b,   // stride sb
                            int sb) {
    const int b = blockIdx.x;
    const int idx = blockIdx.y * 256 + threadIdx.x;

    float gi = gates[b * G4H_ + idx];
    float gf = gates[b * G4H_ + H_ + idx];
    float gg = gates[b * G4H_ + 2 * H_ + idx];
    float go = gates[b * G4H_ + 3 * H_ + idx];
    float c  = c_prev[b * H_ + idx];

    float si = 1.f / (1.f + expf(-gi));
    float sf = 1.f / (1.f + expf(-gf));
    float so = 1.f / (1.f + expf(-go));

    float cn = sf * c + si * tanhf(gg);
    float hn = so * tanhf(cn);

    c_out[b * H_ + idx]   = cn;
    h_out_a[b * H_ + idx] = hn;
    h_out_b[b * sb + idx] = hn;
}

// ---------------- launch -----------------------------------------------------
extern "C" void kernel_launch(void* const* d_in, const int* in_sizes, int n_in,
                              void* d_out, int out_size) {
    const int*   tok    = (const int*)  d_in[0];
    const float* hidden = (const float*)d_in[1];
    const float* cell   = (const float*)d_in[2];
    const float* enc    = (const float*)d_in[3];
    const int*   mask   = (const int*)  d_in[4];
    const float* emb    = (const float*)d_in[5];
    const float* Wq     = (const float*)d_in[6];
    const float* Wk     = (const float*)d_in[7];
    const float* v      = (const float*)d_in[8];
    const float* Wih0   = (const float*)d_in[9];
    const float* Whh0   = (const float*)d_in[10];
    const float* bih0   = (const float*)d_in[11];
    const float* bhh0   = (const float*)d_in[12];
    const float* Wih1   = (const float*)d_in[13];
    const float* Whh1   = (const float*)d_in[14];
    const float* bih1   = (const float*)d_in[15];
    const float* bhh1   = (const float*)d_in[16];
    const float* Wout   = (const float*)d_in[17];
    const float* bout   = (const float*)d_in[18];

    float* out      = (float*)d_out;
    float* out_pred = out;                                  // [B, V]
    float* out_hid  = out + (long)B_ * V_;                  // [2, B, H]
    float* out_cell = out_hid + 2 * B_ * H_;                // [2, B, H]
    float* out_attn = out_cell + 2 * B_ * H_;               // [B, S]

    void* sp = nullptr;
    cudaGetSymbolAddress(&sp, g_scratch);
    float* scratch = (float*)sp;
    float* query  = scratch + OFF_QUERY;
    float* x0     = scratch + OFF_X0;
    float* feat   = scratch + OFF_FEAT;
    float* gates  = scratch + OFF_GATES;
    float* h0     = scratch + OFF_H0;
    float* energy = scratch + OFF_ENERGY;

    // 1. embedding gather -> x0[:, :512], feat[:, 2048:2560]
    embed_kernel<<<B_, 128>>>(tok, emb, x0, feat);

    // 2. query = hidden[1] @ Wq^T   [64, 1024]
    gemm_m64<16, 1, false><<<H_ / 16, 256>>>(hidden + B_ * H_, Wq, query,
                                             nullptr, nullptr, H_, H_);

    // 3. fused keys GEMM + tanh-attention energy   [64, 256]
    energy_kernel<<<dim3(S_ / 64, B_), 256>>>(enc, Wk, v, query, energy);

    // 4. masked softmax -> attn (written straight to output region)
    softmax_kernel<<<B_, 256>>>(energy, mask, out_attn);

    // 5. context = attn @ enc  -> x0[:, 512:1536], feat[:, 1024:2048]
    context_kernel<<<B_, 256>>>(enc, out_attn, x0, feat);

    // 6. layer-0 gates = x0 @ Wih0^T + bih0 + bhh0 ; += hidden[0] @ Whh0^T
    gemm_m64<64, 4, false><<<G4H_ / 64, 256>>>(x0, Wih0, gates, bih0, bhh0, G4H_, XDIM_);
    gemm_m64<64, 4, true><<<G4H_ / 64, 256>>>(hidden, Whh0, gates, nullptr, nullptr, G4H_, H_);

    // 7. LSTM cell 0: h0 -> out_hid[0], scratch h0 ; c0 -> out_cell[0]
    lstm_kernel<<<dim3(B_, H_ / 256), 256>>>(gates, cell, out_cell, out_hid, h0, H_);

    // 8. layer-1 gates = h0 @ Wih1^T + bih1 + bhh1 ; += hidden[1] @ Whh1^T
    gemm_m64<64, 4, false><<<G4H_ / 64, 256>>>(h0, Wih1, gates, bih1, bhh1, G4H_, H_);
    gemm_m64<64, 4, true><<<G4H_ / 64, 256>>>(hidden + B_ * H_, Whh1, gates, nullptr, nullptr, G4H_, H_);

    // 9. LSTM cell 1: h1 -> out_hid[1], feat[:, 0:1024] ; c1 -> out_cell[1]
    lstm_kernel<<<dim3(B_, H_ / 256), 256>>>(gates, cell + B_ * H_, out_cell + B_ * H_,
                                             out_hid + B_ * H_, feat, FDIM_);

    // 10. prediction = feat @ Wout^T + bout   [64, 32000]
    gemm_m64<128, 8, false><<<V_ / 128, 256>>>(feat, Wout, out_pred, bout, nullptr, V_, FDIM_);
}

// round 3
// speedup vs baseline: 2.6630x; 2.6630x over previous
#include <cuda_runtime.h>
#include <cuda_bf16.h>
#include <math.h>
#include <stdint.h>

#define B_   64
#define S_   256
#define H_   1024
#define ENC_ 1024
#define E_   512
#define V_   32000
#define XDIM_ (E_ + ENC_)        // 1536
#define FDIM_ (H_ + ENC_ + E_)   // 2560
#define G4H_  (4 * H_)           // 4096

// ---------------- scratch (device globals; no allocation allowed) ----------
#define OFF_QUERY  0
#define OFF_X0     (OFF_QUERY + B_ * H_)
#define OFF_FEAT   (OFF_X0 + B_ * XDIM_)
#define OFF_GATES  (OFF_FEAT + B_ * FDIM_)
#define OFF_H0     (OFF_GATES + B_ * G4H_)
#define OFF_ENERGY (OFF_H0 + B_ * H_)
#define SCRATCH_TOTAL (OFF_ENERGY + B_ * S_)

__device__ __align__(16) float g_scratch[SCRATCH_TOTAL];

// bf16 split buffers
__device__ __align__(16) __nv_bfloat16 g_enc_hi[(long)B_ * S_ * ENC_];
__device__ __align__(16) __nv_bfloat16 g_enc_lo[(long)B_ * S_ * ENC_];
__device__ __align__(16) __nv_bfloat16 g_wk_hi[H_ * ENC_];
__device__ __align__(16) __nv_bfloat16 g_wk_lo[H_ * ENC_];
__device__ __align__(16) __nv_bfloat16 g_feat_hi[B_ * FDIM_];
__device__ __align__(16) __nv_bfloat16 g_feat_lo[B_ * FDIM_];

// ===================== low-level helpers =====================================
__device__ __forceinline__ uint32_t smem_to_u32(const void* p) {
    uint32_t a;
    asm("{ .reg .u64 t; cvta.to.shared.u64 t, %1; cvt.u32.u64 %0, t; }" : "=r"(a) : "l"(p));
    return a;
}

#define CP16(dst_u32, src_ptr) \
    asm volatile("cp.async.cg.shared.global [%0], [%1], 16;" :: "r"(dst_u32), "l"(src_ptr))
#define CP_COMMIT() asm volatile("cp.async.commit_group;" ::: "memory")
template<int N> __device__ __forceinline__ void cp_wait() {
    asm volatile("cp.async.wait_group %0;" :: "n"(N) : "memory");
}

__device__ __forceinline__ void ldmx4(uint32_t addr, uint32_t r[4]) {
    asm volatile("ldmatrix.sync.aligned.m8n8.x4.shared.b16 {%0,%1,%2,%3}, [%4];"
        : "=r"(r[0]), "=r"(r[1]), "=r"(r[2]), "=r"(r[3]) : "r"(addr));
}

__device__ __forceinline__ void mma16816(float* c, const uint32_t a[4],
                                         uint32_t b0, uint32_t b1) {
    asm volatile("mma.sync.aligned.m16n8k16.row.col.f32.bf16.bf16.f32 "
        "{%0,%1,%2,%3}, {%4,%5,%6,%7}, {%8,%9}, {%0,%1,%2,%3};"
        : "+f"(c[0]), "+f"(c[1]), "+f"(c[2]), "+f"(c[3])
        : "r"(a[0]), "r"(a[1]), "r"(a[2]), "r"(a[3]), "r"(b0), "r"(b1));
}

#define STS128(addr, a, b, c, d) \
    asm volatile("st.shared.v4.b32 [%0], {%1,%2,%3,%4};" \
        :: "r"(addr), "r"(a), "r"(b), "r"(c), "r"(d) : "memory")

// swizzled byte offset within a 128B-row tile: chunk16' = chunk16 ^ (row%8)
__device__ __forceinline__ uint32_t swz(int row, int chunk16) {
    return (uint32_t)(row * 128 + ((chunk16 ^ (row & 7)) * 16));
}

__device__ __forceinline__ void split2(float a, float b, uint32_t& hi, uint32_t& lo) {
    __nv_bfloat162 h2 = __floats2bfloat162_rn(a, b);
    float ra = a - __bfloat162float(__low2bfloat16(h2));
    float rb = b - __bfloat162float(__high2bfloat16(h2));
    __nv_bfloat162 l2 = __floats2bfloat162_rn(ra, rb);
    hi = *reinterpret_cast<uint32_t*>(&h2);
    lo = *reinterpret_cast<uint32_t*>(&l2);
}

// ===================== energy MMA kernel =====================================
// Block tile: 128 s-rows x 128 h-cols, K=1024 over 16 K-tiles of 64.
// C = enc_hi·wk_hi^T + enc_lo·wk_hi^T + enc_hi·wk_lo^T (fp32 accum)
// epilogue: energy[b,s] += sum_h v[h]*tanh(q[b,h] + C[s,h])
// smem: 1KB header (vs,qs) | 2 stages x {Ah,Al,Bh,Bl} x 16KB
#define EK_TILE  16384
#define EK_STAGE (4 * EK_TILE)
#define EK_SMEM_BYTES (2048 + 2 * EK_STAGE)

__device__ __forceinline__ void ek_load_stage(const __nv_bfloat16* eh, const __nv_bfloat16* el,
                                              const __nv_bfloat16* wh, const __nv_bfloat16* wl,
                                              long m0, int n0, int c0, uint32_t stg) {
    const int tid = threadIdx.x;
#pragma unroll
    for (int i = 0; i < 4; i++) {
        int idx = tid + i * 256;              // 1024 chunks of 16B per operand
        int r = idx >> 3, c = idx & 7;
        uint32_t off = swz(r, c);
        long asrc = (m0 + r) * (long)ENC_ + c0 + c * 8;
        CP16(stg + off, eh + asrc);
        CP16(stg + EK_TILE + off, el + asrc);
        long bsrc = (long)(n0 + r) * ENC_ + c0 + c * 8;
        CP16(stg + 2 * EK_TILE + off, wh + bsrc);
        CP16(stg + 3 * EK_TILE + off, wl + bsrc);
    }
}

__device__ __forceinline__ void ek_compute(uint32_t stg, float c[2][8][4],
                                           int warp_m, int warp_n, int lane) {
    const uint32_t Ah = stg, Al = stg + EK_TILE;
    const uint32_t Bh = stg + 2 * EK_TILE, Bl = stg + 3 * EK_TILE;
    const int lm = lane & 15, lh = lane >> 4;
#pragma unroll
    for (int ks = 0; ks < 4; ks++) {
        const int ch = ks * 2 + lh;
        uint32_t ah[2][4], al[2][4];
#pragma unroll
        for (int mf = 0; mf < 2; mf++) {
            uint32_t off = swz(warp_m + mf * 16 + lm, ch);
            ldmx4(Ah + off, ah[mf]);
            ldmx4(Al + off, al[mf]);
        }
        uint32_t bb[4][4];
#pragma unroll
        for (int nf2 = 0; nf2 < 4; nf2++) {
            uint32_t off = swz(warp_n + nf2 * 16 + lm, ch);
            ldmx4(Bh + off, bb[nf2]);
        }
#pragma unroll
        for (int nf2 = 0; nf2 < 4; nf2++)
#pragma unroll
            for (int mf = 0; mf < 2; mf++) {
                mma16816(c[mf][nf2 * 2 + 0], ah[mf], bb[nf2][0], bb[nf2][2]);
                mma16816(c[mf][nf2 * 2 + 1], ah[mf], bb[nf2][1], bb[nf2][3]);
                mma16816(c[mf][nf2 * 2 + 0], al[mf], bb[nf2][0], bb[nf2][2]);
                mma16816(c[mf][nf2 * 2 + 1], al[mf], bb[nf2][1], bb[nf2][3]);
            }
#pragma unroll
        for (int nf2 = 0; nf2 < 4; nf2++) {
            uint32_t off = swz(warp_n + nf2 * 16 + lm, ch);
            ldmx4(Bl + off, bb[nf2]);
        }
#pragma unroll
        for (int nf2 = 0; nf2 < 4; nf2++)
#pragma unroll
            for (int mf = 0; mf < 2; mf++) {
                mma16816(c[mf][nf2 * 2 + 0], ah[mf], bb[nf2][0], bb[nf2][2]);
                mma16816(c[mf][nf2 * 2 + 1], ah[mf], bb[nf2][1], bb[nf2][3]);
            }
    }
}

__global__ __launch_bounds__(256, 1)
void energy_mma_kernel(const __nv_bfloat16* __restrict__ eh,
                       const __nv_bfloat16* __restrict__ el,
                       const __nv_bfloat16* __restrict__ wh,
                       const __nv_bfloat16* __restrict__ wl,
                       const float* __restrict__ vvec,
                       const float* __restrict__ query,
                       float* __restrict__ energy) {
    extern __shared__ char smem[];
    uint32_t sb = smem_to_u32(smem);
    uint32_t tiles = (sb + 1024 + 1023) & ~1023u;

    const int tid = threadIdx.x;
    const int wid = tid >> 5, lane = tid & 31;
    const int warp_m = (wid & 3) * 32;
    const int warp_n = (wid >> 2) * 64;

    const int n0 = blockIdx.x * 128;          // h offset
    const long m0 = (long)blockIdx.y * 128;   // global (b*S+s) offset
    const int b = blockIdx.y >> 1;
    const int sbase = (blockIdx.y & 1) * 128;

    float* vs = (float*)smem;
    float* qs = vs + 128;
    if (tid < 128) { vs[tid] = vvec[n0 + tid]; qs[tid] = query[b * H_ + n0 + tid]; }

    float c[2][8][4];
#pragma unroll
    for (int i = 0; i < 2; i++)
#pragma unroll
        for (int j = 0; j < 8; j++)
#pragma unroll
            for (int k = 0; k < 4; k++) c[i][j][k] = 0.f;

    ek_load_stage(eh, el, wh, wl, m0, n0, 0, tiles);
    CP_COMMIT();

    const int KT = ENC_ / 64;  // 16
    for (int kt = 0; kt < KT; kt++) {
        if (kt + 1 < KT) {
            ek_load_stage(eh, el, wh, wl, m0, n0, (kt + 1) * 64,
                          tiles + ((kt + 1) & 1) * EK_STAGE);
            CP_COMMIT();
            cp_wait<1>();
        } else {
            cp_wait<0>();
        }
        __syncthreads();
        ek_compute(tiles + (kt & 1) * EK_STAGE, c, warp_m, warp_n, lane);
        __syncthreads();
    }

    // epilogue: v*tanh(q + C), reduce over h
#pragma unroll
    for (int mf = 0; mf < 2; mf++) {
        float s_lo = 0.f, s_hi = 0.f;
#pragma unroll
        for (int nf = 0; nf < 8; nf++) {
            int col = warp_n + nf * 8 + (lane & 3) * 2;
            float v0 = vs[col], v1 = vs[col + 1];
            float q0 = qs[col], q1 = qs[col + 1];
            s_lo += v0 * tanhf(q0 + c[mf][nf][0]) + v1 * tanhf(q1 + c[mf][nf][1]);
            s_hi += v0 * tanhf(q0 + c[mf][nf][2]) + v1 * tanhf(q1 + c[mf][nf][3]);
        }
        s_lo += __shfl_xor_sync(0xffffffff, s_lo, 1);
        s_lo += __shfl_xor_sync(0xffffffff, s_lo, 2);
        s_hi += __shfl_xor_sync(0xffffffff, s_hi, 1);
        s_hi += __shfl_xor_sync(0xffffffff, s_hi, 2);
        if ((lane & 3) == 0) {
            int r0 = warp_m + mf * 16 + (lane >> 2);
            atomicAdd(&energy[b * S_ + sbase + r0], s_lo);
            atomicAdd(&energy[b * S_ + sbase + r0 + 8], s_hi);
        }
    }
}

// ===================== Wout MMA kernel =======================================
// Block tile: 64 x 128, K=2560 over 40 K-tiles of 64.
// A = pre-split feat (bf16), B = Wout fp32 split in-kernel (read exactly once).
#define WO_A_TILE 8192
#define WO_B_TILE 16384
#define WO_STAGE  (2 * WO_A_TILE + 2 * WO_B_TILE)   // 48KB
#define WO_SMEM_BYTES (1024 + 2 * WO_STAGE)

__device__ __forceinline__ void wo_load_A(const __nv_bfloat16* fh, const __nv_bfloat16* fl,
                                          int c0, uint32_t stg) {
    const int tid = threadIdx.x;
#pragma unroll
    for (int i = 0; i < 2; i++) {
        int idx = tid + i * 256;              // 512 chunks per operand
        int r = idx >> 3, cc = idx & 7;
        uint32_t off = swz(r, cc);
        long src = (long)r * FDIM_ + c0 + cc * 8;
        CP16(stg + off, fh + src);
        CP16(stg + WO_A_TILE + off, fl + src);
    }
}

__global__ __launch_bounds__(256, 1)
void wout_mma_kernel(const __nv_bfloat16* __restrict__ fh,
                     const __nv_bfloat16* __restrict__ fl,
                     const float* __restrict__ Wout,
                     const float* __restrict__ bout,
                     float* __restrict__ out_pred) {
    extern __shared__ char smem[];
    uint32_t sb = smem_to_u32(smem);
    uint32_t tiles = (sb + 1023) & ~1023u;

    const int tid = threadIdx.x;
    const int wid = tid >> 5, lane = tid & 31;
    const int warp_m = (wid & 1) * 32;
    const int warp_n = (wid >> 1) * 32;
    const int n0 = blockIdx.x * 128;

    const int br = tid >> 1;        // B row handled by this thread (0..127)
    const int bhalf = tid & 1;      // k half (0..31 / 32..63)
    const float* wrow = Wout + (long)(n0 + br) * FDIM_ + bhalf * 32;

    float c[2][4][4];
#pragma unroll
    for (int i = 0; i < 2; i++)
#pragma unroll
        for (int j = 0; j < 4; j++)
#pragma unroll
            for (int k = 0; k < 4; k++) c[i][j][k] = 0.f;

    // prefetch stage 0
    wo_load_A(fh, fl, 0, tiles);
    CP_COMMIT();
    float4 nb[8];
#pragma unroll
    for (int j = 0; j < 4; j++) {
        nb[2 * j]     = *reinterpret_cast<const float4*>(wrow + j * 8);
        nb[2 * j + 1] = *reinterpret_cast<const float4*>(wrow + j * 8 + 4);
    }

    const int KT = FDIM_ / 64;  // 40
    for (int kt = 0; kt < KT; kt++) {
        uint32_t stg = tiles + (kt & 1) * WO_STAGE;
        if (kt + 1 < KT) {
            wo_load_A(fh, fl, (kt + 1) * 64, tiles + ((kt + 1) & 1) * WO_STAGE);
            CP_COMMIT();
        }
        // convert this stage's B registers -> smem bf16 hi/lo
        uint32_t Bh = stg + 2 * WO_A_TILE, Bl = Bh + WO_B_TILE;
#pragma unroll
        for (int j = 0; j < 4; j++) {
            float4 v0 = nb[2 * j], v1 = nb[2 * j + 1];
            uint4 Hq, Lq;
            split2(v0.x, v0.y, Hq.x, Lq.x);
            split2(v0.z, v0.w, Hq.y, Lq.y);
            split2(v1.x, v1.y, Hq.z, Lq.z);
            split2(v1.z, v1.w, Hq.w, Lq.w);
            uint32_t off = swz(br, bhalf * 4 + j);
            STS128(Bh + off, Hq.x, Hq.y, Hq.z, Hq.w);
            STS128(Bl + off, Lq.x, Lq.y, Lq.z, Lq.w);
        }
        if (kt + 1 < KT) cp_wait<1>(); else cp_wait<0>();
        __syncthreads();
        // prefetch next B f32 (overlaps compute)
        if (kt + 1 < KT) {
            const float* wn = wrow + (kt + 1) * 64;
#pragma unroll
            for (int j = 0; j < 4; j++) {
                nb[2 * j]     = *reinterpret_cast<const float4*>(wn + j * 8);
                nb[2 * j + 1] = *reinterpret_cast<const float4*>(wn + j * 8 + 4);
            }
        }
        // compute
        {
            const uint32_t Ah = stg, Al = stg + WO_A_TILE;
            const int lm = lane & 15, lh = lane >> 4;
#pragma unroll
            for (int ks = 0; ks < 4; ks++) {
                const int ch = ks * 2 + lh;
                uint32_t ah[2][4], al[2][4];
#pragma unroll
                for (int mf = 0; mf < 2; mf++) {
                    uint32_t off = swz(warp_m + mf * 16 + lm, ch);
                    ldmx4(Ah + off, ah[mf]);
                    ldmx4(Al + off, al[mf]);
                }
                uint32_t bb[2][4];
#pragma unroll
                for (int nf2 = 0; nf2 < 2; nf2++) {
                    uint32_t off = swz(warp_n + nf2 * 16 + lm, ch);
                    ldmx4(Bh + off, bb[nf2]);
                }
#pragma unroll
                for (int nf2 = 0; nf2 < 2; nf2++)
#pragma unroll
                    for (int mf = 0; mf < 2; mf++) {
                        mma16816(c[mf][nf2 * 2 + 0], ah[mf], bb[nf2][0], bb[nf2][2]);
                        mma16816(c[mf][nf2 * 2 + 1], ah[mf], bb[nf2][1], bb[nf2][3]);
                        mma16816(c[mf][nf2 * 2 + 0], al[mf], bb[nf2][0], bb[nf2][2]);
                        mma16816(c[mf][nf2 * 2 + 1], al[mf], bb[nf2][1], bb[nf2][3]);
                    }
#pragma unroll
                for (int nf2 = 0; nf2 < 2; nf2++) {
                    uint32_t off = swz(warp_n + nf2 * 16 + lm, ch);
                    ldmx4(Bl + off, bb[nf2]);
                }
#pragma unroll
                for (int nf2 = 0; nf2 < 2; nf2++)
#pragma unroll
                    for (int mf = 0; mf < 2; mf++) {
                        mma16816(c[mf][nf2 * 2 + 0], ah[mf], bb[nf2][0], bb[nf2][2]);
                        mma16816(c[mf][nf2 * 2 + 1], ah[mf], bb[nf2][1], bb[nf2][3]);
                    }
            }
        }
        __syncthreads();
    }

    // epilogue: bias add + store
#pragma unroll
    for (int mf = 0; mf < 2; mf++)
#pragma unroll
        for (int nf = 0; nf < 4; nf++) {
            int col = n0 + warp_n + nf * 8 + (lane & 3) * 2;
            float b0 = bout[col], b1 = bout[col + 1];
            int r0 = warp_m + mf * 16 + (lane >> 2);
            float2 o0 = {c[mf][nf][0] + b0, c[mf][nf][1] + b1};
            float2 o1 = {c[mf][nf][2] + b0, c[mf][nf][3] + b1};
            *reinterpret_cast<float2*>(out_pred + (long)r0 * V_ + col) = o0;
            *reinterpret_cast<float2*>(out_pred + (long)(r0 + 8) * V_ + col) = o1;
        }
}

// ===================== fp32 split pre-pass ===================================
__global__ void split_kernel(const float* __restrict__ src,
                             __nv_bfloat16* __restrict__ hi,
                             __nv_bfloat16* __restrict__ lo, int n) {
    int i = (blockIdx.x * 256 + threadIdx.x) * 4;
    if (i >= n) return;
    float4 v = *reinterpret_cast<const float4*>(src + i);
    uint2 H, L;
    split2(v.x, v.y, H.x, L.x);
    split2(v.z, v.w, H.y, L.y);
    *reinterpret_cast<uint2*>(hi + i) = H;
    *reinterpret_cast<uint2*>(lo + i) = L;
}

// ===================== fp32 SIMT pieces ======================================
template<int BN, int TN, bool ACC>
__global__ void gemm_m64(const float* __restrict__ A,
                         const float* __restrict__ W,
                         float* __restrict__ C,
                         const float* __restrict__ bias1,
                         const float* __restrict__ bias2,
                         int N, int K) {
    constexpr int BK = 16;
    __shared__ float As[BK][64 + 4];
    __shared__ float Ws[BK][BN + 4];

    const int tid = threadIdx.x;
    const int tx = tid & 15;
    const int ty = tid >> 4;
    const int n0 = blockIdx.x * BN;

    float acc[4][TN];
#pragma unroll
    for (int i = 0; i < 4; i++)
#pragma unroll
        for (int j = 0; j < TN; j++) acc[i][j] = 0.f;

    for (int k0 = 0; k0 < K; k0 += BK) {
        __syncthreads();
        {
            int m = tid >> 2, k4 = tid & 3;
            float4 a = *reinterpret_cast<const float4*>(A + (long)m * K + k0 + k4 * 4);
            As[k4 * 4 + 0][m] = a.x; As[k4 * 4 + 1][m] = a.y;
            As[k4 * 4 + 2][m] = a.z; As[k4 * 4 + 3][m] = a.w;
        }
        for (int idx = tid; idx < BN * 4; idx += 256) {
            int n = idx >> 2, k4 = idx & 3;
            float4 w = *reinterpret_cast<const float4*>(W + (long)(n0 + n) * K + k0 + k4 * 4);
            Ws[k4 * 4 + 0][n] = w.x; Ws[k4 * 4 + 1][n] = w.y;
            Ws[k4 * 4 + 2][n] = w.z; Ws[k4 * 4 + 3][n] = w.w;
        }
        __syncthreads();

#pragma unroll
        for (int k = 0; k < BK; k++) {
            float4 a = *reinterpret_cast<const float4*>(&As[k][ty * 4]);
            float av[4] = {a.x, a.y, a.z, a.w};
            float wv[TN];
            if constexpr (TN == 1) {
                wv[0] = Ws[k][tx];
            } else {
#pragma unroll
                for (int jj = 0; jj < TN; jj += 4) {
                    float4 w = *reinterpret_cast<const float4*>(&Ws[k][tx * TN + jj]);
                    wv[jj + 0] = w.x; wv[jj + 1] = w.y; wv[jj + 2] = w.z; wv[jj + 3] = w.w;
                }
            }
#pragma unroll
            for (int i = 0; i < 4; i++)
#pragma unroll
                for (int j = 0; j < TN; j++)
                    acc[i][j] = fmaf(av[i], wv[j], acc[i][j]);
        }
    }
#pragma unroll
    for (int i = 0; i < 4; i++) {
        int m = ty * 4 + i;
#pragma unroll
        for (int j = 0; j < TN; j++) {
            int n = n0 + tx * TN + j;
            float val = acc[i][j];
            if (bias1) val += bias1[n];
            if (bias2) val += bias2[n];
            if (ACC)   val += C[(long)m * N + n];
            C[(long)m * N + n] = val;
        }
    }
}

__global__ void softmax_kernel(const float* __restrict__ energy,
                               const int* __restrict__ mask,
                               float* __restrict__ out_attn) {
    __shared__ float red[256];
    const int b = blockIdx.x;
    const int s = threadIdx.x;
    float val = energy[b * S_ + s];
    if (mask[b * S_ + s] == 0) val = -1e10f;
    red[s] = val;
    __syncthreads();
#pragma unroll
    for (int off = 128; off > 0; off >>= 1) {
        if (s < off) red[s] = fmaxf(red[s], red[s + off]);
        __syncthreads();
    }
    float mx = red[0];
    __syncthreads();
    float ex = expf(val - mx);
    red[s] = ex;
    __syncthreads();
#pragma unroll
    for (int off = 128; off > 0; off >>= 1) {
        if (s < off) red[s] += red[s + off];
        __syncthreads();
    }
    out_attn[b * S_ + s] = ex / red[0];
}

__global__ void context_kernel(const float* __restrict__ enc,
                               const float* __restrict__ attn,
                               float* __restrict__ x0,
                               float* __restrict__ feat) {
    __shared__ float w[S_];
    const int b = blockIdx.x;
    const int tid = threadIdx.x;
    w[tid] = attn[b * S_ + tid];
    __syncthreads();
    const float* eb = enc + (long)b * S_ * ENC_;
    for (int e = tid; e < ENC_; e += 256) {
        float acc = 0.f;
#pragma unroll 8
        for (int s = 0; s < S_; s++)
            acc = fmaf(w[s], eb[(long)s * ENC_ + e], acc);
        x0[b * XDIM_ + E_ + e]   = acc;
        feat[b * FDIM_ + H_ + e] = acc;
    }
}

__global__ void embed_kernel(const int* __restrict__ tok,
                             const float* __restrict__ emb,
                             float* __restrict__ x0,
                             float* __restrict__ feat,
                             float* __restrict__ energy) {
    const int b = blockIdx.x;
    const int t = tok[b];
    for (int j = threadIdx.x; j < E_; j += 128) {
        float val = emb[(long)t * E_ + j];
        x0[b * XDIM_ + j] = val;
        feat[b * FDIM_ + (H_ + ENC_) + j] = val;
    }
    for (int j = threadIdx.x; j < S_; j += 128) energy[b * S_ + j] = 0.f;
}

__global__ void lstm_kernel(const float* __restrict__ gates,
                            const float* __restrict__ c_prev,
                            float* __restrict__ c_out,
                            float* __restrict__ h_out_a,
                            float* __restrict__ h_out_b,
                            int sb) {
    const int b = blockIdx.x;
    const int idx = blockIdx.y * 256 + threadIdx.x;
    float gi = gates[b * G4H_ + idx];
    float gf = gates[b * G4H_ + H_ + idx];
    float gg = gates[b * G4H_ + 2 * H_ + idx];
    float go = gates[b * G4H_ + 3 * H_ + idx];
    float c  = c_prev[b * H_ + idx];
    float si = 1.f / (1.f + expf(-gi));
    float sf = 1.f / (1.f + expf(-gf));
    float so = 1.f / (1.f + expf(-go));
    float cn = sf * c + si * tanhf(gg);
    float hn = so * tanhf(cn);
    c_out[b * H_ + idx]   = cn;
    h_out_a[b * H_ + idx] = hn;
    h_out_b[b * sb + idx] = hn;
}

// ===================== launch ================================================
extern "C" void kernel_launch(void* const* d_in, const int* in_sizes, int n_in,
                              void* d_out, int out_size) {
    const int*   tok    = (const int*)  d_in[0];
    const float* hidden = (const float*)d_in[1];
    const float* cell   = (const float*)d_in[2];
    const float* enc    = (const float*)d_in[3];
    const int*   mask   = (const int*)  d_in[4];
    const float* emb    = (const float*)d_in[5];
    const float* Wq     = (const float*)d_in[6];
    const float* Wk     = (const float*)d_in[7];
    const float* v      = (const float*)d_in[8];
    const float* Wih0   = (const float*)d_in[9];
    const float* Whh0   = (const float*)d_in[10];
    const float* bih0   = (const float*)d_in[11];
    const float* bhh0   = (const float*)d_in[12];
    const float* Wih1   = (const float*)d_in[13];
    const float* Whh1   = (const float*)d_in[14];
    const float* bih1   = (const float*)d_in[15];
    const float* bhh1   = (const float*)d_in[16];
    const float* Wout   = (const float*)d_in[17];
    const float* bout   = (const float*)d_in[18];

    float* out      = (float*)d_out;
    float* out_pred = out;
    float* out_hid  = out + (long)B_ * V_;
    float* out_cell = out_hid + 2 * B_ * H_;
    float* out_attn = out_cell + 2 * B_ * H_;

    void* sp = nullptr;
    cudaGetSymbolAddress(&sp, g_scratch);
    float* scratch = (float*)sp;
    float* query  = scratch + OFF_QUERY;
    float* x0     = scratch + OFF_X0;
    float* feat   = scratch + OFF_FEAT;
    float* gates  = scratch + OFF_GATES;
    float* h0     = scratch + OFF_H0;
    float* energy = scratch + OFF_ENERGY;

    void *p_eh, *p_el, *p_wh, *p_wl, *p_fh, *p_fl;
    cudaGetSymbolAddress(&p_eh, g_enc_hi);
    cudaGetSymbolAddress(&p_el, g_enc_lo);
    cudaGetSymbolAddress(&p_wh, g_wk_hi);
    cudaGetSymbolAddress(&p_wl, g_wk_lo);
    cudaGetSymbolAddress(&p_fh, g_feat_hi);
    cudaGetSymbolAddress(&p_fl, g_feat_lo);

    static bool attr_done = false;
    if (!attr_done) {
        cudaFuncSetAttribute(energy_mma_kernel, cudaFuncAttributeMaxDynamicSharedMemorySize, EK_SMEM_BYTES);
        cudaFuncSetAttribute(wout_mma_kernel,   cudaFuncAttributeMaxDynamicSharedMemorySize, WO_SMEM_BYTES);
        attr_done = true;
    }

    // 1. embedding gather + zero energy accumulator
    embed_kernel<<<B_, 128>>>(tok, emb, x0, feat, energy);

    // 2. bf16 hi/lo split of enc and Wk
    split_kernel<<<(B_ * S_ * ENC_) / 1024, 256>>>(enc, (__nv_bfloat16*)p_eh, (__nv_bfloat16*)p_el, B_ * S_ * ENC_);
    split_kernel<<<(H_ * ENC_) / 1024, 256>>>(Wk, (__nv_bfloat16*)p_wh, (__nv_bfloat16*)p_wl, H_ * ENC_);

    // 3. query = hidden[1] @ Wq^T
    gemm_m64<16, 1, false><<<H_ / 16, 256>>>(hidden + B_ * H_, Wq, query, nullptr, nullptr, H_, H_);

    // 4. fused keys GEMM + tanh energy (HMMA, 3-term bf16 split)
    energy_mma_kernel<<<dim3(H_ / 128, (B_ * S_) / 128), 256, EK_SMEM_BYTES>>>(
        (const __nv_bfloat16*)p_eh, (const __nv_bfloat16*)p_el,
        (const __nv_bfloat16*)p_wh, (const __nv_bfloat16*)p_wl, v, query, energy);

    // 5. masked softmax -> attn output
    softmax_kernel<<<B_, 256>>>(energy, mask, out_attn);

    // 6. context
    context_kernel<<<B_, 256>>>(enc, out_attn, x0, feat);

    // 7. layer-0 gates + LSTM
    gemm_m64<64, 4, false><<<G4H_ / 64, 256>>>(x0, Wih0, gates, bih0, bhh0, G4H_, XDIM_);
    gemm_m64<64, 4, true><<<G4H_ / 64, 256>>>(hidden, Whh0, gates, nullptr, nullptr, G4H_, H_);
    lstm_kernel<<<dim3(B_, H_ / 256), 256>>>(gates, cell, out_cell, out_hid, h0, H_);

    // 8. layer-1 gates + LSTM
    gemm_m64<64, 4, false><<<G4H_ / 64, 256>>>(h0, Wih1, gates, bih1, bhh1, G4H_, H_);
    gemm_m64<64, 4, true><<<G4H_ / 64, 256>>>(hidden + B_ * H_, Whh1, gates, nullptr, nullptr, G4H_, H_);
    lstm_kernel<<<dim3(B_, H_ / 256), 256>>>(gates, cell + B_ * H_, out_cell + B_ * H_,
                                             out_hid + B_ * H_, feat, FDIM_);

    // 9. split feat to bf16 hi/lo
    split_kernel<<<(B_ * FDIM_) / 1024, 256>>>(feat, (__nv_bfloat16*)p_fh, (__nv_bfloat16*)p_fl, B_ * FDIM_);

    // 10. prediction = feat @ Wout^T + bout (HMMA, 3-term bf16 split)
    wout_mma_kernel<<<V_ / 128, 256, WO_SMEM_BYTES>>>(
        (const __nv_bfloat16*)p_fh, (const __nv_bfloat16*)p_fl, Wout, bout, out_pred);
}

// round 4
// speedup vs baseline: 3.2171x; 1.2081x over previous
#include <cuda_runtime.h>
#include <cuda_bf16.h>
#include <math.h>
#include <stdint.h>

#define B_   64
#define S_   256
#define H_   1024
#define ENC_ 1024
#define E_   512
#define V_   32000
#define XDIM_ (E_ + ENC_)        // 1536
#define FDIM_ (H_ + ENC_ + E_)   // 2560
#define G4H_  (4 * H_)           // 4096
#define KCAT0 2560               // emb|ctx|hidden0
#define KCAT1 2048               // h0|hidden1

// ---------------- scratch (device globals) ----------------------------------
#define OFF_QUERY  0
#define OFF_XCAT0  (OFF_QUERY + B_ * H_)
#define OFF_XCAT1  (OFF_XCAT0 + B_ * KCAT0)
#define OFF_FEAT   (OFF_XCAT1 + B_ * KCAT1)
#define OFF_GATES  (OFF_FEAT + B_ * FDIM_)
#define OFF_ENERGY (OFF_GATES + B_ * G4H_)
#define SCRATCH_TOTAL (OFF_ENERGY + B_ * S_)

__device__ __align__(16) float g_scratch[SCRATCH_TOTAL];

// bf16 split buffers
__device__ __align__(16) __nv_bfloat16 g_enc_hi[(long)B_ * S_ * ENC_];
__device__ __align__(16) __nv_bfloat16 g_enc_lo[(long)B_ * S_ * ENC_];
__device__ __align__(16) __nv_bfloat16 g_wk_hi[H_ * ENC_];
__device__ __align__(16) __nv_bfloat16 g_wk_lo[H_ * ENC_];
__device__ __align__(16) __nv_bfloat16 g_h1_hi[B_ * H_];
__device__ __align__(16) __nv_bfloat16 g_h1_lo[B_ * H_];
__device__ __align__(16) __nv_bfloat16 g_a0_hi[B_ * KCAT0];
__device__ __align__(16) __nv_bfloat16 g_a0_lo[B_ * KCAT0];
__device__ __align__(16) __nv_bfloat16 g_a1_hi[B_ * KCAT1];
__device__ __align__(16) __nv_bfloat16 g_a1_lo[B_ * KCAT1];
__device__ __align__(16) __nv_bfloat16 g_feat_hi[B_ * FDIM_];
__device__ __align__(16) __nv_bfloat16 g_feat_lo[B_ * FDIM_];

// ===================== low-level helpers =====================================
__device__ __forceinline__ uint32_t smem_to_u32(const void* p) {
    uint32_t a;
    asm("{ .reg .u64 t; cvta.to.shared.u64 t, %1; cvt.u32.u64 %0, t; }" : "=r"(a) : "l"(p));
    return a;
}

#define CP16(dst_u32, src_ptr) \
    asm volatile("cp.async.cg.shared.global [%0], [%1], 16;" :: "r"(dst_u32), "l"(src_ptr))
#define CP_COMMIT() asm volatile("cp.async.commit_group;" ::: "memory")
template<int N> __device__ __forceinline__ void cp_wait() {
    asm volatile("cp.async.wait_group %0;" :: "n"(N) : "memory");
}

__device__ __forceinline__ void ldmx4(uint32_t addr, uint32_t r[4]) {
    asm volatile("ldmatrix.sync.aligned.m8n8.x4.shared.b16 {%0,%1,%2,%3}, [%4];"
        : "=r"(r[0]), "=r"(r[1]), "=r"(r[2]), "=r"(r[3]) : "r"(addr));
}

__device__ __forceinline__ void mma16816(float* c, const uint32_t a[4],
                                         uint32_t b0, uint32_t b1) {
    asm volatile("mma.sync.aligned.m16n8k16.row.col.f32.bf16.bf16.f32 "
        "{%0,%1,%2,%3}, {%4,%5,%6,%7}, {%8,%9}, {%0,%1,%2,%3};"
        : "+f"(c[0]), "+f"(c[1]), "+f"(c[2]), "+f"(c[3])
        : "r"(a[0]), "r"(a[1]), "r"(a[2]), "r"(a[3]), "r"(b0), "r"(b1));
}

#define STS128(addr, a, b, c, d) \
    asm volatile("st.shared.v4.b32 [%0], {%1,%2,%3,%4};" \
        :: "r"(addr), "r"(a), "r"(b), "r"(c), "r"(d) : "memory")

// swizzled byte offset within a 128B-row tile
__device__ __forceinline__ uint32_t swz(int row, int chunk16) {
    return (uint32_t)(row * 128 + ((chunk16 ^ (row & 7)) * 16));
}

__device__ __forceinline__ void split2(float a, float b, uint32_t& hi, uint32_t& lo) {
    __nv_bfloat162 h2 = __floats2bfloat162_rn(a, b);
    float ra = a - __bfloat162float(__low2bfloat16(h2));
    float rb = b - __bfloat162float(__high2bfloat16(h2));
    __nv_bfloat162 l2 = __floats2bfloat162_rn(ra, rb);
    hi = *reinterpret_cast<uint32_t*>(&h2);
    lo = *reinterpret_cast<uint32_t*>(&l2);
}

// ===================== energy MMA kernel (unchanged) =========================
#define EK_TILE  16384
#define EK_STAGE (4 * EK_TILE)
#define EK_SMEM_BYTES (2048 + 2 * EK_STAGE)

__device__ __forceinline__ void ek_load_stage(const __nv_bfloat16* eh, const __nv_bfloat16* el,
                                              const __nv_bfloat16* wh, const __nv_bfloat16* wl,
                                              long m0, int n0, int c0, uint32_t stg) {
    const int tid = threadIdx.x;
#pragma unroll
    for (int i = 0; i < 4; i++) {
        int idx = tid + i * 256;
        int r = idx >> 3, c = idx & 7;
        uint32_t off = swz(r, c);
        long asrc = (m0 + r) * (long)ENC_ + c0 + c * 8;
        CP16(stg + off, eh + asrc);
        CP16(stg + EK_TILE + off, el + asrc);
        long bsrc = (long)(n0 + r) * ENC_ + c0 + c * 8;
        CP16(stg + 2 * EK_TILE + off, wh + bsrc);
        CP16(stg + 3 * EK_TILE + off, wl + bsrc);
    }
}

__device__ __forceinline__ void ek_compute(uint32_t stg, float c[2][8][4],
                                           int warp_m, int warp_n, int lane) {
    const uint32_t Ah = stg, Al = stg + EK_TILE;
    const uint32_t Bh = stg + 2 * EK_TILE, Bl = stg + 3 * EK_TILE;
    const int lm = lane & 15, lh = lane >> 4;
#pragma unroll
    for (int ks = 0; ks < 4; ks++) {
        const int ch = ks * 2 + lh;
        uint32_t ah[2][4], al[2][4];
#pragma unroll
        for (int mf = 0; mf < 2; mf++) {
            uint32_t off = swz(warp_m + mf * 16 + lm, ch);
            ldmx4(Ah + off, ah[mf]);
            ldmx4(Al + off, al[mf]);
        }
        uint32_t bb[4][4];
#pragma unroll
        for (int nf2 = 0; nf2 < 4; nf2++) {
            uint32_t off = swz(warp_n + nf2 * 16 + lm, ch);
            ldmx4(Bh + off, bb[nf2]);
        }
#pragma unroll
        for (int nf2 = 0; nf2 < 4; nf2++)
#pragma unroll
            for (int mf = 0; mf < 2; mf++) {
                mma16816(c[mf][nf2 * 2 + 0], ah[mf], bb[nf2][0], bb[nf2][2]);
                mma16816(c[mf][nf2 * 2 + 1], ah[mf], bb[nf2][1], bb[nf2][3]);
                mma16816(c[mf][nf2 * 2 + 0], al[mf], bb[nf2][0], bb[nf2][2]);
                mma16816(c[mf][nf2 * 2 + 1], al[mf], bb[nf2][1], bb[nf2][3]);
            }
#pragma unroll
        for (int nf2 = 0; nf2 < 4; nf2++) {
            uint32_t off = swz(warp_n + nf2 * 16 + lm, ch);
            ldmx4(Bl + off, bb[nf2]);
        }
#pragma unroll
        for (int nf2 = 0; nf2 < 4; nf2++)
#pragma unroll
            for (int mf = 0; mf < 2; mf++) {
                mma16816(c[mf][nf2 * 2 + 0], ah[mf], bb[nf2][0], bb[nf2][2]);
                mma16816(c[mf][nf2 * 2 + 1], ah[mf], bb[nf2][1], bb[nf2][3]);
            }
    }
}

__global__ __launch_bounds__(256, 1)
void energy_mma_kernel(const __nv_bfloat16* __restrict__ eh,
                       const __nv_bfloat16* __restrict__ el,
                       const __nv_bfloat16* __restrict__ wh,
                       const __nv_bfloat16* __restrict__ wl,
                       const float* __restrict__ vvec,
                       const float* __restrict__ query,
                       float* __restrict__ energy) {
    extern __shared__ char smem[];
    uint32_t sb = smem_to_u32(smem);
    uint32_t tiles = (sb + 1024 + 1023) & ~1023u;

    const int tid = threadIdx.x;
    const int wid = tid >> 5, lane = tid & 31;
    const int warp_m = (wid & 3) * 32;
    const int warp_n = (wid >> 2) * 64;

    const int n0 = blockIdx.x * 128;
    const long m0 = (long)blockIdx.y * 128;
    const int b = blockIdx.y >> 1;
    const int sbase = (blockIdx.y & 1) * 128;

    float* vs = (float*)smem;
    float* qs = vs + 128;
    if (tid < 128) { vs[tid] = vvec[n0 + tid]; qs[tid] = query[b * H_ + n0 + tid]; }

    float c[2][8][4];
#pragma unroll
    for (int i = 0; i < 2; i++)
#pragma unroll
        for (int j = 0; j < 8; j++)
#pragma unroll
            for (int k = 0; k < 4; k++) c[i][j][k] = 0.f;

    ek_load_stage(eh, el, wh, wl, m0, n0, 0, tiles);
    CP_COMMIT();

    const int KT = ENC_ / 64;
    for (int kt = 0; kt < KT; kt++) {
        if (kt + 1 < KT) {
            ek_load_stage(eh, el, wh, wl, m0, n0, (kt + 1) * 64,
                          tiles + ((kt + 1) & 1) * EK_STAGE);
            CP_COMMIT();
            cp_wait<1>();
        } else {
            cp_wait<0>();
        }
        __syncthreads();
        ek_compute(tiles + (kt & 1) * EK_STAGE, c, warp_m, warp_n, lane);
        __syncthreads();
    }

#pragma unroll
    for (int mf = 0; mf < 2; mf++) {
        float s_lo = 0.f, s_hi = 0.f;
#pragma unroll
        for (int nf = 0; nf < 8; nf++) {
            int col = warp_n + nf * 8 + (lane & 3) * 2;
            float v0 = vs[col], v1 = vs[col + 1];
            float q0 = qs[col], q1 = qs[col + 1];
            s_lo += v0 * tanhf(q0 + c[mf][nf][0]) + v1 * tanhf(q1 + c[mf][nf][1]);
            s_hi += v0 * tanhf(q0 + c[mf][nf][2]) + v1 * tanhf(q1 + c[mf][nf][3]);
        }
        s_lo += __shfl_xor_sync(0xffffffff, s_lo, 1);
        s_lo += __shfl_xor_sync(0xffffffff, s_lo, 2);
        s_hi += __shfl_xor_sync(0xffffffff, s_hi, 1);
        s_hi += __shfl_xor_sync(0xffffffff, s_hi, 2);
        if ((lane & 3) == 0) {
            int r0 = warp_m + mf * 16 + (lane >> 2);
            atomicAdd(&energy[b * S_ + sbase + r0], s_lo);
            atomicAdd(&energy[b * S_ + sbase + r0 + 8], s_hi);
        }
    }
}

// ===================== generalized fat-B HMMA kernel =========================
// C[0:64, n0:n0+128] = A[64,Ktot] @ Bcat[N,Ktot]^T (+bias1+bias2)
// A: pre-split bf16 hi/lo, lda = Ktot.
// B: fp32, read once, split to bf16 hi/lo in-kernel. Two K-segments:
//    cols [0,k1) from B1 (ld k1), cols [k1,Ktot) from B2 (ld Ktot-k1).
#define WO_A_TILE 8192
#define WO_B_TILE 16384
#define WO_STAGE  (2 * WO_A_TILE + 2 * WO_B_TILE)   // 48KB
#define WO_SMEM_BYTES (1024 + 2 * WO_STAGE)

__device__ __forceinline__ void wo_load_A(const __nv_bfloat16* fh, const __nv_bfloat16* fl,
                                          int lda, int c0, uint32_t stg) {
    const int tid = threadIdx.x;
#pragma unroll
    for (int i = 0; i < 2; i++) {
        int idx = tid + i * 256;
        int r = idx >> 3, cc = idx & 7;
        uint32_t off = swz(r, cc);
        long src = (long)r * lda + c0 + cc * 8;
        CP16(stg + off, fh + src);
        CP16(stg + WO_A_TILE + off, fl + src);
    }
}

__global__ __launch_bounds__(256, 1)
void hmma_m64_kernel(const __nv_bfloat16* __restrict__ ah_g,
                     const __nv_bfloat16* __restrict__ al_g,
                     int Ktot,
                     const float* __restrict__ B1, int k1,
                     const float* __restrict__ B2,
                     const float* __restrict__ bias1,
                     const float* __restrict__ bias2,
                     float* __restrict__ C, int ldc) {
    extern __shared__ char smem[];
    uint32_t sb = smem_to_u32(smem);
    uint32_t tiles = (sb + 1023) & ~1023u;

    const int tid = threadIdx.x;
    const int wid = tid >> 5, lane = tid & 31;
    const int warp_m = (wid & 1) * 32;
    const int warp_n = (wid >> 1) * 32;
    const int n0 = blockIdx.x * 128;

    const int br = tid >> 1;
    const int bhalf = tid & 1;
    const int k2 = Ktot - k1;

    float c[2][4][4];
#pragma unroll
    for (int i = 0; i < 2; i++)
#pragma unroll
        for (int j = 0; j < 4; j++)
#pragma unroll
            for (int k = 0; k < 4; k++) c[i][j][k] = 0.f;

    wo_load_A(ah_g, al_g, Ktot, 0, tiles);
    CP_COMMIT();

    const float* w0 = B1 + (long)(n0 + br) * k1 + bhalf * 32;
    float4 nb[8];
#pragma unroll
    for (int j = 0; j < 4; j++) {
        nb[2 * j]     = *reinterpret_cast<const float4*>(w0 + j * 8);
        nb[2 * j + 1] = *reinterpret_cast<const float4*>(w0 + j * 8 + 4);
    }

    const int KT = Ktot / 64;
    for (int kt = 0; kt < KT; kt++) {
        uint32_t stg = tiles + (kt & 1) * WO_STAGE;
        if (kt + 1 < KT) {
            wo_load_A(ah_g, al_g, Ktot, (kt + 1) * 64, tiles + ((kt + 1) & 1) * WO_STAGE);
            CP_COMMIT();
        }
        uint32_t Bh = stg + 2 * WO_A_TILE, Bl = Bh + WO_B_TILE;
#pragma unroll
        for (int j = 0; j < 4; j++) {
            float4 v0 = nb[2 * j], v1 = nb[2 * j + 1];
            uint4 Hq, Lq;
            split2(v0.x, v0.y, Hq.x, Lq.x);
            split2(v0.z, v0.w, Hq.y, Lq.y);
            split2(v1.x, v1.y, Hq.z, Lq.z);
            split2(v1.z, v1.w, Hq.w, Lq.w);
            uint32_t off = swz(br, bhalf * 4 + j);
            STS128(Bh + off, Hq.x, Hq.y, Hq.z, Hq.w);
            STS128(Bl + off, Lq.x, Lq.y, Lq.z, Lq.w);
        }
        if (kt + 1 < KT) cp_wait<1>(); else cp_wait<0>();
        __syncthreads();
        // prefetch next B fp32 chunk (picks segment by k offset)
        if (kt + 1 < KT) {
            int c0 = (kt + 1) * 64;
            const float* wn = (c0 < k1)
                ? B1 + (long)(n0 + br) * k1 + c0 + bhalf * 32
                : B2 + (long)(n0 + br) * k2 + (c0 - k1) + bhalf * 32;
#pragma unroll
            for (int j = 0; j < 4; j++) {
                nb[2 * j]     = *reinterpret_cast<const float4*>(wn + j * 8);
                nb[2 * j + 1] = *reinterpret_cast<const float4*>(wn + j * 8 + 4);
            }
        }
        // compute this stage
        {
            const uint32_t Ah = stg, Al = stg + WO_A_TILE;
            const int lm = lane & 15, lh = lane >> 4;
#pragma unroll
            for (int ks = 0; ks < 4; ks++) {
                const int ch = ks * 2 + lh;
                uint32_t ah[2][4], al[2][4];
#pragma unroll
                for (int mf = 0; mf < 2; mf++) {
                    uint32_t off = swz(warp_m + mf * 16 + lm, ch);
                    ldmx4(Ah + off, ah[mf]);
                    ldmx4(Al + off, al[mf]);
                }
                uint32_t bb[2][4];
#pragma unroll
                for (int nf2 = 0; nf2 < 2; nf2++) {
                    uint32_t off = swz(warp_n + nf2 * 16 + lm, ch);
                    ldmx4(Bh + off, bb[nf2]);
                }
#pragma unroll
                for (int nf2 = 0; nf2 < 2; nf2++)
#pragma unroll
                    for (int mf = 0; mf < 2; mf++) {
                        mma16816(c[mf][nf2 * 2 + 0], ah[mf], bb[nf2][0], bb[nf2][2]);
                        mma16816(c[mf][nf2 * 2 + 1], ah[mf], bb[nf2][1], bb[nf2][3]);
                        mma16816(c[mf][nf2 * 2 + 0], al[mf], bb[nf2][0], bb[nf2][2]);
                        mma16816(c[mf][nf2 * 2 + 1], al[mf], bb[nf2][1], bb[nf2][3]);
                    }
#pragma unroll
                for (int nf2 = 0; nf2 < 2; nf2++) {
                    uint32_t off = swz(warp_n + nf2 * 16 + lm, ch);
                    ldmx4(Bl + off, bb[nf2]);
                }
#pragma unroll
                for (int nf2 = 0; nf2 < 2; nf2++)
#pragma unroll
                    for (int mf = 0; mf < 2; mf++) {
                        mma16816(c[mf][nf2 * 2 + 0], ah[mf], bb[nf2][0], bb[nf2][2]);
                        mma16816(c[mf][nf2 * 2 + 1], ah[mf], bb[nf2][1], bb[nf2][3]);
                    }
            }
        }
        __syncthreads();
    }

    // epilogue: optional biases + store
#pragma unroll
    for (int mf = 0; mf < 2; mf++)
#pragma unroll
        for (int nf = 0; nf < 4; nf++) {
            int col = n0 + warp_n + nf * 8 + (lane & 3) * 2;
            float b0 = 0.f, b1 = 0.f;
            if (bias1) { b0 += bias1[col]; b1 += bias1[col + 1]; }
            if (bias2) { b0 += bias2[col]; b1 += bias2[col + 1]; }
            int r0 = warp_m + mf * 16 + (lane >> 2);
            float2 o0 = {c[mf][nf][0] + b0, c[mf][nf][1] + b1};
            float2 o1 = {c[mf][nf][2] + b0, c[mf][nf][3] + b1};
            *reinterpret_cast<float2*>(C + (long)r0 * ldc + col) = o0;
            *reinterpret_cast<float2*>(C + (long)(r0 + 8) * ldc + col) = o1;
        }
}

// ===================== fp32 split pre-pass ===================================
__global__ void split_kernel(const float* __restrict__ src,
                             __nv_bfloat16* __restrict__ hi,
                             __nv_bfloat16* __restrict__ lo, int n) {
    int i = (blockIdx.x * 256 + threadIdx.x) * 4;
    if (i >= n) return;
    float4 v = *reinterpret_cast<const float4*>(src + i);
    uint2 H, L;
    split2(v.x, v.y, H.x, L.x);
    split2(v.z, v.w, H.y, L.y);
    *reinterpret_cast<uint2*>(hi + i) = H;
    *reinterpret_cast<uint2*>(lo + i) = L;
}

// ===================== small fp32 kernels ====================================
__global__ void softmax_kernel(const float* __restrict__ energy,
                               const int* __restrict__ mask,
                               float* __restrict__ out_attn) {
    __shared__ float red[256];
    const int b = blockIdx.x;
    const int s = threadIdx.x;
    float val = energy[b * S_ + s];
    if (mask[b * S_ + s] == 0) val = -1e10f;
    red[s] = val;
    __syncthreads();
#pragma unroll
    for (int off = 128; off > 0; off >>= 1) {
        if (s < off) red[s] = fmaxf(red[s], red[s + off]);
        __syncthreads();
    }
    float mx = red[0];
    __syncthreads();
    float ex = expf(val - mx);
    red[s] = ex;
    __syncthreads();
#pragma unroll
    for (int off = 128; off > 0; off >>= 1) {
        if (s < off) red[s] += red[s + off];
        __syncthreads();
    }
    out_attn[b * S_ + s] = ex / red[0];
}

// context: grid (B_, 4), 256 threads; each thread owns one enc column
__global__ void context_kernel(const float* __restrict__ enc,
                               const float* __restrict__ attn,
                               float* __restrict__ xcat0,
                               float* __restrict__ feat) {
    __shared__ float w[S_];
    const int b = blockIdx.x;
    const int c = blockIdx.y * 256 + threadIdx.x;
    w[threadIdx.x] = attn[b * S_ + threadIdx.x];
    __syncthreads();
    const float* eb = enc + (long)b * S_ * ENC_ + c;
    float acc = 0.f;
#pragma unroll 8
    for (int s = 0; s < S_; s++)
        acc = fmaf(w[s], eb[(long)s * ENC_], acc);
    xcat0[b * KCAT0 + E_ + c]  = acc;
    feat[b * FDIM_ + H_ + c]   = acc;
}

// embed + scatter hidden copies + zero energy
__global__ void embed_kernel(const int* __restrict__ tok,
                             const float* __restrict__ emb,
                             const float* __restrict__ hidden,
                             float* __restrict__ xcat0,
                             float* __restrict__ xcat1,
                             float* __restrict__ feat,
                             float* __restrict__ energy) {
    const int b = blockIdx.x;
    const int t = tok[b];
    for (int j = threadIdx.x; j < E_; j += 256) {
        float val = emb[(long)t * E_ + j];
        xcat0[b * KCAT0 + j] = val;
        feat[b * FDIM_ + (H_ + ENC_) + j] = val;
    }
    for (int j = threadIdx.x; j < H_; j += 256) {
        xcat0[b * KCAT0 + XDIM_ + j] = hidden[b * H_ + j];            // hidden[0]
        xcat1[b * KCAT1 + H_ + j]    = hidden[B_ * H_ + b * H_ + j];  // hidden[1]
    }
    for (int j = threadIdx.x; j < S_; j += 256) energy[b * S_ + j] = 0.f;
}

__global__ void lstm_kernel(const float* __restrict__ gates,
                            const float* __restrict__ c_prev,
                            float* __restrict__ c_out,
                            float* __restrict__ h_out_a,
                            float* __restrict__ h_out_b,
                            int sb) {
    const int b = blockIdx.x;
    const int idx = blockIdx.y * 256 + threadIdx.x;
    float gi = gates[b * G4H_ + idx];
    float gf = gates[b * G4H_ + H_ + idx];
    float gg = gates[b * G4H_ + 2 * H_ + idx];
    float go = gates[b * G4H_ + 3 * H_ + idx];
    float c  = c_prev[b * H_ + idx];
    float si = 1.f / (1.f + expf(-gi));
    float sf = 1.f / (1.f + expf(-gf));
    float so = 1.f / (1.f + expf(-go));
    float cn = sf * c + si * tanhf(gg);
    float hn = so * tanhf(cn);
    c_out[b * H_ + idx]   = cn;
    h_out_a[b * H_ + idx] = hn;
    h_out_b[b * sb + idx] = hn;
}

// ===================== launch ================================================
extern "C" void kernel_launch(void* const* d_in, const int* in_sizes, int n_in,
                              void* d_out, int out_size) {
    const int*   tok    = (const int*)  d_in[0];
    const float* hidden = (const float*)d_in[1];
    const float* cell   = (const float*)d_in[2];
    const float* enc    = (const float*)d_in[3];
    const int*   mask   = (const int*)  d_in[4];
    const float* emb    = (const float*)d_in[5];
    const float* Wq     = (const float*)d_in[6];
    const float* Wk     = (const float*)d_in[7];
    const float* v      = (const float*)d_in[8];
    const float* Wih0   = (const float*)d_in[9];
    const float* Whh0   = (const float*)d_in[10];
    const float* bih0   = (const float*)d_in[11];
    const float* bhh0   = (const float*)d_in[12];
    const float* Wih1   = (const float*)d_in[13];
    const float* Whh1   = (const float*)d_in[14];
    const float* bih1   = (const float*)d_in[15];
    const float* bhh1   = (const float*)d_in[16];
    const float* Wout   = (const float*)d_in[17];
    const float* bout   = (const float*)d_in[18];

    float* out      = (float*)d_out;
    float* out_pred = out;
    float* out_hid  = out + (long)B_ * V_;
    float* out_cell = out_hid + 2 * B_ * H_;
    float* out_attn = out_cell + 2 * B_ * H_;

    void* sp = nullptr;
    cudaGetSymbolAddress(&sp, g_scratch);
    float* scratch = (float*)sp;
    float* query  = scratch + OFF_QUERY;
    float* xcat0  = scratch + OFF_XCAT0;
    float* xcat1  = scratch + OFF_XCAT1;
    float* feat   = scratch + OFF_FEAT;
    float* gates  = scratch + OFF_GATES;
    float* energy = scratch + OFF_ENERGY;

    void *p_eh, *p_el, *p_wh, *p_wl, *p_h1h, *p_h1l,
         *p_a0h, *p_a0l, *p_a1h, *p_a1l, *p_fh, *p_fl;
    cudaGetSymbolAddress(&p_eh,  g_enc_hi);
    cudaGetSymbolAddress(&p_el,  g_enc_lo);
    cudaGetSymbolAddress(&p_wh,  g_wk_hi);
    cudaGetSymbolAddress(&p_wl,  g_wk_lo);
    cudaGetSymbolAddress(&p_h1h, g_h1_hi);
    cudaGetSymbolAddress(&p_h1l, g_h1_lo);
    cudaGetSymbolAddress(&p_a0h, g_a0_hi);
    cudaGetSymbolAddress(&p_a0l, g_a0_lo);
    cudaGetSymbolAddress(&p_a1h, g_a1_hi);
    cudaGetSymbolAddress(&p_a1l, g_a1_lo);
    cudaGetSymbolAddress(&p_fh,  g_feat_hi);
    cudaGetSymbolAddress(&p_fl,  g_feat_lo);

    cudaFuncSetAttribute(energy_mma_kernel, cudaFuncAttributeMaxDynamicSharedMemorySize, EK_SMEM_BYTES);
    cudaFuncSetAttribute(hmma_m64_kernel,   cudaFuncAttributeMaxDynamicSharedMemorySize, WO_SMEM_BYTES);

    // 1. embedding gather + hidden copies into cat buffers + zero energy
    embed_kernel<<<B_, 256>>>(tok, emb, hidden, xcat0, xcat1, feat, energy);

    // 2. bf16 hi/lo splits: enc, Wk, hidden[1]
    split_kernel<<<(B_ * S_ * ENC_) / 1024, 256>>>(enc, (__nv_bfloat16*)p_eh, (__nv_bfloat16*)p_el, B_ * S_ * ENC_);
    split_kernel<<<(H_ * ENC_) / 1024, 256>>>(Wk, (__nv_bfloat16*)p_wh, (__nv_bfloat16*)p_wl, H_ * ENC_);
    split_kernel<<<(B_ * H_) / 1024, 256>>>(hidden + B_ * H_, (__nv_bfloat16*)p_h1h, (__nv_bfloat16*)p_h1l, B_ * H_);

    // 3. query = hidden[1] @ Wq^T (HMMA)
    hmma_m64_kernel<<<H_ / 128, 256, WO_SMEM_BYTES>>>(
        (const __nv_bfloat16*)p_h1h, (const __nv_bfloat16*)p_h1l, H_,
        Wq, H_, Wq, nullptr, nullptr, query, H_);

    // 4. fused keys GEMM + tanh energy
    energy_mma_kernel<<<dim3(H_ / 128, (B_ * S_) / 128), 256, EK_SMEM_BYTES>>>(
        (const __nv_bfloat16*)p_eh, (const __nv_bfloat16*)p_el,
        (const __nv_bfloat16*)p_wh, (const __nv_bfloat16*)p_wl, v, query, energy);

    // 5. masked softmax
    softmax_kernel<<<B_, 256>>>(energy, mask, out_attn);

    // 6. context -> xcat0[:,512:1536], feat[:,1024:2048]
    context_kernel<<<dim3(B_, 4), 256>>>(enc, out_attn, xcat0, feat);

    // 7. layer-0 gates (fused ih+hh, HMMA) + LSTM
    split_kernel<<<(B_ * KCAT0) / 1024, 256>>>(xcat0, (__nv_bfloat16*)p_a0h, (__nv_bfloat16*)p_a0l, B_ * KCAT0);
    hmma_m64_kernel<<<G4H_ / 128, 256, WO_SMEM_BYTES>>>(
        (const __nv_bfloat16*)p_a0h, (const __nv_bfloat16*)p_a0l, KCAT0,
        Wih0, XDIM_, Whh0, bih0, bhh0, gates, G4H_);
    lstm_kernel<<<dim3(B_, H_ / 256), 256>>>(gates, cell, out_cell, out_hid, xcat1, KCAT1);

    // 8. layer-1 gates (fused ih+hh, HMMA) + LSTM
    split_kernel<<<(B_ * KCAT1) / 1024, 256>>>(xcat1, (__nv_bfloat16*)p_a1h, (__nv_bfloat16*)p_a1l, B_ * KCAT1);
    hmma_m64_kernel<<<G4H_ / 128, 256, WO_SMEM_BYTES>>>(
        (const __nv_bfloat16*)p_a1h, (const __nv_bfloat16*)p_a1l, KCAT1,
        Wih1, H_, Whh1, bih1, bhh1, gates, G4H_);
    lstm_kernel<<<dim3(B_, H_ / 256), 256>>>(gates, cell + B_ * H_, out_cell + B_ * H_,
                                             out_hid + B_ * H_, feat, FDIM_);

    // 9. split feat, then prediction = feat @ Wout^T + bout (HMMA)
    split_kernel<<<(B_ * FDIM_) / 1024, 256>>>(feat, (__nv_bfloat16*)p_fh, (__nv_bfloat16*)p_fl, B_ * FDIM_);
    hmma_m64_kernel<<<V_ / 128, 256, WO_SMEM_BYTES>>>(
        (const __nv_bfloat16*)p_fh, (const __nv_bfloat16*)p_fl, FDIM_,
        Wout, FDIM_, Wout, bout, nullptr, out_pred, V_);
}

// round 5
// speedup vs baseline: 3.4120x; 1.0606x over previous
#include <cuda_runtime.h>
#include <cuda_bf16.h>
#include <math.h>
#include <stdint.h>

#define B_   64
#define S_   256
#define H_   1024
#define ENC_ 1024
#define E_   512
#define V_   32000
#define FDIM_ (H_ + ENC_ + E_)   // 2560
#define G4H_  (4 * H_)           // 4096
#define KCAT0 2560               // emb(512)|ctx(1024)|hidden0(1024)
#define KCAT1 2048               // h0(1024)|hidden1(1024)

// ---------------- scratch (device globals) ----------------------------------
#define OFF_QUERY  0
#define OFF_GATES  (OFF_QUERY + B_ * H_)
#define OFF_ENERGY (OFF_GATES + B_ * G4H_)
#define SCRATCH_TOTAL (OFF_ENERGY + B_ * S_)

__device__ __align__(16) float g_scratch[SCRATCH_TOTAL];
__device__ int g_sidx[B_ * S_];
__device__ int g_scnt[B_];

// bf16 split buffers
__device__ __align__(16) __nv_bfloat16 g_enc_hi[(long)B_ * S_ * ENC_];
__device__ __align__(16) __nv_bfloat16 g_enc_lo[(long)B_ * S_ * ENC_];
__device__ __align__(16) __nv_bfloat16 g_wk_hi[H_ * ENC_];
__device__ __align__(16) __nv_bfloat16 g_wk_lo[H_ * ENC_];
__device__ __align__(16) __nv_bfloat16 g_h1_hi[B_ * H_];
__device__ __align__(16) __nv_bfloat16 g_h1_lo[B_ * H_];
__device__ __align__(16) __nv_bfloat16 g_a0_hi[B_ * KCAT0];
__device__ __align__(16) __nv_bfloat16 g_a0_lo[B_ * KCAT0];
__device__ __align__(16) __nv_bfloat16 g_a1_hi[B_ * KCAT1];
__device__ __align__(16) __nv_bfloat16 g_a1_lo[B_ * KCAT1];
__device__ __align__(16) __nv_bfloat16 g_feat_hi[B_ * FDIM_];
__device__ __align__(16) __nv_bfloat16 g_feat_lo[B_ * FDIM_];

// ===================== low-level helpers =====================================
__device__ __forceinline__ uint32_t smem_to_u32(const void* p) {
    uint32_t a;
    asm("{ .reg .u64 t; cvta.to.shared.u64 t, %1; cvt.u32.u64 %0, t; }" : "=r"(a) : "l"(p));
    return a;
}

#define CP16(dst_u32, src_ptr) \
    asm volatile("cp.async.cg.shared.global [%0], [%1], 16;" :: "r"(dst_u32), "l"(src_ptr))
#define CP_COMMIT() asm volatile("cp.async.commit_group;" ::: "memory")
template<int N> __device__ __forceinline__ void cp_wait() {
    asm volatile("cp.async.wait_group %0;" :: "n"(N) : "memory");
}

__device__ __forceinline__ void ldmx4(uint32_t addr, uint32_t r[4]) {
    asm volatile("ldmatrix.sync.aligned.m8n8.x4.shared.b16 {%0,%1,%2,%3}, [%4];"
        : "=r"(r[0]), "=r"(r[1]), "=r"(r[2]), "=r"(r[3]) : "r"(addr));
}

__device__ __forceinline__ void mma16816(float* c, const uint32_t a[4],
                                         uint32_t b0, uint32_t b1) {
    asm volatile("mma.sync.aligned.m16n8k16.row.col.f32.bf16.bf16.f32 "
        "{%0,%1,%2,%3}, {%4,%5,%6,%7}, {%8,%9}, {%0,%1,%2,%3};"
        : "+f"(c[0]), "+f"(c[1]), "+f"(c[2]), "+f"(c[3])
        : "r"(a[0]), "r"(a[1]), "r"(a[2]), "r"(a[3]), "r"(b0), "r"(b1));
}

#define STS128(addr, a, b, c, d) \
    asm volatile("st.shared.v4.b32 [%0], {%1,%2,%3,%4};" \
        :: "r"(addr), "r"(a), "r"(b), "r"(c), "r"(d) : "memory")

__device__ __forceinline__ uint32_t swz(int row, int chunk16) {
    return (uint32_t)(row * 128 + ((chunk16 ^ (row & 7)) * 16));
}

__device__ __forceinline__ void split2(float a, float b, uint32_t& hi, uint32_t& lo) {
    __nv_bfloat162 h2 = __floats2bfloat162_rn(a, b);
    float ra = a - __bfloat162float(__low2bfloat16(h2));
    float rb = b - __bfloat162float(__high2bfloat16(h2));
    __nv_bfloat162 l2 = __floats2bfloat162_rn(ra, rb);
    hi = *reinterpret_cast<uint32_t*>(&h2);
    lo = *reinterpret_cast<uint32_t*>(&l2);
}

__device__ __forceinline__ void split1(float a, __nv_bfloat16& hi, __nv_bfloat16& lo) {
    hi = __float2bfloat16_rn(a);
    lo = __float2bfloat16_rn(a - __bfloat162float(hi));
}

// ===================== combined enc+wk split ================================
#define ENC_BLKS ((B_ * S_ * ENC_) / 1024)   // 16384
#define WK_BLKS  ((H_ * ENC_) / 1024)        // 1024

__global__ void split2src_kernel(const float* __restrict__ enc,
                                 __nv_bfloat16* __restrict__ eh,
                                 __nv_bfloat16* __restrict__ el,
                                 const float* __restrict__ wk,
                                 __nv_bfloat16* __restrict__ wh,
                                 __nv_bfloat16* __restrict__ wl) {
    const float* src;
    __nv_bfloat16 *hi, *lo;
    long i;
    if (blockIdx.x < ENC_BLKS) {
        i = ((long)blockIdx.x * 256 + threadIdx.x) * 4;
        src = enc; hi = eh; lo = el;
    } else {
        i = ((long)(blockIdx.x - ENC_BLKS) * 256 + threadIdx.x) * 4;
        src = wk; hi = wh; lo = wl;
    }
    float4 v = *reinterpret_cast<const float4*>(src + i);
    uint2 H, L;
    split2(v.x, v.y, H.x, L.x);
    split2(v.z, v.w, H.y, L.y);
    *reinterpret_cast<uint2*>(hi + i) = H;
    *reinterpret_cast<uint2*>(lo + i) = L;
}

// ===================== prep: mask compact + energy init + h1 split ===========
__global__ void prep_kernel(const int* __restrict__ mask,
                            const float* __restrict__ hidden,
                            float* __restrict__ energy,
                            __nv_bfloat16* __restrict__ h1h,
                            __nv_bfloat16* __restrict__ h1l) {
    const int tid = threadIdx.x;
    if (blockIdx.x < B_) {
        const int b = blockIdx.x;
        __shared__ int sc[256];
        int m = (mask[b * S_ + tid] != 0) ? 1 : 0;
        sc[tid] = m;
        __syncthreads();
#pragma unroll
        for (int off = 1; off < 256; off <<= 1) {
            int t = (tid >= off) ? sc[tid - off] : 0;
            __syncthreads();
            sc[tid] += t;
            __syncthreads();
        }
        int total = sc[255];
        int my = sc[tid] - m;
        if (m) g_sidx[b * S_ + my] = tid;
        if (tid >= total) g_sidx[b * S_ + tid] = 0;
        energy[b * S_ + tid] = m ? 0.f : -1e10f;
        if (tid == 0) g_scnt[b] = total;
    } else {
        long i = ((long)(blockIdx.x - B_) * 256 + tid) * 4;
        float4 v = *reinterpret_cast<const float4*>(hidden + (long)B_ * H_ + i);
        uint2 H, L;
        split2(v.x, v.y, H.x, L.x);
        split2(v.z, v.w, H.y, L.y);
        *reinterpret_cast<uint2*>(h1h + i) = H;
        *reinterpret_cast<uint2*>(h1l + i) = L;
    }
}

// ===================== fat-B HMMA kernel (query/gates/wout) ==================
#define WO_A_TILE 8192
#define WO_B_TILE 16384
#define WO_STAGE  (2 * WO_A_TILE + 2 * WO_B_TILE)   // 48KB
#define WO_SMEM_BYTES (1024 + 2 * WO_STAGE)

__device__ __forceinline__ void wo_load_A(const __nv_bfloat16* fh, const __nv_bfloat16* fl,
                                          int lda, int c0, uint32_t stg) {
    const int tid = threadIdx.x;
#pragma unroll
    for (int i = 0; i < 2; i++) {
        int idx = tid + i * 256;
        int r = idx >> 3, cc = idx & 7;
        uint32_t off = swz(r, cc);
        long src = (long)r * lda + c0 + cc * 8;
        CP16(stg + off, fh + src);
        CP16(stg + WO_A_TILE + off, fl + src);
    }
}

__global__ __launch_bounds__(256, 1)
void hmma_m64_kernel(const __nv_bfloat16* __restrict__ ah_g,
                     const __nv_bfloat16* __restrict__ al_g,
                     int Ktot,
                     const float* __restrict__ B1, int k1,
                     const float* __restrict__ B2,
                     const float* __restrict__ bias1,
                     const float* __restrict__ bias2,
                     float* __restrict__ C, int ldc) {
    extern __shared__ char smem[];
    uint32_t sb = smem_to_u32(smem);
    uint32_t tiles = (sb + 1023) & ~1023u;

    const int tid = threadIdx.x;
    const int wid = tid >> 5, lane = tid & 31;
    const int warp_m = (wid & 1) * 32;
    const int warp_n = (wid >> 1) * 32;
    const int n0 = blockIdx.x * 128;

    const int br = tid >> 1;
    const int bhalf = tid & 1;
    const int k2 = Ktot - k1;

    float c[2][4][4];
#pragma unroll
    for (int i = 0; i < 2; i++)
#pragma unroll
        for (int j = 0; j < 4; j++)
#pragma unroll
            for (int k = 0; k < 4; k++) c[i][j][k] = 0.f;

    wo_load_A(ah_g, al_g, Ktot, 0, tiles);
    CP_COMMIT();

    const float* w0 = B1 + (long)(n0 + br) * k1 + bhalf * 32;
    float4 nb[8];
#pragma unroll
    for (int j = 0; j < 4; j++) {
        nb[2 * j]     = *reinterpret_cast<const float4*>(w0 + j * 8);
        nb[2 * j + 1] = *reinterpret_cast<const float4*>(w0 + j * 8 + 4);
    }

    const int KT = Ktot / 64;
    for (int kt = 0; kt < KT; kt++) {
        uint32_t stg = tiles + (kt & 1) * WO_STAGE;
        if (kt + 1 < KT) {
            wo_load_A(ah_g, al_g, Ktot, (kt + 1) * 64, tiles + ((kt + 1) & 1) * WO_STAGE);
            CP_COMMIT();
        }
        uint32_t Bh = stg + 2 * WO_A_TILE, Bl = Bh + WO_B_TILE;
#pragma unroll
        for (int j = 0; j < 4; j++) {
            float4 v0 = nb[2 * j], v1 = nb[2 * j + 1];
            uint4 Hq, Lq;
            split2(v0.x, v0.y, Hq.x, Lq.x);
            split2(v0.z, v0.w, Hq.y, Lq.y);
            split2(v1.x, v1.y, Hq.z, Lq.z);
            split2(v1.z, v1.w, Hq.w, Lq.w);
            uint32_t off = swz(br, bhalf * 4 + j);
            STS128(Bh + off, Hq.x, Hq.y, Hq.z, Hq.w);
            STS128(Bl + off, Lq.x, Lq.y, Lq.z, Lq.w);
        }
        if (kt + 1 < KT) cp_wait<1>(); else cp_wait<0>();
        __syncthreads();
        if (kt + 1 < KT) {
            int c0 = (kt + 1) * 64;
            const float* wn = (c0 < k1)
                ? B1 + (long)(n0 + br) * k1 + c0 + bhalf * 32
                : B2 + (long)(n0 + br) * k2 + (c0 - k1) + bhalf * 32;
#pragma unroll
            for (int j = 0; j < 4; j++) {
                nb[2 * j]     = *reinterpret_cast<const float4*>(wn + j * 8);
                nb[2 * j + 1] = *reinterpret_cast<const float4*>(wn + j * 8 + 4);
            }
        }
        {
            const uint32_t Ah = stg, Al = stg + WO_A_TILE;
            const int lm = lane & 15, lh = lane >> 4;
#pragma unroll
            for (int ks = 0; ks < 4; ks++) {
                const int ch = ks * 2 + lh;
                uint32_t ah[2][4], al[2][4];
#pragma unroll
                for (int mf = 0; mf < 2; mf++) {
                    uint32_t off = swz(warp_m + mf * 16 + lm, ch);
                    ldmx4(Ah + off, ah[mf]);
                    ldmx4(Al + off, al[mf]);
                }
                uint32_t bb[2][4];
#pragma unroll
                for (int nf2 = 0; nf2 < 2; nf2++) {
                    uint32_t off = swz(warp_n + nf2 * 16 + lm, ch);
                    ldmx4(Bh + off, bb[nf2]);
                }
#pragma unroll
                for (int nf2 = 0; nf2 < 2; nf2++)
#pragma unroll
                    for (int mf = 0; mf < 2; mf++) {
                        mma16816(c[mf][nf2 * 2 + 0], ah[mf], bb[nf2][0], bb[nf2][2]);
                        mma16816(c[mf][nf2 * 2 + 1], ah[mf], bb[nf2][1], bb[nf2][3]);
                        mma16816(c[mf][nf2 * 2 + 0], al[mf], bb[nf2][0], bb[nf2][2]);
                        mma16816(c[mf][nf2 * 2 + 1], al[mf], bb[nf2][1], bb[nf2][3]);
                    }
#pragma unroll
                for (int nf2 = 0; nf2 < 2; nf2++) {
                    uint32_t off = swz(warp_n + nf2 * 16 + lm, ch);
                    ldmx4(Bl + off, bb[nf2]);
                }
#pragma unroll
                for (int nf2 = 0; nf2 < 2; nf2++)
#pragma unroll
                    for (int mf = 0; mf < 2; mf++) {
                        mma16816(c[mf][nf2 * 2 + 0], ah[mf], bb[nf2][0], bb[nf2][2]);
                        mma16816(c[mf][nf2 * 2 + 1], ah[mf], bb[nf2][1], bb[nf2][3]);
                    }
            }
        }
        __syncthreads();
    }

#pragma unroll
    for (int mf = 0; mf < 2; mf++)
#pragma unroll
        for (int nf = 0; nf < 4; nf++) {
            int col = n0 + warp_n + nf * 8 + (lane & 3) * 2;
            float b0 = 0.f, b1 = 0.f;
            if (bias1) { b0 += bias1[col]; b1 += bias1[col + 1]; }
            if (bias2) { b0 += bias2[col]; b1 += bias2[col + 1]; }
            int r0 = warp_m + mf * 16 + (lane >> 2);
            float2 o0 = {c[mf][nf][0] + b0, c[mf][nf][1] + b1};
            float2 o1 = {c[mf][nf][2] + b0, c[mf][nf][3] + b1};
            *reinterpret_cast<float2*>(C + (long)r0 * ldc + col) = o0;
            *reinterpret_cast<float2*>(C + (long)(r0 + 8) * ldc + col) = o1;
        }
}

// ===================== energy kernel: gathered M=64 tiles ====================
// grid (8 n-blocks, B_*4 m-tiles). Tile = 64 gathered s-rows x 128 h-cols.
// A = gathered enc hi/lo rows (via sidx), B = wk hi/lo. 3-term split.
// epilogue: energy[b, sidx[r]] += sum_h v[h]*tanh(q[b,h] + C[r,h])
#define EN_A_TILE 8192
#define EN_B_TILE 16384
#define EN_STAGE  (2 * EN_A_TILE + 2 * EN_B_TILE)   // 48KB
#define EN_SMEM_BYTES (2048 + 2 * EN_STAGE)

__global__ __launch_bounds__(256, 1)
void energy64_mma_kernel(const __nv_bfloat16* __restrict__ eh,
                         const __nv_bfloat16* __restrict__ el,
                         const __nv_bfloat16* __restrict__ wh,
                         const __nv_bfloat16* __restrict__ wl,
                         const float* __restrict__ vvec,
                         const float* __restrict__ query,
                         float* __restrict__ energy) {
    const int b  = blockIdx.y >> 2;
    const int mt = (blockIdx.y & 3) * 64;
    const int cnt = g_scnt[b];
    if (mt >= cnt) return;

    extern __shared__ char smem[];
    uint32_t sb = smem_to_u32(smem);
    uint32_t tiles = (sb + 1024 + 1023) & ~1023u;

    const int tid = threadIdx.x;
    const int wid = tid >> 5, lane = tid & 31;
    const int warp_m = (wid & 1) * 32;
    const int warp_n = (wid >> 1) * 32;
    const int n0 = blockIdx.x * 128;

    float* vs = (float*)smem;
    float* qs = vs + 128;
    if (tid < 128) { vs[tid] = vvec[n0 + tid]; qs[tid] = query[b * H_ + n0 + tid]; }

    // gathered global row indices for this thread's two A-load rows
    const int lr = tid >> 3;                 // 0..31
    const long ga0 = (long)b * S_ + g_sidx[b * S_ + mt + lr];
    const long ga1 = (long)b * S_ + g_sidx[b * S_ + mt + lr + 32];
    const int lc = (tid & 7) * 8;            // element col within k-tile

    float c[2][4][4];
#pragma unroll
    for (int i = 0; i < 2; i++)
#pragma unroll
        for (int j = 0; j < 4; j++)
#pragma unroll
            for (int k = 0; k < 4; k++) c[i][j][k] = 0.f;

    // stage loader
    auto load_stage = [&](int c0, uint32_t stg) {
        uint32_t offA0 = swz(lr, tid & 7);
        uint32_t offA1 = swz(lr + 32, tid & 7);
        CP16(stg + offA0, eh + ga0 * ENC_ + c0 + lc);
        CP16(stg + EN_A_TILE + offA0, el + ga0 * ENC_ + c0 + lc);
        CP16(stg + offA1, eh + ga1 * ENC_ + c0 + lc);
        CP16(stg + EN_A_TILE + offA1, el + ga1 * ENC_ + c0 + lc);
        uint32_t Bh = stg + 2 * EN_A_TILE, Bl = Bh + EN_B_TILE;
#pragma unroll
        for (int i = 0; i < 4; i++) {
            int r = lr + i * 32;
            uint32_t off = swz(r, tid & 7);
            long src = (long)(n0 + r) * ENC_ + c0 + lc;
            CP16(Bh + off, wh + src);
            CP16(Bl + off, wl + src);
        }
    };

    load_stage(0, tiles);
    CP_COMMIT();

    const int KT = ENC_ / 64;   // 16
    for (int kt = 0; kt < KT; kt++) {
        uint32_t stg = tiles + (kt & 1) * EN_STAGE;
        if (kt + 1 < KT) {
            load_stage((kt + 1) * 64, tiles + ((kt + 1) & 1) * EN_STAGE);
            CP_COMMIT();
            cp_wait<1>();
        } else {
            cp_wait<0>();
        }
        __syncthreads();
        {
            const uint32_t Ah = stg, Al = stg + EN_A_TILE;
            const uint32_t Bh = stg + 2 * EN_A_TILE, Bl = Bh + EN_B_TILE;
            const int lm = lane & 15, lh = lane >> 4;
#pragma unroll
            for (int ks = 0; ks < 4; ks++) {
                const int ch = ks * 2 + lh;
                uint32_t ah[2][4], al[2][4];
#pragma unroll
                for (int mf = 0; mf < 2; mf++) {
                    uint32_t off = swz(warp_m + mf * 16 + lm, ch);
                    ldmx4(Ah + off, ah[mf]);
                    ldmx4(Al + off, al[mf]);
                }
                uint32_t bb[2][4];
#pragma unroll
                for (int nf2 = 0; nf2 < 2; nf2++) {
                    uint32_t off = swz(warp_n + nf2 * 16 + lm, ch);
                    ldmx4(Bh + off, bb[nf2]);
                }
#pragma unroll
                for (int nf2 = 0; nf2 < 2; nf2++)
#pragma unroll
                    for (int mf = 0; mf < 2; mf++) {
                        mma16816(c[mf][nf2 * 2 + 0], ah[mf], bb[nf2][0], bb[nf2][2]);
                        mma16816(c[mf][nf2 * 2 + 1], ah[mf], bb[nf2][1], bb[nf2][3]);
                        mma16816(c[mf][nf2 * 2 + 0], al[mf], bb[nf2][0], bb[nf2][2]);
                        mma16816(c[mf][nf2 * 2 + 1], al[mf], bb[nf2][1], bb[nf2][3]);
                    }
#pragma unroll
                for (int nf2 = 0; nf2 < 2; nf2++) {
                    uint32_t off = swz(warp_n + nf2 * 16 + lm, ch);
                    ldmx4(Bl + off, bb[nf2]);
                }
#pragma unroll
                for (int nf2 = 0; nf2 < 2; nf2++)
#pragma unroll
                    for (int mf = 0; mf < 2; mf++) {
                        mma16816(c[mf][nf2 * 2 + 0], ah[mf], bb[nf2][0], bb[nf2][2]);
                        mma16816(c[mf][nf2 * 2 + 1], ah[mf], bb[nf2][1], bb[nf2][3]);
                    }
            }
        }
        __syncthreads();
    }

    // epilogue: v*tanh(q + C), reduce over this warp's 32 cols, scatter-add
#pragma unroll
    for (int mf = 0; mf < 2; mf++) {
        float s_lo = 0.f, s_hi = 0.f;
#pragma unroll
        for (int nf = 0; nf < 4; nf++) {
            int col = warp_n + nf * 8 + (lane & 3) * 2;
            float v0 = vs[col], v1 = vs[col + 1];
            float q0 = qs[col], q1 = qs[col + 1];
            s_lo += v0 * tanhf(q0 + c[mf][nf][0]) + v1 * tanhf(q1 + c[mf][nf][1]);
            s_hi += v0 * tanhf(q0 + c[mf][nf][2]) + v1 * tanhf(q1 + c[mf][nf][3]);
        }
        s_lo += __shfl_xor_sync(0xffffffff, s_lo, 1);
        s_lo += __shfl_xor_sync(0xffffffff, s_lo, 2);
        s_hi += __shfl_xor_sync(0xffffffff, s_hi, 1);
        s_hi += __shfl_xor_sync(0xffffffff, s_hi, 2);
        if ((lane & 3) == 0) {
            int r0 = warp_m + mf * 16 + (lane >> 2);
            if (mt + r0 < cnt)
                atomicAdd(&energy[b * S_ + g_sidx[b * S_ + mt + r0]], s_lo);
            if (mt + r0 + 8 < cnt)
                atomicAdd(&energy[b * S_ + g_sidx[b * S_ + mt + r0 + 8]], s_hi);
        }
    }
}

// ===================== fused softmax + compacted context =====================
__global__ void softmax_context_kernel(const float* __restrict__ energy,
                                       const float* __restrict__ enc,
                                       float* __restrict__ out_attn) {
    __shared__ float red[256];
    __shared__ float w[256];
    __shared__ int sid[256];
    __shared__ int cnts;
    const int b = blockIdx.x;
    const int tid = threadIdx.x;

    float val = energy[b * S_ + tid];
    red[tid] = val;
    sid[tid] = g_sidx[b * S_ + tid];
    if (tid == 0) cnts = g_scnt[b];
    __syncthreads();
#pragma unroll
    for (int off = 128; off > 0; off >>= 1) {
        if (tid < off) red[tid] = fmaxf(red[tid], red[tid + off]);
        __syncthreads();
    }
    float mx = red[0];
    __syncthreads();
    float ex = expf(val - mx);
    red[tid] = ex;
    __syncthreads();
#pragma unroll
    for (int off = 128; off > 0; off >>= 1) {
        if (tid < off) red[tid] += red[tid + off];
        __syncthreads();
    }
    float aw = ex / red[0];
    out_attn[b * S_ + tid] = aw;
    w[tid] = aw;
    __syncthreads();

    const int cnt = cnts;
    const float* eb = enc + (long)b * S_ * ENC_;
#pragma unroll
    for (int k = 0; k < 4; k++) {
        int col = k * 256 + tid;
        float acc = 0.f;
        for (int j = 0; j < cnt; j++) {
            int s = sid[j];
            acc = fmaf(w[s], eb[(long)s * ENC_ + col], acc);
        }
        __nv_bfloat16 hi, lo;
        split1(acc, hi, lo);
        g_a0_hi[b * KCAT0 + E_ + col] = hi;
        g_a0_lo[b * KCAT0 + E_ + col] = lo;
        g_feat_hi[b * FDIM_ + H_ + col] = hi;
        g_feat_lo[b * FDIM_ + H_ + col] = lo;
    }
}

// ===================== embed + hidden scatter (bf16 direct) ==================
__global__ void embed_kernel(const int* __restrict__ tok,
                             const float* __restrict__ emb,
                             const float* __restrict__ hidden) {
    const int b = blockIdx.x;
    const int t = tok[b];
    for (int j = threadIdx.x; j < E_; j += 256) {
        __nv_bfloat16 hi, lo;
        split1(emb[(long)t * E_ + j], hi, lo);
        g_a0_hi[b * KCAT0 + j] = hi;
        g_a0_lo[b * KCAT0 + j] = lo;
        g_feat_hi[b * FDIM_ + (H_ + ENC_) + j] = hi;
        g_feat_lo[b * FDIM_ + (H_ + ENC_) + j] = lo;
    }
    for (int j = threadIdx.x; j < H_; j += 256) {
        __nv_bfloat16 hi, lo;
        split1(hidden[b * H_ + j], hi, lo);               // hidden[0]
        g_a0_hi[b * KCAT0 + (E_ + ENC_) + j] = hi;
        g_a0_lo[b * KCAT0 + (E_ + ENC_) + j] = lo;
        split1(hidden[B_ * H_ + b * H_ + j], hi, lo);     // hidden[1]
        g_a1_hi[b * KCAT1 + H_ + j] = hi;
        g_a1_lo[b * KCAT1 + H_ + j] = lo;
    }
}

// ===================== LSTM pointwise (bf16 split output) ====================
__global__ void lstm_kernel(const float* __restrict__ gates,
                            const float* __restrict__ c_prev,
                            float* __restrict__ c_out,
                            float* __restrict__ h_out_f32,
                            __nv_bfloat16* __restrict__ hb_hi,
                            __nv_bfloat16* __restrict__ hb_lo,
                            int sb) {
    const int b = blockIdx.x;
    const int idx = blockIdx.y * 256 + threadIdx.x;
    float gi = gates[b * G4H_ + idx];
    float gf = gates[b * G4H_ + H_ + idx];
    float gg = gates[b * G4H_ + 2 * H_ + idx];
    float go = gates[b * G4H_ + 3 * H_ + idx];
    float c  = c_prev[b * H_ + idx];
    float si = 1.f / (1.f + expf(-gi));
    float sf = 1.f / (1.f + expf(-gf));
    float so = 1.f / (1.f + expf(-go));
    float cn = sf * c + si * tanhf(gg);
    float hn = so * tanhf(cn);
    c_out[b * H_ + idx]     = cn;
    h_out_f32[b * H_ + idx] = hn;
    __nv_bfloat16 hi, lo;
    split1(hn, hi, lo);
    hb_hi[b * sb + idx] = hi;
    hb_lo[b * sb + idx] = lo;
}

// ===================== launch ================================================
extern "C" void kernel_launch(void* const* d_in, const int* in_sizes, int n_in,
                              void* d_out, int out_size) {
    const int*   tok    = (const int*)  d_in[0];
    const float* hidden = (const float*)d_in[1];
    const float* cell   = (const float*)d_in[2];
    const float* enc    = (const float*)d_in[3];
    const int*   mask   = (const int*)  d_in[4];
    const float* emb    = (const float*)d_in[5];
    const float* Wq     = (const float*)d_in[6];
    const float* Wk     = (const float*)d_in[7];
    const float* v      = (const float*)d_in[8];
    const float* Wih0   = (const float*)d_in[9];
    const float* Whh0   = (const float*)d_in[10];
    const float* bih0   = (const float*)d_in[11];
    const float* bhh0   = (const float*)d_in[12];
    const float* Wih1   = (const float*)d_in[13];
    const float* Whh1   = (const float*)d_in[14];
    const float* bih1   = (const float*)d_in[15];
    const float* bhh1   = (const float*)d_in[16];
    const float* Wout   = (const float*)d_in[17];
    const float* bout   = (const float*)d_in[18];

    float* out      = (float*)d_out;
    float* out_pred = out;
    float* out_hid  = out + (long)B_ * V_;
    float* out_cell = out_hid + 2 * B_ * H_;
    float* out_attn = out_cell + 2 * B_ * H_;

    void* sp = nullptr;
    cudaGetSymbolAddress(&sp, g_scratch);
    float* scratch = (float*)sp;
    float* query  = scratch + OFF_QUERY;
    float* gates  = scratch + OFF_GATES;
    float* energy = scratch + OFF_ENERGY;

    void *p_eh, *p_el, *p_wh, *p_wl, *p_h1h, *p_h1l,
         *p_a0h, *p_a0l, *p_a1h, *p_a1l, *p_fh, *p_fl;
    cudaGetSymbolAddress(&p_eh,  g_enc_hi);
    cudaGetSymbolAddress(&p_el,  g_enc_lo);
    cudaGetSymbolAddress(&p_wh,  g_wk_hi);
    cudaGetSymbolAddress(&p_wl,  g_wk_lo);
    cudaGetSymbolAddress(&p_h1h, g_h1_hi);
    cudaGetSymbolAddress(&p_h1l, g_h1_lo);
    cudaGetSymbolAddress(&p_a0h, g_a0_hi);
    cudaGetSymbolAddress(&p_a0l, g_a0_lo);
    cudaGetSymbolAddress(&p_a1h, g_a1_hi);
    cudaGetSymbolAddress(&p_a1l, g_a1_lo);
    cudaGetSymbolAddress(&p_fh,  g_feat_hi);
    cudaGetSymbolAddress(&p_fl,  g_feat_lo);

    cudaFuncSetAttribute(hmma_m64_kernel,     cudaFuncAttributeMaxDynamicSharedMemorySize, WO_SMEM_BYTES);
    cudaFuncSetAttribute(energy64_mma_kernel, cudaFuncAttributeMaxDynamicSharedMemorySize, EN_SMEM_BYTES);

    // 1. combined enc + Wk bf16 split
    split2src_kernel<<<ENC_BLKS + WK_BLKS, 256>>>(
        enc, (__nv_bfloat16*)p_eh, (__nv_bfloat16*)p_el,
        Wk,  (__nv_bfloat16*)p_wh, (__nv_bfloat16*)p_wl);

    // 2. prep: mask compaction + energy init + hidden[1] split
    prep_kernel<<<B_ + (B_ * H_) / 1024, 256>>>(
        mask, hidden, energy, (__nv_bfloat16*)p_h1h, (__nv_bfloat16*)p_h1l);

    // 3. query = hidden[1] @ Wq^T
    hmma_m64_kernel<<<H_ / 128, 256, WO_SMEM_BYTES>>>(
        (const __nv_bfloat16*)p_h1h, (const __nv_bfloat16*)p_h1l, H_,
        Wq, H_, Wq, nullptr, nullptr, query, H_);

    // 4. energy: gathered unmasked rows only (profiled launch)
    energy64_mma_kernel<<<dim3(H_ / 128, B_ * 4), 256, EN_SMEM_BYTES>>>(
        (const __nv_bfloat16*)p_eh, (const __nv_bfloat16*)p_el,
        (const __nv_bfloat16*)p_wh, (const __nv_bfloat16*)p_wl, v, query, energy);

    // 5. embedding + hidden scatter (bf16 direct)
    embed_kernel<<<B_, 256>>>(tok, emb, hidden);

    // 6. fused masked softmax + compacted context (bf16 direct)
    softmax_context_kernel<<<B_, 256>>>(energy, enc, out_attn);

    // 7. layer-0 gates + LSTM
    hmma_m64_kernel<<<G4H_ / 128, 256, WO_SMEM_BYTES>>>(
        (const __nv_bfloat16*)p_a0h, (const __nv_bfloat16*)p_a0l, KCAT0,
        Wih0, E_ + ENC_, Whh0, bih0, bhh0, gates, G4H_);
    lstm_kernel<<<dim3(B_, H_ / 256), 256>>>(gates, cell, out_cell, out_hid,
                                             (__nv_bfloat16*)p_a1h, (__nv_bfloat16*)p_a1l, KCAT1);

    // 8. layer-1 gates + LSTM
    hmma_m64_kernel<<<G4H_ / 128, 256, WO_SMEM_BYTES>>>(
        (const __nv_bfloat16*)p_a1h, (const __nv_bfloat16*)p_a1l, KCAT1,
        Wih1, H_, Whh1, bih1, bhh1, gates, G4H_);
    lstm_kernel<<<dim3(B_, H_ / 256), 256>>>(gates, cell + B_ * H_, out_cell + B_ * H_,
                                             out_hid + B_ * H_,
                                             (__nv_bfloat16*)p_fh, (__nv_bfloat16*)p_fl, FDIM_);

    // 9. prediction = feat @ Wout^T + bout
    hmma_m64_kernel<<<V_ / 128, 256, WO_SMEM_BYTES>>>(
        (const __nv_bfloat16*)p_fh, (const __nv_bfloat16*)p_fl, FDIM_,
        Wout, FDIM_, Wout, bout, nullptr, out_pred, V_);
}

// round 6
// speedup vs baseline: 4.6581x; 1.3652x over previous
#include <cuda_runtime.h>
#include <cuda_bf16.h>
#include <math.h>
#include <stdint.h>

#define B_   64
#define S_   256
#define H_   1024
#define ENC_ 1024
#define E_   512
#define V_   32000
#define FDIM_ (H_ + ENC_ + E_)   // 2560
#define G4H_  (4 * H_)           // 4096
#define KCAT0 2560               // emb(512)|ctx(1024)|hidden0(1024)
#define KCAT1 2048               // h0(1024)|hidden1(1024)

// ---------------- scratch (device globals) ----------------------------------
#define OFF_QUERY   0
#define OFF_GATES0  (OFF_QUERY + B_ * H_)
#define OFF_GATES1  (OFF_GATES0 + B_ * G4H_)
#define OFF_ENERGY  (OFF_GATES1 + B_ * G4H_)
#define SCRATCH_TOTAL (OFF_ENERGY + B_ * S_)

__device__ __align__(16) float g_scratch[SCRATCH_TOTAL];
__device__ int g_sidx[B_ * S_];
__device__ int g_scnt[B_];

// bf16 split buffers
__device__ __align__(16) __nv_bfloat16 g_enc_hi[(long)B_ * S_ * ENC_];
__device__ __align__(16) __nv_bfloat16 g_enc_lo[(long)B_ * S_ * ENC_];
__device__ __align__(16) __nv_bfloat16 g_wk_hi[H_ * ENC_];
__device__ __align__(16) __nv_bfloat16 g_wk_lo[H_ * ENC_];
__device__ __align__(16) __nv_bfloat16 g_h1_hi[B_ * H_];
__device__ __align__(16) __nv_bfloat16 g_h1_lo[B_ * H_];
__device__ __align__(16) __nv_bfloat16 g_a0_hi[B_ * KCAT0];
__device__ __align__(16) __nv_bfloat16 g_a0_lo[B_ * KCAT0];
__device__ __align__(16) __nv_bfloat16 g_a1_hi[B_ * KCAT1];
__device__ __align__(16) __nv_bfloat16 g_a1_lo[B_ * KCAT1];
__device__ __align__(16) __nv_bfloat16 g_feat_hi[B_ * FDIM_];
__device__ __align__(16) __nv_bfloat16 g_feat_lo[B_ * FDIM_];

// ===================== low-level helpers =====================================
__device__ __forceinline__ uint32_t smem_to_u32(const void* p) {
    uint32_t a;
    asm("{ .reg .u64 t; cvta.to.shared.u64 t, %1; cvt.u32.u64 %0, t; }" : "=r"(a) : "l"(p));
    return a;
}

#define CP16(dst_u32, src_ptr) \
    asm volatile("cp.async.cg.shared.global [%0], [%1], 16;" :: "r"(dst_u32), "l"(src_ptr))
#define CP_COMMIT() asm volatile("cp.async.commit_group;" ::: "memory")
template<int N> __device__ __forceinline__ void cp_wait() {
    asm volatile("cp.async.wait_group %0;" :: "n"(N) : "memory");
}

__device__ __forceinline__ void ldmx4(uint32_t addr, uint32_t r[4]) {
    asm volatile("ldmatrix.sync.aligned.m8n8.x4.shared.b16 {%0,%1,%2,%3}, [%4];"
        : "=r"(r[0]), "=r"(r[1]), "=r"(r[2]), "=r"(r[3]) : "r"(addr));
}

__device__ __forceinline__ void mma16816(float* c, const uint32_t a[4],
                                         uint32_t b0, uint32_t b1) {
    asm volatile("mma.sync.aligned.m16n8k16.row.col.f32.bf16.bf16.f32 "
        "{%0,%1,%2,%3}, {%4,%5,%6,%7}, {%8,%9}, {%0,%1,%2,%3};"
        : "+f"(c[0]), "+f"(c[1]), "+f"(c[2]), "+f"(c[3])
        : "r"(a[0]), "r"(a[1]), "r"(a[2]), "r"(a[3]), "r"(b0), "r"(b1));
}

#define STS128(addr, a, b, c, d) \
    asm volatile("st.shared.v4.b32 [%0], {%1,%2,%3,%4};" \
        :: "r"(addr), "r"(a), "r"(b), "r"(c), "r"(d) : "memory")

__device__ __forceinline__ uint32_t swz(int row, int chunk16) {
    return (uint32_t)(row * 128 + ((chunk16 ^ (row & 7)) * 16));
}

__device__ __forceinline__ void split2(float a, float b, uint32_t& hi, uint32_t& lo) {
    __nv_bfloat162 h2 = __floats2bfloat162_rn(a, b);
    float ra = a - __bfloat162float(__low2bfloat16(h2));
    float rb = b - __bfloat162float(__high2bfloat16(h2));
    __nv_bfloat162 l2 = __floats2bfloat162_rn(ra, rb);
    hi = *reinterpret_cast<uint32_t*>(&h2);
    lo = *reinterpret_cast<uint32_t*>(&l2);
}

__device__ __forceinline__ void split1(float a, __nv_bfloat16& hi, __nv_bfloat16& lo) {
    hi = __float2bfloat16_rn(a);
    lo = __float2bfloat16_rn(a - __bfloat162float(hi));
}

// ===================== combined enc+wk split ================================
#define ENC_BLKS ((B_ * S_ * ENC_) / 1024)   // 16384
#define WK_BLKS  ((H_ * ENC_) / 1024)        // 1024

__global__ void split2src_kernel(const float* __restrict__ enc,
                                 __nv_bfloat16* __restrict__ eh,
                                 __nv_bfloat16* __restrict__ el,
                                 const float* __restrict__ wk,
                                 __nv_bfloat16* __restrict__ wh,
                                 __nv_bfloat16* __restrict__ wl) {
    const float* src;
    __nv_bfloat16 *hi, *lo;
    long i;
    if (blockIdx.x < ENC_BLKS) {
        i = ((long)blockIdx.x * 256 + threadIdx.x) * 4;
        src = enc; hi = eh; lo = el;
    } else {
        i = ((long)(blockIdx.x - ENC_BLKS) * 256 + threadIdx.x) * 4;
        src = wk; hi = wh; lo = wl;
    }
    float4 v = *reinterpret_cast<const float4*>(src + i);
    uint2 H, L;
    split2(v.x, v.y, H.x, L.x);
    split2(v.z, v.w, H.y, L.y);
    *reinterpret_cast<uint2*>(hi + i) = H;
    *reinterpret_cast<uint2*>(lo + i) = L;
}

// ===================== mega-prep kernel ======================================
// blk [0,64): per-b mask compact + energy init + embed + hidden scatter
// blk [64,128): h1 bf16 split
// blk [128,192): query zero-init
// blk [192,448): gates0 init = bih0+bhh0
// blk [448,704): gates1 init = bih1+bhh1
#define PREP_BLKS 704

__global__ void prep_kernel(const int* __restrict__ mask,
                            const float* __restrict__ hidden,
                            const int* __restrict__ tok,
                            const float* __restrict__ emb,
                            const float* __restrict__ bih0,
                            const float* __restrict__ bhh0,
                            const float* __restrict__ bih1,
                            const float* __restrict__ bhh1,
                            float* __restrict__ energy,
                            float* __restrict__ query,
                            float* __restrict__ gates0,
                            float* __restrict__ gates1,
                            __nv_bfloat16* __restrict__ h1h,
                            __nv_bfloat16* __restrict__ h1l) {
    const int tid = threadIdx.x;
    const int blk = blockIdx.x;
    if (blk < B_) {
        const int b = blk;
        // ---- mask compact + energy init ----
        __shared__ int sc[256];
        int m = (mask[b * S_ + tid] != 0) ? 1 : 0;
        sc[tid] = m;
        __syncthreads();
#pragma unroll
        for (int off = 1; off < 256; off <<= 1) {
            int t = (tid >= off) ? sc[tid - off] : 0;
            __syncthreads();
            sc[tid] += t;
            __syncthreads();
        }
        int total = sc[255];
        int my = sc[tid] - m;
        if (m) g_sidx[b * S_ + my] = tid;
        if (tid >= total) g_sidx[b * S_ + tid] = 0;
        energy[b * S_ + tid] = m ? 0.f : -1e10f;
        if (tid == 0) g_scnt[b] = total;
        // ---- embed scatter ----
        const int t = tok[b];
        for (int j = tid; j < E_; j += 256) {
            __nv_bfloat16 hi, lo;
            split1(emb[(long)t * E_ + j], hi, lo);
            g_a0_hi[b * KCAT0 + j] = hi;
            g_a0_lo[b * KCAT0 + j] = lo;
            g_feat_hi[b * FDIM_ + (H_ + ENC_) + j] = hi;
            g_feat_lo[b * FDIM_ + (H_ + ENC_) + j] = lo;
        }
        // ---- hidden scatter ----
        for (int j = tid; j < H_; j += 256) {
            __nv_bfloat16 hi, lo;
            split1(hidden[b * H_ + j], hi, lo);               // hidden[0]
            g_a0_hi[b * KCAT0 + (E_ + ENC_) + j] = hi;
            g_a0_lo[b * KCAT0 + (E_ + ENC_) + j] = lo;
            split1(hidden[B_ * H_ + b * H_ + j], hi, lo);     // hidden[1]
            g_a1_hi[b * KCAT1 + H_ + j] = hi;
            g_a1_lo[b * KCAT1 + H_ + j] = lo;
        }
    } else if (blk < 128) {
        long i = ((long)(blk - 64) * 256 + tid) * 4;
        float4 v = *reinterpret_cast<const float4*>(hidden + (long)B_ * H_ + i);
        uint2 H, L;
        split2(v.x, v.y, H.x, L.x);
        split2(v.z, v.w, H.y, L.y);
        *reinterpret_cast<uint2*>(h1h + i) = H;
        *reinterpret_cast<uint2*>(h1l + i) = L;
    } else if (blk < 192) {
        long i = ((long)(blk - 128) * 256 + tid) * 4;
        float4 z = {0.f, 0.f, 0.f, 0.f};
        *reinterpret_cast<float4*>(query + i) = z;
    } else if (blk < 448) {
        long i = ((long)(blk - 192) * 256 + tid) * 4;
        int n = (int)(i & (G4H_ - 1));
        float4 o;
        o.x = bih0[n] + bhh0[n];
        o.y = bih0[n + 1] + bhh0[n + 1];
        o.z = bih0[n + 2] + bhh0[n + 2];
        o.w = bih0[n + 3] + bhh0[n + 3];
        *reinterpret_cast<float4*>(gates0 + i) = o;
    } else {
        long i = ((long)(blk - 448) * 256 + tid) * 4;
        int n = (int)(i & (G4H_ - 1));
        float4 o;
        o.x = bih1[n] + bhh1[n];
        o.y = bih1[n + 1] + bhh1[n + 1];
        o.z = bih1[n + 2] + bhh1[n + 2];
        o.w = bih1[n + 3] + bhh1[n + 3];
        *reinterpret_cast<float4*>(gates1 + i) = o;
    }
}

// ===================== fat-B HMMA kernel (query/gates/wout) ==================
// C[0:64, n0:n0+128] (+=) A[64,Ktot] @ Bcat^T over k-range [ky*KT/nks, ...)
// ATOMIC=true: atomicAdd into pre-initialized C (bias already there).
#define WO_A_TILE 8192
#define WO_B_TILE 16384
#define WO_STAGE  (2 * WO_A_TILE + 2 * WO_B_TILE)   // 48KB
#define WO_SMEM_BYTES (1024 + 2 * WO_STAGE)

__device__ __forceinline__ void wo_load_A(const __nv_bfloat16* fh, const __nv_bfloat16* fl,
                                          int lda, int c0, uint32_t stg) {
    const int tid = threadIdx.x;
#pragma unroll
    for (int i = 0; i < 2; i++) {
        int idx = tid + i * 256;
        int r = idx >> 3, cc = idx & 7;
        uint32_t off = swz(r, cc);
        long src = (long)r * lda + c0 + cc * 8;
        CP16(stg + off, fh + src);
        CP16(stg + WO_A_TILE + off, fl + src);
    }
}

template<bool ATOMIC>
__global__ __launch_bounds__(256, 1)
void hmma_m64_kernel(const __nv_bfloat16* __restrict__ ah_g,
                     const __nv_bfloat16* __restrict__ al_g,
                     int Ktot,
                     const float* __restrict__ B1, int k1,
                     const float* __restrict__ B2,
                     const float* __restrict__ bias1,
                     float* __restrict__ C, int ldc, int nks) {
    extern __shared__ char smem[];
    uint32_t sb = smem_to_u32(smem);
    uint32_t tiles = (sb + 1023) & ~1023u;

    const int tid = threadIdx.x;
    const int wid = tid >> 5, lane = tid & 31;
    const int warp_m = (wid & 1) * 32;
    const int warp_n = (wid >> 1) * 32;
    const int n0 = blockIdx.x * 128;

    const int br = tid >> 1;
    const int bhalf = tid & 1;
    const int k2 = Ktot - k1;

    const int KT = Ktot / 64;
    const int kt0 = (int)blockIdx.y * (KT / nks);
    const int kt1 = kt0 + KT / nks;

    auto bptr = [&](int c0) -> const float* {
        return (c0 < k1) ? B1 + (long)(n0 + br) * k1 + c0 + bhalf * 32
                         : B2 + (long)(n0 + br) * k2 + (c0 - k1) + bhalf * 32;
    };

    float c[2][4][4];
#pragma unroll
    for (int i = 0; i < 2; i++)
#pragma unroll
        for (int j = 0; j < 4; j++)
#pragma unroll
            for (int k = 0; k < 4; k++) c[i][j][k] = 0.f;

    wo_load_A(ah_g, al_g, Ktot, kt0 * 64, tiles + (kt0 & 1) * WO_STAGE);
    CP_COMMIT();

    const float* w0 = bptr(kt0 * 64);
    float4 nb[8];
#pragma unroll
    for (int j = 0; j < 4; j++) {
        nb[2 * j]     = *reinterpret_cast<const float4*>(w0 + j * 8);
        nb[2 * j + 1] = *reinterpret_cast<const float4*>(w0 + j * 8 + 4);
    }

    for (int kt = kt0; kt < kt1; kt++) {
        uint32_t stg = tiles + (kt & 1) * WO_STAGE;
        if (kt + 1 < kt1) {
            wo_load_A(ah_g, al_g, Ktot, (kt + 1) * 64, tiles + ((kt + 1) & 1) * WO_STAGE);
            CP_COMMIT();
        }
        uint32_t Bh = stg + 2 * WO_A_TILE, Bl = Bh + WO_B_TILE;
#pragma unroll
        for (int j = 0; j < 4; j++) {
            float4 v0 = nb[2 * j], v1 = nb[2 * j + 1];
            uint4 Hq, Lq;
            split2(v0.x, v0.y, Hq.x, Lq.x);
            split2(v0.z, v0.w, Hq.y, Lq.y);
            split2(v1.x, v1.y, Hq.z, Lq.z);
            split2(v1.z, v1.w, Hq.w, Lq.w);
            uint32_t off = swz(br, bhalf * 4 + j);
            STS128(Bh + off, Hq.x, Hq.y, Hq.z, Hq.w);
            STS128(Bl + off, Lq.x, Lq.y, Lq.z, Lq.w);
        }
        if (kt + 1 < kt1) cp_wait<1>(); else cp_wait<0>();
        __syncthreads();
        if (kt + 1 < kt1) {
            const float* wn = bptr((kt + 1) * 64);
#pragma unroll
            for (int j = 0; j < 4; j++) {
                nb[2 * j]     = *reinterpret_cast<const float4*>(wn + j * 8);
                nb[2 * j + 1] = *reinterpret_cast<const float4*>(wn + j * 8 + 4);
            }
        }
        {
            const uint32_t Ah = stg, Al = stg + WO_A_TILE;
            const int lm = lane & 15, lh = lane >> 4;
#pragma unroll
            for (int ks = 0; ks < 4; ks++) {
                const int ch = ks * 2 + lh;
                uint32_t ah[2][4], al[2][4];
#pragma unroll
                for (int mf = 0; mf < 2; mf++) {
                    uint32_t off = swz(warp_m + mf * 16 + lm, ch);
                    ldmx4(Ah + off, ah[mf]);
                    ldmx4(Al + off, al[mf]);
                }
                uint32_t bb[2][4];
#pragma unroll
                for (int nf2 = 0; nf2 < 2; nf2++) {
                    uint32_t off = swz(warp_n + nf2 * 16 + lm, ch);
                    ldmx4(Bh + off, bb[nf2]);
                }
#pragma unroll
                for (int nf2 = 0; nf2 < 2; nf2++)
#pragma unroll
                    for (int mf = 0; mf < 2; mf++) {
                        mma16816(c[mf][nf2 * 2 + 0], ah[mf], bb[nf2][0], bb[nf2][2]);
                        mma16816(c[mf][nf2 * 2 + 1], ah[mf], bb[nf2][1], bb[nf2][3]);
                        mma16816(c[mf][nf2 * 2 + 0], al[mf], bb[nf2][0], bb[nf2][2]);
                        mma16816(c[mf][nf2 * 2 + 1], al[mf], bb[nf2][1], bb[nf2][3]);
                    }
#pragma unroll
                for (int nf2 = 0; nf2 < 2; nf2++) {
                    uint32_t off = swz(warp_n + nf2 * 16 + lm, ch);
                    ldmx4(Bl + off, bb[nf2]);
                }
#pragma unroll
                for (int nf2 = 0; nf2 < 2; nf2++)
#pragma unroll
                    for (int mf = 0; mf < 2; mf++) {
                        mma16816(c[mf][nf2 * 2 + 0], ah[mf], bb[nf2][0], bb[nf2][2]);
                        mma16816(c[mf][nf2 * 2 + 1], ah[mf], bb[nf2][1], bb[nf2][3]);
                    }
            }
        }
        __syncthreads();
    }

#pragma unroll
    for (int mf = 0; mf < 2; mf++)
#pragma unroll
        for (int nf = 0; nf < 4; nf++) {
            int col = n0 + warp_n + nf * 8 + (lane & 3) * 2;
            int r0 = warp_m + mf * 16 + (lane >> 2);
            if (ATOMIC) {
                atomicAdd(&C[(long)r0 * ldc + col],           c[mf][nf][0]);
                atomicAdd(&C[(long)r0 * ldc + col + 1],       c[mf][nf][1]);
                atomicAdd(&C[(long)(r0 + 8) * ldc + col],     c[mf][nf][2]);
                atomicAdd(&C[(long)(r0 + 8) * ldc + col + 1], c[mf][nf][3]);
            } else {
                float b0 = 0.f, b1 = 0.f;
                if (bias1) { b0 = bias1[col]; b1 = bias1[col + 1]; }
                float2 o0 = {c[mf][nf][0] + b0, c[mf][nf][1] + b1};
                float2 o1 = {c[mf][nf][2] + b0, c[mf][nf][3] + b1};
                *reinterpret_cast<float2*>(C + (long)r0 * ldc + col) = o0;
                *reinterpret_cast<float2*>(C + (long)(r0 + 8) * ldc + col) = o1;
            }
        }
}

// ===================== energy kernel: gathered M=128 tiles ===================
// grid (8 n-blocks, B_*2 m-tiles). Tile = 128 gathered s-rows x 128 h-cols.
// warp tile 32x64 (c[2][8][4]).
#define EN_A_TILE 16384
#define EN_B_TILE 16384
#define EN_STAGE  (2 * EN_A_TILE + 2 * EN_B_TILE)   // 64KB
#define EN_SMEM_BYTES (2048 + 2 * EN_STAGE)

__global__ __launch_bounds__(256, 1)
void energy128_mma_kernel(const __nv_bfloat16* __restrict__ eh,
                          const __nv_bfloat16* __restrict__ el,
                          const __nv_bfloat16* __restrict__ wh,
                          const __nv_bfloat16* __restrict__ wl,
                          const float* __restrict__ vvec,
                          const float* __restrict__ query,
                          float* __restrict__ energy) {
    const int b  = blockIdx.y >> 1;
    const int mt = (blockIdx.y & 1) * 128;
    const int cnt = g_scnt[b];
    if (mt >= cnt) return;

    extern __shared__ char smem[];
    uint32_t sb = smem_to_u32(smem);
    uint32_t tiles = (sb + 2048 + 1023) & ~1023u;

    const int tid = threadIdx.x;
    const int wid = tid >> 5, lane = tid & 31;
    const int warp_m = (wid & 3) * 32;
    const int warp_n = (wid >> 2) * 64;
    const int n0 = blockIdx.x * 128;

    float* vs = (float*)smem;               // 128 floats
    float* qs = vs + 128;                   // 128 floats
    int*   sid = (int*)(qs + 128);          // 128 ints
    if (tid < 128) {
        vs[tid]  = vvec[n0 + tid];
        qs[tid]  = query[b * H_ + n0 + tid];
        sid[tid] = g_sidx[b * S_ + mt + tid];
    }
    __syncthreads();

    float c[2][8][4];
#pragma unroll
    for (int i = 0; i < 2; i++)
#pragma unroll
        for (int j = 0; j < 8; j++)
#pragma unroll
            for (int k = 0; k < 4; k++) c[i][j][k] = 0.f;

    auto load_stage = [&](int c0, uint32_t stg) {
#pragma unroll
        for (int i = 0; i < 4; i++) {
            int idx = tid + i * 256;
            int r = idx >> 3, cc = idx & 7;
            uint32_t off = swz(r, cc);
            long ga = (long)b * S_ + sid[r];
            long asrc = ga * ENC_ + c0 + cc * 8;
            CP16(stg + off, eh + asrc);
            CP16(stg + EN_A_TILE + off, el + asrc);
            long bsrc = (long)(n0 + r) * ENC_ + c0 + cc * 8;
            CP16(stg + 2 * EN_A_TILE + off, wh + bsrc);
            CP16(stg + 3 * EN_A_TILE + off, wl + bsrc);
        }
    };

    load_stage(0, tiles);
    CP_COMMIT();

    const int KT = ENC_ / 64;   // 16
    for (int kt = 0; kt < KT; kt++) {
        uint32_t stg = tiles + (kt & 1) * EN_STAGE;
        if (kt + 1 < KT) {
            load_stage((kt + 1) * 64, tiles + ((kt + 1) & 1) * EN_STAGE);
            CP_COMMIT();
            cp_wait<1>();
        } else {
            cp_wait<0>();
        }
        __syncthreads();
        {
            const uint32_t Ah = stg, Al = stg + EN_A_TILE;
            const uint32_t Bh = stg + 2 * EN_A_TILE, Bl = stg + 3 * EN_A_TILE;
            const int lm = lane & 15, lh = lane >> 4;
#pragma unroll
            for (int ks = 0; ks < 4; ks++) {
                const int ch = ks * 2 + lh;
                uint32_t ah[2][4], al[2][4];
#pragma unroll
                for (int mf = 0; mf < 2; mf++) {
                    uint32_t off = swz(warp_m + mf * 16 + lm, ch);
                    ldmx4(Ah + off, ah[mf]);
                    ldmx4(Al + off, al[mf]);
                }
                uint32_t bb[4][4];
#pragma unroll
                for (int nf2 = 0; nf2 < 4; nf2++) {
                    uint32_t off = swz(warp_n + nf2 * 16 + lm, ch);
                    ldmx4(Bh + off, bb[nf2]);
                }
#pragma unroll
                for (int nf2 = 0; nf2 < 4; nf2++)
#pragma unroll
                    for (int mf = 0; mf < 2; mf++) {
                        mma16816(c[mf][nf2 * 2 + 0], ah[mf], bb[nf2][0], bb[nf2][2]);
                        mma16816(c[mf][nf2 * 2 + 1], ah[mf], bb[nf2][1], bb[nf2][3]);
                        mma16816(c[mf][nf2 * 2 + 0], al[mf], bb[nf2][0], bb[nf2][2]);
                        mma16816(c[mf][nf2 * 2 + 1], al[mf], bb[nf2][1], bb[nf2][3]);
                    }
#pragma unroll
                for (int nf2 = 0; nf2 < 4; nf2++) {
                    uint32_t off = swz(warp_n + nf2 * 16 + lm, ch);
                    ldmx4(Bl + off, bb[nf2]);
                }
#pragma unroll
                for (int nf2 = 0; nf2 < 4; nf2++)
#pragma unroll
                    for (int mf = 0; mf < 2; mf++) {
                        mma16816(c[mf][nf2 * 2 + 0], ah[mf], bb[nf2][0], bb[nf2][2]);
                        mma16816(c[mf][nf2 * 2 + 1], ah[mf], bb[nf2][1], bb[nf2][3]);
                    }
            }
        }
        __syncthreads();
    }

    // epilogue: v*tanh(q + C), reduce over h, scatter-add via sid
#pragma unroll
    for (int mf = 0; mf < 2; mf++) {
        float s_lo = 0.f, s_hi = 0.f;
#pragma unroll
        for (int nf = 0; nf < 8; nf++) {
            int col = warp_n + nf * 8 + (lane & 3) * 2;
            float v0 = vs[col], v1 = vs[col + 1];
            float q0 = qs[col], q1 = qs[col + 1];
            s_lo += v0 * tanhf(q0 + c[mf][nf][0]) + v1 * tanhf(q1 + c[mf][nf][1]);
            s_hi += v0 * tanhf(q0 + c[mf][nf][2]) + v1 * tanhf(q1 + c[mf][nf][3]);
        }
        s_lo += __shfl_xor_sync(0xffffffff, s_lo, 1);
        s_lo += __shfl_xor_sync(0xffffffff, s_lo, 2);
        s_hi += __shfl_xor_sync(0xffffffff, s_hi, 1);
        s_hi += __shfl_xor_sync(0xffffffff, s_hi, 2);
        if ((lane & 3) == 0) {
            int r0 = warp_m + mf * 16 + (lane >> 2);
            if (mt + r0 < cnt)
                atomicAdd(&energy[b * S_ + sid[r0]], s_lo);
            if (mt + r0 + 8 < cnt)
                atomicAdd(&energy[b * S_ + sid[r0 + 8]], s_hi);
        }
    }
}

// ===================== fused softmax + compacted context =====================
// grid (B_, 4): each block redundantly computes softmax, handles 256 enc cols.
__global__ void softmax_context_kernel(const float* __restrict__ energy,
                                       const float* __restrict__ enc,
                                       float* __restrict__ out_attn) {
    __shared__ float red[256];
    __shared__ float w[256];
    __shared__ int sid[256];
    __shared__ int cnts;
    const int b = blockIdx.x;
    const int tid = threadIdx.x;

    float val = energy[b * S_ + tid];
    red[tid] = val;
    sid[tid] = g_sidx[b * S_ + tid];
    if (tid == 0) cnts = g_scnt[b];
    __syncthreads();
#pragma unroll
    for (int off = 128; off > 0; off >>= 1) {
        if (tid < off) red[tid] = fmaxf(red[tid], red[tid + off]);
        __syncthreads();
    }
    float mx = red[0];
    __syncthreads();
    float ex = expf(val - mx);
    red[tid] = ex;
    __syncthreads();
#pragma unroll
    for (int off = 128; off > 0; off >>= 1) {
        if (tid < off) red[tid] += red[tid + off];
        __syncthreads();
    }
    float aw = ex / red[0];
    if (blockIdx.y == 0) out_attn[b * S_ + tid] = aw;
    w[tid] = aw;
    __syncthreads();

    const int cnt = cnts;
    const int col = blockIdx.y * 256 + tid;
    const float* eb = enc + (long)b * S_ * ENC_;
    float acc = 0.f;
    for (int j = 0; j < cnt; j++) {
        int s = sid[j];
        acc = fmaf(w[s], eb[(long)s * ENC_ + col], acc);
    }
    __nv_bfloat16 hi, lo;
    split1(acc, hi, lo);
    g_a0_hi[b * KCAT0 + E_ + col] = hi;
    g_a0_lo[b * KCAT0 + E_ + col] = lo;
    g_feat_hi[b * FDIM_ + H_ + col] = hi;
    g_feat_lo[b * FDIM_ + H_ + col] = lo;
}

// ===================== LSTM pointwise ========================================
__global__ void lstm_kernel(const float* __restrict__ gates,
                            const float* __restrict__ c_prev,
                            float* __restrict__ c_out,
                            float* __restrict__ h_out_f32,
                            __nv_bfloat16* __restrict__ hb_hi,
                            __nv_bfloat16* __restrict__ hb_lo,
                            int sb) {
    const int b = blockIdx.x;
    const int idx = blockIdx.y * 256 + threadIdx.x;
    float gi = gates[b * G4H_ + idx];
    float gf = gates[b * G4H_ + H_ + idx];
    float gg = gates[b * G4H_ + 2 * H_ + idx];
    float go = gates[b * G4H_ + 3 * H_ + idx];
    float c  = c_prev[b * H_ + idx];
    float si = 1.f / (1.f + expf(-gi));
    float sf = 1.f / (1.f + expf(-gf));
    float so = 1.f / (1.f + expf(-go));
    float cn = sf * c + si * tanhf(gg);
    float hn = so * tanhf(cn);
    c_out[b * H_ + idx]     = cn;
    h_out_f32[b * H_ + idx] = hn;
    __nv_bfloat16 hi, lo;
    split1(hn, hi, lo);
    hb_hi[b * sb + idx] = hi;
    hb_lo[b * sb + idx] = lo;
}

// ===================== launch ================================================
extern "C" void kernel_launch(void* const* d_in, const int* in_sizes, int n_in,
                              void* d_out, int out_size) {
    const int*   tok    = (const int*)  d_in[0];
    const float* hidden = (const float*)d_in[1];
    const float* cell   = (const float*)d_in[2];
    const float* enc    = (const float*)d_in[3];
    const int*   mask   = (const int*)  d_in[4];
    const float* emb    = (const float*)d_in[5];
    const float* Wq     = (const float*)d_in[6];
    const float* Wk     = (const float*)d_in[7];
    const float* v      = (const float*)d_in[8];
    const float* Wih0   = (const float*)d_in[9];
    const float* Whh0   = (const float*)d_in[10];
    const float* bih0   = (const float*)d_in[11];
    const float* bhh0   = (const float*)d_in[12];
    const float* Wih1   = (const float*)d_in[13];
    const float* Whh1   = (const float*)d_in[14];
    const float* bih1   = (const float*)d_in[15];
    const float* bhh1   = (const float*)d_in[16];
    const float* Wout   = (const float*)d_in[17];
    const float* bout   = (const float*)d_in[18];

    float* out      = (float*)d_out;
    float* out_pred = out;
    float* out_hid  = out + (long)B_ * V_;
    float* out_cell = out_hid + 2 * B_ * H_;
    float* out_attn = out_cell + 2 * B_ * H_;

    void* sp = nullptr;
    cudaGetSymbolAddress(&sp, g_scratch);
    float* scratch = (float*)sp;
    float* query  = scratch + OFF_QUERY;
    float* gates0 = scratch + OFF_GATES0;
    float* gates1 = scratch + OFF_GATES1;
    float* energy = scratch + OFF_ENERGY;

    void *p_eh, *p_el, *p_wh, *p_wl, *p_h1h, *p_h1l,
         *p_a0h, *p_a0l, *p_a1h, *p_a1l, *p_fh, *p_fl;
    cudaGetSymbolAddress(&p_eh,  g_enc_hi);
    cudaGetSymbolAddress(&p_el,  g_enc_lo);
    cudaGetSymbolAddress(&p_wh,  g_wk_hi);
    cudaGetSymbolAddress(&p_wl,  g_wk_lo);
    cudaGetSymbolAddress(&p_h1h, g_h1_hi);
    cudaGetSymbolAddress(&p_h1l, g_h1_lo);
    cudaGetSymbolAddress(&p_a0h, g_a0_hi);
    cudaGetSymbolAddress(&p_a0l, g_a0_lo);
    cudaGetSymbolAddress(&p_a1h, g_a1_hi);
    cudaGetSymbolAddress(&p_a1l, g_a1_lo);
    cudaGetSymbolAddress(&p_fh,  g_feat_hi);
    cudaGetSymbolAddress(&p_fl,  g_feat_lo);

    cudaFuncSetAttribute(hmma_m64_kernel<false>,  cudaFuncAttributeMaxDynamicSharedMemorySize, WO_SMEM_BYTES);
    cudaFuncSetAttribute(hmma_m64_kernel<true>,   cudaFuncAttributeMaxDynamicSharedMemorySize, WO_SMEM_BYTES);
    cudaFuncSetAttribute(energy128_mma_kernel,    cudaFuncAttributeMaxDynamicSharedMemorySize, EN_SMEM_BYTES);

    // 1. combined enc + Wk bf16 split
    split2src_kernel<<<ENC_BLKS + WK_BLKS, 256>>>(
        enc, (__nv_bfloat16*)p_eh, (__nv_bfloat16*)p_el,
        Wk,  (__nv_bfloat16*)p_wh, (__nv_bfloat16*)p_wl);

    // 2. mega-prep
    prep_kernel<<<PREP_BLKS, 256>>>(mask, hidden, tok, emb,
                                    bih0, bhh0, bih1, bhh1,
                                    energy, query, gates0, gates1,
                                    (__nv_bfloat16*)p_h1h, (__nv_bfloat16*)p_h1l);

    // 3. query = hidden[1] @ Wq^T (K-split 4, atomic)
    hmma_m64_kernel<true><<<dim3(H_ / 128, 4), 256, WO_SMEM_BYTES>>>(
        (const __nv_bfloat16*)p_h1h, (const __nv_bfloat16*)p_h1l, H_,
        Wq, H_, Wq, nullptr, query, H_, 4);

    // 4. energy: gathered unmasked rows, 128-row tiles
    energy128_mma_kernel<<<dim3(H_ / 128, B_ * 2), 256, EN_SMEM_BYTES>>>(
        (const __nv_bfloat16*)p_eh, (const __nv_bfloat16*)p_el,
        (const __nv_bfloat16*)p_wh, (const __nv_bfloat16*)p_wl, v, query, energy);

    // 5. fused masked softmax + compacted context
    softmax_context_kernel<<<dim3(B_, 4), 256>>>(energy, enc, out_attn);

    // 6. layer-0 gates (K-split 4, atomic; bias pre-initialized) + LSTM
    hmma_m64_kernel<true><<<dim3(G4H_ / 128, 4), 256, WO_SMEM_BYTES>>>(
        (const __nv_bfloat16*)p_a0h, (const __nv_bfloat16*)p_a0l, KCAT0,
        Wih0, E_ + ENC_, Whh0, nullptr, gates0, G4H_, 4);
    lstm_kernel<<<dim3(B_, H_ / 256), 256>>>(gates0, cell, out_cell, out_hid,
                                             (__nv_bfloat16*)p_a1h, (__nv_bfloat16*)p_a1l, KCAT1);

    // 7. layer-1 gates (K-split 4, atomic) + LSTM
    hmma_m64_kernel<true><<<dim3(G4H_ / 128, 4), 256, WO_SMEM_BYTES>>>(
        (const __nv_bfloat16*)p_a1h, (const __nv_bfloat16*)p_a1l, KCAT1,
        Wih1, H_, Whh1, nullptr, gates1, G4H_, 4);
    lstm_kernel<<<dim3(B_, H_ / 256), 256>>>(gates1, cell + B_ * H_, out_cell + B_ * H_,
                                             out_hid + B_ * H_,
                                             (__nv_bfloat16*)p_fh, (__nv_bfloat16*)p_fl, FDIM_);

    // 8. prediction = feat @ Wout^T + bout
    hmma_m64_kernel<false><<<dim3(V_ / 128, 1), 256, WO_SMEM_BYTES>>>(
        (const __nv_bfloat16*)p_fh, (const __nv_bfloat16*)p_fl, FDIM_,
        Wout, FDIM_, Wout, bout, out_pred, V_, 1);
}

// round 7
// speedup vs baseline: 4.9950x; 1.0723x over previous
#include <cuda_runtime.h>
#include <cuda_bf16.h>
#include <math.h>
#include <stdint.h>

#define B_   64
#define S_   256
#define H_   1024
#define ENC_ 1024
#define E_   512
#define V_   32000
#define FDIM_ (H_ + ENC_ + E_)   // 2560
#define G4H_  (4 * H_)           // 4096
#define KCAT0 2560
#define KCAT1 2048

// ---------------- scratch ----------------------------------------------------
#define OFF_QUERY   0
#define OFF_GATES0  (OFF_QUERY + B_ * H_)
#define OFF_GATES1  (OFF_GATES0 + B_ * G4H_)
#define OFF_ENERGY  (OFF_GATES1 + B_ * G4H_)
#define SCRATCH_TOTAL (OFF_ENERGY + B_ * S_)

__device__ __align__(16) float g_scratch[SCRATCH_TOTAL];
__device__ int g_sidx[B_ * S_];
__device__ int g_scnt[B_];
__device__ int g_gidx[B_ * S_];
__device__ int g_total;

__device__ __align__(16) __nv_bfloat16 g_enc_hi[(long)B_ * S_ * ENC_];
__device__ __align__(16) __nv_bfloat16 g_enc_lo[(long)B_ * S_ * ENC_];
__device__ __align__(16) __nv_bfloat16 g_wk_hi[H_ * ENC_];
__device__ __align__(16) __nv_bfloat16 g_wk_lo[H_ * ENC_];
__device__ __align__(16) __nv_bfloat16 g_h1_hi[B_ * H_];
__device__ __align__(16) __nv_bfloat16 g_h1_lo[B_ * H_];
__device__ __align__(16) __nv_bfloat16 g_a0_hi[B_ * KCAT0];
__device__ __align__(16) __nv_bfloat16 g_a0_lo[B_ * KCAT0];
__device__ __align__(16) __nv_bfloat16 g_a1_hi[B_ * KCAT1];
__device__ __align__(16) __nv_bfloat16 g_a1_lo[B_ * KCAT1];
__device__ __align__(16) __nv_bfloat16 g_feat_hi[B_ * FDIM_];
__device__ __align__(16) __nv_bfloat16 g_feat_lo[B_ * FDIM_];

// ===================== low-level helpers =====================================
__device__ __forceinline__ uint32_t smem_to_u32(const void* p) {
    uint32_t a;
    asm("{ .reg .u64 t; cvta.to.shared.u64 t, %1; cvt.u32.u64 %0, t; }" : "=r"(a) : "l"(p));
    return a;
}

#define CP16(dst_u32, src_ptr) \
    asm volatile("cp.async.cg.shared.global [%0], [%1], 16;" :: "r"(dst_u32), "l"(src_ptr))
#define CP_COMMIT() asm volatile("cp.async.commit_group;" ::: "memory")
template<int N> __device__ __forceinline__ void cp_wait() {
    asm volatile("cp.async.wait_group %0;" :: "n"(N) : "memory");
}

__device__ __forceinline__ void ldmx4(uint32_t addr, uint32_t r[4]) {
    asm volatile("ldmatrix.sync.aligned.m8n8.x4.shared.b16 {%0,%1,%2,%3}, [%4];"
        : "=r"(r[0]), "=r"(r[1]), "=r"(r[2]), "=r"(r[3]) : "r"(addr));
}

__device__ __forceinline__ void mma16816(float* c, const uint32_t a[4],
                                         uint32_t b0, uint32_t b1) {
    asm volatile("mma.sync.aligned.m16n8k16.row.col.f32.bf16.bf16.f32 "
        "{%0,%1,%2,%3}, {%4,%5,%6,%7}, {%8,%9}, {%0,%1,%2,%3};"
        : "+f"(c[0]), "+f"(c[1]), "+f"(c[2]), "+f"(c[3])
        : "r"(a[0]), "r"(a[1]), "r"(a[2]), "r"(a[3]), "r"(b0), "r"(b1));
}

#define STS128(addr, a, b, c, d) \
    asm volatile("st.shared.v4.b32 [%0], {%1,%2,%3,%4};" \
        :: "r"(addr), "r"(a), "r"(b), "r"(c), "r"(d) : "memory")

__device__ __forceinline__ uint32_t swz(int row, int chunk16) {
    return (uint32_t)(row * 128 + ((chunk16 ^ (row & 7)) * 16));
}

__device__ __forceinline__ void split2(float a, float b, uint32_t& hi, uint32_t& lo) {
    __nv_bfloat162 h2 = __floats2bfloat162_rn(a, b);
    float ra = a - __bfloat162float(__low2bfloat16(h2));
    float rb = b - __bfloat162float(__high2bfloat16(h2));
    __nv_bfloat162 l2 = __floats2bfloat162_rn(ra, rb);
    hi = *reinterpret_cast<uint32_t*>(&h2);
    lo = *reinterpret_cast<uint32_t*>(&l2);
}

__device__ __forceinline__ void split1(float a, __nv_bfloat16& hi, __nv_bfloat16& lo) {
    hi = __float2bfloat16_rn(a);
    lo = __float2bfloat16_rn(a - __bfloat162float(hi));
}

// ===================== combined enc+wk split ================================
#define ENC_BLKS ((B_ * S_ * ENC_) / 1024)   // 16384
#define WK_BLKS  ((H_ * ENC_) / 1024)        // 1024

__global__ void split2src_kernel(const float* __restrict__ enc,
                                 __nv_bfloat16* __restrict__ eh,
                                 __nv_bfloat16* __restrict__ el,
                                 const float* __restrict__ wk,
                                 __nv_bfloat16* __restrict__ wh,
                                 __nv_bfloat16* __restrict__ wl) {
    const float* src;
    __nv_bfloat16 *hi, *lo;
    long i;
    if (blockIdx.x < ENC_BLKS) {
        i = ((long)blockIdx.x * 256 + threadIdx.x) * 4;
        src = enc; hi = eh; lo = el;
    } else {
        i = ((long)(blockIdx.x - ENC_BLKS) * 256 + threadIdx.x) * 4;
        src = wk; hi = wh; lo = wl;
    }
    float4 v = *reinterpret_cast<const float4*>(src + i);
    uint2 H, L;
    split2(v.x, v.y, H.x, L.x);
    split2(v.z, v.w, H.y, L.y);
    *reinterpret_cast<uint2*>(hi + i) = H;
    *reinterpret_cast<uint2*>(hi + i) = H;
    *reinterpret_cast<uint2*>(lo + i) = L;
}

// ===================== mega-prep kernel ======================================
// [0,64): mask compact + energy init + embed + hidden scatter
// [64,128): h1 split   [128,192): query zero   [192,448): gates0   [448,704): gates1
// [704,2704): out_pred init = bout
#define PREP_BLKS 2704

__global__ void prep_kernel(const int* __restrict__ mask,
                            const float* __restrict__ hidden,
                            const int* __restrict__ tok,
                            const float* __restrict__ emb,
                            const float* __restrict__ bih0,
                            const float* __restrict__ bhh0,
                            const float* __restrict__ bih1,
                            const float* __restrict__ bhh1,
                            const float* __restrict__ bout,
                            float* __restrict__ energy,
                            float* __restrict__ query,
                            float* __restrict__ gates0,
                            float* __restrict__ gates1,
                            float* __restrict__ out_pred,
                            __nv_bfloat16* __restrict__ h1h,
                            __nv_bfloat16* __restrict__ h1l) {
    const int tid = threadIdx.x;
    const int blk = blockIdx.x;
    if (blk < B_) {
        const int b = blk;
        __shared__ int sc[256];
        int m = (mask[b * S_ + tid] != 0) ? 1 : 0;
        sc[tid] = m;
        __syncthreads();
#pragma unroll
        for (int off = 1; off < 256; off <<= 1) {
            int t = (tid >= off) ? sc[tid - off] : 0;
            __syncthreads();
            sc[tid] += t;
            __syncthreads();
        }
        int total = sc[255];
        int my = sc[tid] - m;
        if (m) g_sidx[b * S_ + my] = tid;
        if (tid >= total) g_sidx[b * S_ + tid] = 0;
        energy[b * S_ + tid] = m ? 0.f : -1e10f;
        if (tid == 0) g_scnt[b] = total;
        const int t = tok[b];
        for (int j = tid; j < E_; j += 256) {
            __nv_bfloat16 hi, lo;
            split1(emb[(long)t * E_ + j], hi, lo);
            g_a0_hi[b * KCAT0 + j] = hi;
            g_a0_lo[b * KCAT0 + j] = lo;
            g_feat_hi[b * FDIM_ + (H_ + ENC_) + j] = hi;
            g_feat_lo[b * FDIM_ + (H_ + ENC_) + j] = lo;
        }
        for (int j = tid; j < H_; j += 256) {
            __nv_bfloat16 hi, lo;
            split1(hidden[b * H_ + j], hi, lo);
            g_a0_hi[b * KCAT0 + (E_ + ENC_) + j] = hi;
            g_a0_lo[b * KCAT0 + (E_ + ENC_) + j] = lo;
            split1(hidden[B_ * H_ + b * H_ + j], hi, lo);
            g_a1_hi[b * KCAT1 + H_ + j] = hi;
            g_a1_lo[b * KCAT1 + H_ + j] = lo;
        }
    } else if (blk < 128) {
        long i = ((long)(blk - 64) * 256 + tid) * 4;
        float4 v = *reinterpret_cast<const float4*>(hidden + (long)B_ * H_ + i);
        uint2 H, L;
        split2(v.x, v.y, H.x, L.x);
        split2(v.z, v.w, H.y, L.y);
        *reinterpret_cast<uint2*>(h1h + i) = H;
        *reinterpret_cast<uint2*>(h1l + i) = L;
    } else if (blk < 192) {
        long i = ((long)(blk - 128) * 256 + tid) * 4;
        float4 z = {0.f, 0.f, 0.f, 0.f};
        *reinterpret_cast<float4*>(query + i) = z;
    } else if (blk < 448) {
        long i = ((long)(blk - 192) * 256 + tid) * 4;
        int n = (int)(i & (G4H_ - 1));
        float4 o = {bih0[n] + bhh0[n], bih0[n + 1] + bhh0[n + 1],
                    bih0[n + 2] + bhh0[n + 2], bih0[n + 3] + bhh0[n + 3]};
        *reinterpret_cast<float4*>(gates0 + i) = o;
    } else if (blk < 704) {
        long i = ((long)(blk - 448) * 256 + tid) * 4;
        int n = (int)(i & (G4H_ - 1));
        float4 o = {bih1[n] + bhh1[n], bih1[n + 1] + bhh1[n + 1],
                    bih1[n + 2] + bhh1[n + 2], bih1[n + 3] + bhh1[n + 3]};
        *reinterpret_cast<float4*>(gates1 + i) = o;
    } else {
        long i = ((long)(blk - 704) * 1024 + tid * 4);
        int col = (int)(i % V_);
        float4 o = {bout[col], bout[col + 1], bout[col + 2], bout[col + 3]};
        *reinterpret_cast<float4*>(out_pred + i) = o;
    }
}

// ===================== global gather (cross-b compaction) ====================
__global__ void gather_kernel() {
    __shared__ int offs[B_ + 1];
    const int tid = threadIdx.x;
    if (tid == 0) {
        int acc = 0;
        for (int b = 0; b < B_; b++) { offs[b] = acc; acc += g_scnt[b]; }
        offs[B_] = acc;
        g_total = acc;
    }
    __syncthreads();
    for (int b = 0; b < B_; b++) {
        int o = offs[b], cnt = offs[b + 1] - o;
        for (int j = tid; j < cnt; j += 256)
            g_gidx[o + j] = b * S_ + g_sidx[b * S_ + j];
    }
    int total = offs[B_];
    for (int j = total + tid; j < B_ * S_; j += 256) g_gidx[j] = 0;
}

// ===================== fat-B HMMA kernel (query/gates/wout) ==================
#define WO_A_TILE 8192
#define WO_B_TILE 16384
#define WO_STAGE  (2 * WO_A_TILE + 2 * WO_B_TILE)   // 48KB
#define WO_SMEM_BYTES (1024 + 2 * WO_STAGE)

__device__ __forceinline__ void wo_load_A(const __nv_bfloat16* fh, const __nv_bfloat16* fl,
                                          int lda, int c0, uint32_t stg) {
    const int tid = threadIdx.x;
#pragma unroll
    for (int i = 0; i < 2; i++) {
        int idx = tid + i * 256;
        int r = idx >> 3, cc = idx & 7;
        uint32_t off = swz(r, cc);
        long src = (long)r * lda + c0 + cc * 8;
        CP16(stg + off, fh + src);
        CP16(stg + WO_A_TILE + off, fl + src);
    }
}

template<bool ATOMIC>
__global__ __launch_bounds__(256, 2)
void hmma_m64_kernel(const __nv_bfloat16* __restrict__ ah_g,
                     const __nv_bfloat16* __restrict__ al_g,
                     int Ktot,
                     const float* __restrict__ B1, int k1,
                     const float* __restrict__ B2,
                     const float* __restrict__ bias1,
                     float* __restrict__ C, int ldc, int nks) {
    extern __shared__ char smem[];
    uint32_t sb = smem_to_u32(smem);
    uint32_t tiles = (sb + 1023) & ~1023u;

    const int tid = threadIdx.x;
    const int wid = tid >> 5, lane = tid & 31;
    const int warp_m = (wid & 1) * 32;
    const int warp_n = (wid >> 1) * 32;
    const int n0 = blockIdx.x * 128;

    const int br = tid >> 1;
    const int bhalf = tid & 1;
    const int k2 = Ktot - k1;

    const int KT = Ktot / 64;
    const int kt0 = (int)blockIdx.y * (KT / nks);
    const int kt1 = kt0 + KT / nks;

    auto bptr = [&](int c0) -> const float* {
        return (c0 < k1) ? B1 + (long)(n0 + br) * k1 + c0 + bhalf * 32
                         : B2 + (long)(n0 + br) * k2 + (c0 - k1) + bhalf * 32;
    };

    float c[2][4][4];
#pragma unroll
    for (int i = 0; i < 2; i++)
#pragma unroll
        for (int j = 0; j < 4; j++)
#pragma unroll
            for (int k = 0; k < 4; k++) c[i][j][k] = 0.f;

    wo_load_A(ah_g, al_g, Ktot, kt0 * 64, tiles + (kt0 & 1) * WO_STAGE);
    CP_COMMIT();

    for (int kt = kt0; kt < kt1; kt++) {
        uint32_t stg = tiles + (kt & 1) * WO_STAGE;
        if (kt + 1 < kt1) {
            wo_load_A(ah_g, al_g, Ktot, (kt + 1) * 64, tiles + ((kt + 1) & 1) * WO_STAGE);
            CP_COMMIT();
        }
        // load + split B fp32 for this stage (latency hidden by 2nd CTA)
        uint32_t Bh = stg + 2 * WO_A_TILE, Bl = Bh + WO_B_TILE;
        const float* w = bptr(kt * 64);
#pragma unroll
        for (int j = 0; j < 4; j++) {
            float4 v0 = *reinterpret_cast<const float4*>(w + j * 8);
            float4 v1 = *reinterpret_cast<const float4*>(w + j * 8 + 4);
            uint4 Hq, Lq;
            split2(v0.x, v0.y, Hq.x, Lq.x);
            split2(v0.z, v0.w, Hq.y, Lq.y);
            split2(v1.x, v1.y, Hq.z, Lq.z);
            split2(v1.z, v1.w, Hq.w, Lq.w);
            uint32_t off = swz(br, bhalf * 4 + j);
            STS128(Bh + off, Hq.x, Hq.y, Hq.z, Hq.w);
            STS128(Bl + off, Lq.x, Lq.y, Lq.z, Lq.w);
        }
        if (kt + 1 < kt1) cp_wait<1>(); else cp_wait<0>();
        __syncthreads();
        {
            const uint32_t Ah = stg, Al = stg + WO_A_TILE;
            const int lm = lane & 15, lh = lane >> 4;
#pragma unroll
            for (int ks = 0; ks < 4; ks++) {
                const int ch = ks * 2 + lh;
                uint32_t ah[2][4], al[2][4];
#pragma unroll
                for (int mf = 0; mf < 2; mf++) {
                    uint32_t off = swz(warp_m + mf * 16 + lm, ch);
                    ldmx4(Ah + off, ah[mf]);
                    ldmx4(Al + off, al[mf]);
                }
                uint32_t bb[2][4];
#pragma unroll
                for (int nf2 = 0; nf2 < 2; nf2++) {
                    uint32_t off = swz(warp_n + nf2 * 16 + lm, ch);
                    ldmx4(Bh + off, bb[nf2]);
                }
#pragma unroll
                for (int nf2 = 0; nf2 < 2; nf2++)
#pragma unroll
                    for (int mf = 0; mf < 2; mf++) {
                        mma16816(c[mf][nf2 * 2 + 0], ah[mf], bb[nf2][0], bb[nf2][2]);
                        mma16816(c[mf][nf2 * 2 + 1], ah[mf], bb[nf2][1], bb[nf2][3]);
                        mma16816(c[mf][nf2 * 2 + 0], al[mf], bb[nf2][0], bb[nf2][2]);
                        mma16816(c[mf][nf2 * 2 + 1], al[mf], bb[nf2][1], bb[nf2][3]);
                    }
#pragma unroll
                for (int nf2 = 0; nf2 < 2; nf2++) {
                    uint32_t off = swz(warp_n + nf2 * 16 + lm, ch);
                    ldmx4(Bl + off, bb[nf2]);
                }
#pragma unroll
                for (int nf2 = 0; nf2 < 2; nf2++)
#pragma unroll
                    for (int mf = 0; mf < 2; mf++) {
                        mma16816(c[mf][nf2 * 2 + 0], ah[mf], bb[nf2][0], bb[nf2][2]);
                        mma16816(c[mf][nf2 * 2 + 1], ah[mf], bb[nf2][1], bb[nf2][3]);
                    }
            }
        }
        __syncthreads();
    }

#pragma unroll
    for (int mf = 0; mf < 2; mf++)
#pragma unroll
        for (int nf = 0; nf < 4; nf++) {
            int col = n0 + warp_n + nf * 8 + (lane & 3) * 2;
            int r0 = warp_m + mf * 16 + (lane >> 2);
            if (ATOMIC) {
                atomicAdd(&C[(long)r0 * ldc + col],           c[mf][nf][0]);
                atomicAdd(&C[(long)r0 * ldc + col + 1],       c[mf][nf][1]);
                atomicAdd(&C[(long)(r0 + 8) * ldc + col],     c[mf][nf][2]);
                atomicAdd(&C[(long)(r0 + 8) * ldc + col + 1], c[mf][nf][3]);
            } else {
                float b0 = 0.f, b1 = 0.f;
                if (bias1) { b0 = bias1[col]; b1 = bias1[col + 1]; }
                float2 o0 = {c[mf][nf][0] + b0, c[mf][nf][1] + b1};
                float2 o1 = {c[mf][nf][2] + b0, c[mf][nf][3] + b1};
                *reinterpret_cast<float2*>(C + (long)r0 * ldc + col) = o0;
                *reinterpret_cast<float2*>(C + (long)(r0 + 8) * ldc + col) = o1;
            }
        }
}

// ===================== energy kernel: globally compacted M tiles =============
#define EN_A_TILE 16384
#define EN_STAGE  (4 * EN_A_TILE)   // 64KB
#define EN_SMEM_BYTES (2048 + 2 * EN_STAGE)

__global__ __launch_bounds__(256, 1)
void energy_gc_kernel(const __nv_bfloat16* __restrict__ eh,
                      const __nv_bfloat16* __restrict__ el,
                      const __nv_bfloat16* __restrict__ wh,
                      const __nv_bfloat16* __restrict__ wl,
                      const float* __restrict__ vvec,
                      const float* __restrict__ query,
                      float* __restrict__ energy) {
    const int total = g_total;
    const int mt = (int)blockIdx.y * 128;
    if (mt >= total) return;

    extern __shared__ char smem[];
    uint32_t sb = smem_to_u32(smem);
    uint32_t tiles = (sb + 2048 + 1023) & ~1023u;

    const int tid = threadIdx.x;
    const int wid = tid >> 5, lane = tid & 31;
    const int warp_m = (wid & 3) * 32;
    const int warp_n = (wid >> 2) * 64;
    const int n0 = blockIdx.x * 128;

    float* vs = (float*)smem;               // 128 floats
    int*   sid = (int*)(vs + 128);          // 128 ints
    if (tid < 128) {
        vs[tid]  = vvec[n0 + tid];
        sid[tid] = g_gidx[mt + tid];
    }
    __syncthreads();

    // hoisted per-thread load bases: idx_i = tid + i*256 -> r = tid>>3 + 32i, cc = tid&7
    const int rb = tid >> 3, cc8 = (tid & 7) * 8;
    long abase[4], bbase[4];
    uint32_t soff[4];
#pragma unroll
    for (int i = 0; i < 4; i++) {
        int r = rb + 32 * i;
        soff[i]  = swz(r, tid & 7);
        abase[i] = (long)sid[r] * ENC_ + cc8;
        bbase[i] = (long)(n0 + r) * ENC_ + cc8;
    }

    float c[2][8][4];
#pragma unroll
    for (int i = 0; i < 2; i++)
#pragma unroll
        for (int j = 0; j < 8; j++)
#pragma unroll
            for (int k = 0; k < 4; k++) c[i][j][k] = 0.f;

    auto load_stage = [&](int c0, uint32_t stg) {
#pragma unroll
        for (int i = 0; i < 4; i++) {
            CP16(stg + soff[i], eh + abase[i] + c0);
            CP16(stg + EN_A_TILE + soff[i], el + abase[i] + c0);
            CP16(stg + 2 * EN_A_TILE + soff[i], wh + bbase[i] + c0);
            CP16(stg + 3 * EN_A_TILE + soff[i], wl + bbase[i] + c0);
        }
    };

    load_stage(0, tiles);
    CP_COMMIT();

    const int KT = ENC_ / 64;   // 16
    for (int kt = 0; kt < KT; kt++) {
        uint32_t stg = tiles + (kt & 1) * EN_STAGE;
        if (kt + 1 < KT) {
            load_stage((kt + 1) * 64, tiles + ((kt + 1) & 1) * EN_STAGE);
            CP_COMMIT();
            cp_wait<1>();
        } else {
            cp_wait<0>();
        }
        __syncthreads();
        {
            const uint32_t Ah = stg, Al = stg + EN_A_TILE;
            const uint32_t Bh = stg + 2 * EN_A_TILE, Bl = stg + 3 * EN_A_TILE;
            const int lm = lane & 15, lh = lane >> 4;
#pragma unroll
            for (int ks = 0; ks < 4; ks++) {
                const int ch = ks * 2 + lh;
                uint32_t ah[2][4], al[2][4];
#pragma unroll
                for (int mf = 0; mf < 2; mf++) {
                    uint32_t off = swz(warp_m + mf * 16 + lm, ch);
                    ldmx4(Ah + off, ah[mf]);
                    ldmx4(Al + off, al[mf]);
                }
                uint32_t bb[4][4];
#pragma unroll
                for (int nf2 = 0; nf2 < 4; nf2++) {
                    uint32_t off = swz(warp_n + nf2 * 16 + lm, ch);
                    ldmx4(Bh + off, bb[nf2]);
                }
#pragma unroll
                for (int nf2 = 0; nf2 < 4; nf2++)
#pragma unroll
                    for (int mf = 0; mf < 2; mf++) {
                        mma16816(c[mf][nf2 * 2 + 0], ah[mf], bb[nf2][0], bb[nf2][2]);
                        mma16816(c[mf][nf2 * 2 + 1], ah[mf], bb[nf2][1], bb[nf2][3]);
                        mma16816(c[mf][nf2 * 2 + 0], al[mf], bb[nf2][0], bb[nf2][2]);
                        mma16816(c[mf][nf2 * 2 + 1], al[mf], bb[nf2][1], bb[nf2][3]);
                    }
#pragma unroll
                for (int nf2 = 0; nf2 < 4; nf2++) {
                    uint32_t off = swz(warp_n + nf2 * 16 + lm, ch);
                    ldmx4(Bl + off, bb[nf2]);
                }
#pragma unroll
                for (int nf2 = 0; nf2 < 4; nf2++)
#pragma unroll
                    for (int mf = 0; mf < 2; mf++) {
                        mma16816(c[mf][nf2 * 2 + 0], ah[mf], bb[nf2][0], bb[nf2][2]);
                        mma16816(c[mf][nf2 * 2 + 1], ah[mf], bb[nf2][1], bb[nf2][3]);
                    }
            }
        }
        __syncthreads();
    }

    // epilogue: per-row b-specific query; reduce over h; scatter-add
#pragma unroll
    for (int mf = 0; mf < 2; mf++) {
        int row_lo = warp_m + mf * 16 + (lane >> 2);
        int row_hi = row_lo + 8;
        int gid_lo = sid[row_lo], gid_hi = sid[row_hi];
        const float* qlo = query + (long)(gid_lo >> 8) * H_ + n0;
        const float* qhi = query + (long)(gid_hi >> 8) * H_ + n0;
        float s_lo = 0.f, s_hi = 0.f;
#pragma unroll
        for (int nf = 0; nf < 8; nf++) {
            int col = warp_n + nf * 8 + (lane & 3) * 2;
            float v0 = vs[col], v1 = vs[col + 1];
            s_lo += v0 * tanhf(qlo[col] + c[mf][nf][0]) + v1 * tanhf(qlo[col + 1] + c[mf][nf][1]);
            s_hi += v0 * tanhf(qhi[col] + c[mf][nf][2]) + v1 * tanhf(qhi[col + 1] + c[mf][nf][3]);
        }
        s_lo += __shfl_xor_sync(0xffffffff, s_lo, 1);
        s_lo += __shfl_xor_sync(0xffffffff, s_lo, 2);
        s_hi += __shfl_xor_sync(0xffffffff, s_hi, 1);
        s_hi += __shfl_xor_sync(0xffffffff, s_hi, 2);
        if ((lane & 3) == 0) {
            if (mt + row_lo < total) atomicAdd(&energy[gid_lo], s_lo);
            if (mt + row_hi < total) atomicAdd(&energy[gid_hi], s_hi);
        }
    }
}

// ===================== fused softmax + compacted context =====================
__global__ void softmax_context_kernel(const float* __restrict__ energy,
                                       const float* __restrict__ enc,
                                       float* __restrict__ out_attn) {
    __shared__ float red[256];
    __shared__ float w[256];
    __shared__ int sid[256];
    __shared__ int cnts;
    const int b = blockIdx.x;
    const int tid = threadIdx.x;

    float val = energy[b * S_ + tid];
    red[tid] = val;
    sid[tid] = g_sidx[b * S_ + tid];
    if (tid == 0) cnts = g_scnt[b];
    __syncthreads();
#pragma unroll
    for (int off = 128; off > 0; off >>= 1) {
        if (tid < off) red[tid] = fmaxf(red[tid], red[tid + off]);
        __syncthreads();
    }
    float mx = red[0];
    __syncthreads();
    float ex = expf(val - mx);
    red[tid] = ex;
    __syncthreads();
#pragma unroll
    for (int off = 128; off > 0; off >>= 1) {
        if (tid < off) red[tid] += red[tid + off];
        __syncthreads();
    }
    float aw = ex / red[0];
    if (blockIdx.y == 0) out_attn[b * S_ + tid] = aw;
    w[tid] = aw;
    __syncthreads();

    const int cnt = cnts;
    const int col = blockIdx.y * 256 + tid;
    const float* eb = enc + (long)b * S_ * ENC_;
    float acc = 0.f;
    for (int j = 0; j < cnt; j++) {
        int s = sid[j];
        acc = fmaf(w[s], eb[(long)s * ENC_ + col], acc);
    }
    __nv_bfloat16 hi, lo;
    split1(acc, hi, lo);
    g_a0_hi[b * KCAT0 + E_ + col] = hi;
    g_a0_lo[b * KCAT0 + E_ + col] = lo;
    g_feat_hi[b * FDIM_ + H_ + col] = hi;
    g_feat_lo[b * FDIM_ + H_ + col] = lo;
}

// ===================== LSTM pointwise ========================================
__global__ void lstm_kernel(const float* __restrict__ gates,
                            const float* __restrict__ c_prev,
                            float* __restrict__ c_out,
                            float* __restrict__ h_out_f32,
                            __nv_bfloat16* __restrict__ hb_hi,
                            __nv_bfloat16* __restrict__ hb_lo,
                            int sb) {
    const int b = blockIdx.x;
    const int idx = blockIdx.y * 256 + threadIdx.x;
    float gi = gates[b * G4H_ + idx];
    float gf = gates[b * G4H_ + H_ + idx];
    float gg = gates[b * G4H_ + 2 * H_ + idx];
    float go = gates[b * G4H_ + 3 * H_ + idx];
    float c  = c_prev[b * H_ + idx];
    float si = 1.f / (1.f + expf(-gi));
    float sf = 1.f / (1.f + expf(-gf));
    float so = 1.f / (1.f + expf(-go));
    float cn = sf * c + si * tanhf(gg);
    float hn = so * tanhf(cn);
    c_out[b * H_ + idx]     = cn;
    h_out_f32[b * H_ + idx] = hn;
    __nv_bfloat16 hi, lo;
    split1(hn, hi, lo);
    hb_hi[b * sb + idx] = hi;
    hb_lo[b * sb + idx] = lo;
}

// ===================== launch ================================================
extern "C" void kernel_launch(void* const* d_in, const int* in_sizes, int n_in,
                              void* d_out, int out_size) {
    const int*   tok    = (const int*)  d_in[0];
    const float* hidden = (const float*)d_in[1];
    const float* cell   = (const float*)d_in[2];
    const float* enc    = (const float*)d_in[3];
    const int*   mask   = (const int*)  d_in[4];
    const float* emb    = (const float*)d_in[5];
    const float* Wq     = (const float*)d_in[6];
    const float* Wk     = (const float*)d_in[7];
    const float* v      = (const float*)d_in[8];
    const float* Wih0   = (const float*)d_in[9];
    const float* Whh0   = (const float*)d_in[10];
    const float* bih0   = (const float*)d_in[11];
    const float* bhh0   = (const float*)d_in[12];
    const float* Wih1   = (const float*)d_in[13];
    const float* Whh1   = (const float*)d_in[14];
    const float* bih1   = (const float*)d_in[15];
    const float* bhh1   = (const float*)d_in[16];
    const float* Wout   = (const float*)d_in[17];
    const float* bout   = (const float*)d_in[18];

    float* out      = (float*)d_out;
    float* out_pred = out;
    float* out_hid  = out + (long)B_ * V_;
    float* out_cell = out_hid + 2 * B_ * H_;
    float* out_attn = out_cell + 2 * B_ * H_;

    void* sp = nullptr;
    cudaGetSymbolAddress(&sp, g_scratch);
    float* scratch = (float*)sp;
    float* query  = scratch + OFF_QUERY;
    float* gates0 = scratch + OFF_GATES0;
    float* gates1 = scratch + OFF_GATES1;
    float* energy = scratch + OFF_ENERGY;

    void *p_eh, *p_el, *p_wh, *p_wl, *p_h1h, *p_h1l,
         *p_a0h, *p_a0l, *p_a1h, *p_a1l, *p_fh, *p_fl;
    cudaGetSymbolAddress(&p_eh,  g_enc_hi);
    cudaGetSymbolAddress(&p_el,  g_enc_lo);
    cudaGetSymbolAddress(&p_wh,  g_wk_hi);
    cudaGetSymbolAddress(&p_wl,  g_wk_lo);
    cudaGetSymbolAddress(&p_h1h, g_h1_hi);
    cudaGetSymbolAddress(&p_h1l, g_h1_lo);
    cudaGetSymbolAddress(&p_a0h, g_a0_hi);
    cudaGetSymbolAddress(&p_a0l, g_a0_lo);
    cudaGetSymbolAddress(&p_a1h, g_a1_hi);
    cudaGetSymbolAddress(&p_a1l, g_a1_lo);
    cudaGetSymbolAddress(&p_fh,  g_feat_hi);
    cudaGetSymbolAddress(&p_fl,  g_feat_lo);

    cudaFuncSetAttribute(hmma_m64_kernel<false>, cudaFuncAttributeMaxDynamicSharedMemorySize, WO_SMEM_BYTES);
    cudaFuncSetAttribute(hmma_m64_kernel<true>,  cudaFuncAttributeMaxDynamicSharedMemorySize, WO_SMEM_BYTES);
    cudaFuncSetAttribute(energy_gc_kernel,       cudaFuncAttributeMaxDynamicSharedMemorySize, EN_SMEM_BYTES);

    // 1. enc + Wk bf16 split
    split2src_kernel<<<ENC_BLKS + WK_BLKS, 256>>>(
        enc, (__nv_bfloat16*)p_eh, (__nv_bfloat16*)p_el,
        Wk,  (__nv_bfloat16*)p_wh, (__nv_bfloat16*)p_wl);

    // 2. mega-prep (mask compact, inits, embed/hidden scatter, out_pred=bout)
    prep_kernel<<<PREP_BLKS, 256>>>(mask, hidden, tok, emb,
                                    bih0, bhh0, bih1, bhh1, bout,
                                    energy, query, gates0, gates1, out_pred,
                                    (__nv_bfloat16*)p_h1h, (__nv_bfloat16*)p_h1l);

    // 3. global compaction across batches
    gather_kernel<<<1, 256>>>();

    // 4. query = hidden[1] @ Wq^T (K-split 4, atomic)
    hmma_m64_kernel<true><<<dim3(H_ / 128, 4), 256, WO_SMEM_BYTES>>>(
        (const __nv_bfloat16*)p_h1h, (const __nv_bfloat16*)p_h1l, H_,
        Wq, H_, Wq, nullptr, query, H_, 4);

    // 5. energy on globally-compacted rows
    energy_gc_kernel<<<dim3(H_ / 128, (B_ * S_) / 128), 256, EN_SMEM_BYTES>>>(
        (const __nv_bfloat16*)p_eh, (const __nv_bfloat16*)p_el,
        (const __nv_bfloat16*)p_wh, (const __nv_bfloat16*)p_wl, v, query, energy);

    // 6. fused masked softmax + compacted context
    softmax_context_kernel<<<dim3(B_, 4), 256>>>(energy, enc, out_attn);

    // 7. layer-0 gates + LSTM
    hmma_m64_kernel<true><<<dim3(G4H_ / 128, 4), 256, WO_SMEM_BYTES>>>(
        (const __nv_bfloat16*)p_a0h, (const __nv_bfloat16*)p_a0l, KCAT0,
        Wih0, E_ + ENC_, Whh0, nullptr, gates0, G4H_, 4);
    lstm_kernel<<<dim3(B_, H_ / 256), 256>>>(gates0, cell, out_cell, out_hid,
                                             (__nv_bfloat16*)p_a1h, (__nv_bfloat16*)p_a1l, KCAT1);

    // 8. layer-1 gates + LSTM
    hmma_m64_kernel<true><<<dim3(G4H_ / 128, 4), 256, WO_SMEM_BYTES>>>(
        (const __nv_bfloat16*)p_a1h, (const __nv_bfloat16*)p_a1l, KCAT1,
        Wih1, H_, Whh1, nullptr, gates1, G4H_, 4);
    lstm_kernel<<<dim3(B_, H_ / 256), 256>>>(gates1, cell + B_ * H_, out_cell + B_ * H_,
                                             out_hid + B_ * H_,
                                             (__nv_bfloat16*)p_fh, (__nv_bfloat16*)p_fl, FDIM_);

    // 9. prediction = feat @ Wout^T + bout (K-split 2, atomic; bout pre-init)
    hmma_m64_kernel<true><<<dim3(V_ / 128, 2), 256, WO_SMEM_BYTES>>>(
        (const __nv_bfloat16*)p_fh, (const __nv_bfloat16*)p_fl, FDIM_,
        Wout, FDIM_, Wout, nullptr, out_pred, V_, 2);
}

// round 8
// speedup vs baseline: 5.7356x; 1.1483x over previous
#include <cuda_runtime.h>
#include <cuda_bf16.h>
#include <cuda_fp16.h>
#include <math.h>
#include <stdint.h>

#define B_   64
#define S_   256
#define H_   1024
#define ENC_ 1024
#define E_   512
#define V_   32000
#define FDIM_ (H_ + ENC_ + E_)   // 2560
#define G4H_  (4 * H_)           // 4096
#define KCAT0 2560
#define KCAT1 2048
#define WKSCALE 2048.0f
#define INVWK   (1.0f / 2048.0f)

// ---------------- scratch ----------------------------------------------------
#define OFF_QUERY   0
#define OFF_GATES0  (OFF_QUERY + B_ * H_)
#define OFF_GATES1  (OFF_GATES0 + B_ * G4H_)
#define OFF_ENERGY  (OFF_GATES1 + B_ * G4H_)
#define SCRATCH_TOTAL (OFF_ENERGY + B_ * S_)

__device__ __align__(16) float g_scratch[SCRATCH_TOTAL];
__device__ int g_sidx[B_ * S_];
__device__ int g_scnt[B_];
__device__ int g_gidx[B_ * S_];
__device__ int g_total;

// fp16 buffers for energy GEMM
__device__ __align__(16) __half g_enc_f16[(long)B_ * S_ * ENC_];
__device__ __align__(16) __half g_wk_h[H_ * ENC_];
__device__ __align__(16) __half g_wk_l[H_ * ENC_];
// bf16 split buffers for the other GEMMs
__device__ __align__(16) __nv_bfloat16 g_h1_hi[B_ * H_];
__device__ __align__(16) __nv_bfloat16 g_h1_lo[B_ * H_];
__device__ __align__(16) __nv_bfloat16 g_a0_hi[B_ * KCAT0];
__device__ __align__(16) __nv_bfloat16 g_a0_lo[B_ * KCAT0];
__device__ __align__(16) __nv_bfloat16 g_a1_hi[B_ * KCAT1];
__device__ __align__(16) __nv_bfloat16 g_a1_lo[B_ * KCAT1];
__device__ __align__(16) __nv_bfloat16 g_feat_hi[B_ * FDIM_];
__device__ __align__(16) __nv_bfloat16 g_feat_lo[B_ * FDIM_];

// ===================== low-level helpers =====================================
__device__ __forceinline__ uint32_t smem_to_u32(const void* p) {
    uint32_t a;
    asm("{ .reg .u64 t; cvta.to.shared.u64 t, %1; cvt.u32.u64 %0, t; }" : "=r"(a) : "l"(p));
    return a;
}

#define CP16(dst_u32, src_ptr) \
    asm volatile("cp.async.cg.shared.global [%0], [%1], 16;" :: "r"(dst_u32), "l"(src_ptr))
#define CP_COMMIT() asm volatile("cp.async.commit_group;" ::: "memory")
template<int N> __device__ __forceinline__ void cp_wait() {
    asm volatile("cp.async.wait_group %0;" :: "n"(N) : "memory");
}

__device__ __forceinline__ void ldmx4(uint32_t addr, uint32_t r[4]) {
    asm volatile("ldmatrix.sync.aligned.m8n8.x4.shared.b16 {%0,%1,%2,%3}, [%4];"
        : "=r"(r[0]), "=r"(r[1]), "=r"(r[2]), "=r"(r[3]) : "r"(addr));
}

__device__ __forceinline__ void mma16816(float* c, const uint32_t a[4],
                                         uint32_t b0, uint32_t b1) {
    asm volatile("mma.sync.aligned.m16n8k16.row.col.f32.bf16.bf16.f32 "
        "{%0,%1,%2,%3}, {%4,%5,%6,%7}, {%8,%9}, {%0,%1,%2,%3};"
        : "+f"(c[0]), "+f"(c[1]), "+f"(c[2]), "+f"(c[3])
        : "r"(a[0]), "r"(a[1]), "r"(a[2]), "r"(a[3]), "r"(b0), "r"(b1));
}

__device__ __forceinline__ void mma16816h(float* c, const uint32_t a[4],
                                          uint32_t b0, uint32_t b1) {
    asm volatile("mma.sync.aligned.m16n8k16.row.col.f32.f16.f16.f32 "
        "{%0,%1,%2,%3}, {%4,%5,%6,%7}, {%8,%9}, {%0,%1,%2,%3};"
        : "+f"(c[0]), "+f"(c[1]), "+f"(c[2]), "+f"(c[3])
        : "r"(a[0]), "r"(a[1]), "r"(a[2]), "r"(a[3]), "r"(b0), "r"(b1));
}

#define STS128(addr, a, b, c, d) \
    asm volatile("st.shared.v4.b32 [%0], {%1,%2,%3,%4};" \
        :: "r"(addr), "r"(a), "r"(b), "r"(c), "r"(d) : "memory")

__device__ __forceinline__ uint32_t swz(int row, int chunk16) {
    return (uint32_t)(row * 128 + ((chunk16 ^ (row & 7)) * 16));
}

__device__ __forceinline__ void split2(float a, float b, uint32_t& hi, uint32_t& lo) {
    __nv_bfloat162 h2 = __floats2bfloat162_rn(a, b);
    float ra = a - __bfloat162float(__low2bfloat16(h2));
    float rb = b - __bfloat162float(__high2bfloat16(h2));
    __nv_bfloat162 l2 = __floats2bfloat162_rn(ra, rb);
    hi = *reinterpret_cast<uint32_t*>(&h2);
    lo = *reinterpret_cast<uint32_t*>(&l2);
}

__device__ __forceinline__ void split1(float a, __nv_bfloat16& hi, __nv_bfloat16& lo) {
    hi = __float2bfloat16_rn(a);
    lo = __float2bfloat16_rn(a - __bfloat162float(hi));
}

// fp16 scaled split: w*2048 = hi + lo
__device__ __forceinline__ void split2h(float a, float b, uint32_t& hi, uint32_t& lo) {
    float as = a * WKSCALE, bs = b * WKSCALE;
    __half2 h2 = __floats2half2_rn(as, bs);
    float ra = as - __half2float(__low2half(h2));
    float rb = bs - __half2float(__high2half(h2));
    __half2 l2 = __floats2half2_rn(ra, rb);
    hi = *reinterpret_cast<uint32_t*>(&h2);
    lo = *reinterpret_cast<uint32_t*>(&l2);
}

// ===================== combined enc+wk split ================================
#define ENC_BLKS ((B_ * S_ * ENC_) / 1024)   // 16384
#define WK_BLKS  ((H_ * ENC_) / 1024)        // 1024

__global__ void split2src_kernel(const float* __restrict__ enc,
                                 __half* __restrict__ ef,
                                 const float* __restrict__ wk,
                                 __half* __restrict__ wh,
                                 __half* __restrict__ wl) {
    if (blockIdx.x < ENC_BLKS) {
        long i = ((long)blockIdx.x * 256 + threadIdx.x) * 4;
        float4 v = *reinterpret_cast<const float4*>(enc + i);
        __half2 h0 = __floats2half2_rn(v.x, v.y);
        __half2 h1 = __floats2half2_rn(v.z, v.w);
        uint2 o = {*reinterpret_cast<uint32_t*>(&h0), *reinterpret_cast<uint32_t*>(&h1)};
        *reinterpret_cast<uint2*>(ef + i) = o;
    } else {
        long i = ((long)(blockIdx.x - ENC_BLKS) * 256 + threadIdx.x) * 4;
        float4 v = *reinterpret_cast<const float4*>(wk + i);
        uint2 H, L;
        split2h(v.x, v.y, H.x, L.x);
        split2h(v.z, v.w, H.y, L.y);
        *reinterpret_cast<uint2*>(wh + i) = H;
        *reinterpret_cast<uint2*>(wl + i) = L;
    }
}

// ===================== mega-prep kernel ======================================
#define PREP_BLKS 2704

__global__ void prep_kernel(const int* __restrict__ mask,
                            const float* __restrict__ hidden,
                            const int* __restrict__ tok,
                            const float* __restrict__ emb,
                            const float* __restrict__ bih0,
                            const float* __restrict__ bhh0,
                            const float* __restrict__ bih1,
                            const float* __restrict__ bhh1,
                            const float* __restrict__ bout,
                            float* __restrict__ energy,
                            float* __restrict__ query,
                            float* __restrict__ gates0,
                            float* __restrict__ gates1,
                            float* __restrict__ out_pred,
                            __nv_bfloat16* __restrict__ h1h,
                            __nv_bfloat16* __restrict__ h1l) {
    const int tid = threadIdx.x;
    const int blk = blockIdx.x;
    if (blk < B_) {
        const int b = blk;
        __shared__ int sc[256];
        int m = (mask[b * S_ + tid] != 0) ? 1 : 0;
        sc[tid] = m;
        __syncthreads();
#pragma unroll
        for (int off = 1; off < 256; off <<= 1) {
            int t = (tid >= off) ? sc[tid - off] : 0;
            __syncthreads();
            sc[tid] += t;
            __syncthreads();
        }
        int total = sc[255];
        int my = sc[tid] - m;
        if (m) g_sidx[b * S_ + my] = tid;
        if (tid >= total) g_sidx[b * S_ + tid] = 0;
        energy[b * S_ + tid] = m ? 0.f : -1e10f;
        if (tid == 0) g_scnt[b] = total;
        const int t = tok[b];
        for (int j = tid; j < E_; j += 256) {
            __nv_bfloat16 hi, lo;
            split1(emb[(long)t * E_ + j], hi, lo);
            g_a0_hi[b * KCAT0 + j] = hi;
            g_a0_lo[b * KCAT0 + j] = lo;
            g_feat_hi[b * FDIM_ + (H_ + ENC_) + j] = hi;
            g_feat_lo[b * FDIM_ + (H_ + ENC_) + j] = lo;
        }
        for (int j = tid; j < H_; j += 256) {
            __nv_bfloat16 hi, lo;
            split1(hidden[b * H_ + j], hi, lo);
            g_a0_hi[b * KCAT0 + (E_ + ENC_) + j] = hi;
            g_a0_lo[b * KCAT0 + (E_ + ENC_) + j] = lo;
            split1(hidden[B_ * H_ + b * H_ + j], hi, lo);
            g_a1_hi[b * KCAT1 + H_ + j] = hi;
            g_a1_lo[b * KCAT1 + H_ + j] = lo;
        }
    } else if (blk < 128) {
        long i = ((long)(blk - 64) * 256 + tid) * 4;
        float4 v = *reinterpret_cast<const float4*>(hidden + (long)B_ * H_ + i);
        uint2 H, L;
        split2(v.x, v.y, H.x, L.x);
        split2(v.z, v.w, H.y, L.y);
        *reinterpret_cast<uint2*>(h1h + i) = H;
        *reinterpret_cast<uint2*>(h1l + i) = L;
    } else if (blk < 192) {
        long i = ((long)(blk - 128) * 256 + tid) * 4;
        float4 z = {0.f, 0.f, 0.f, 0.f};
        *reinterpret_cast<float4*>(query + i) = z;
    } else if (blk < 448) {
        long i = ((long)(blk - 192) * 256 + tid) * 4;
        int n = (int)(i & (G4H_ - 1));
        float4 o = {bih0[n] + bhh0[n], bih0[n + 1] + bhh0[n + 1],
                    bih0[n + 2] + bhh0[n + 2], bih0[n + 3] + bhh0[n + 3]};
        *reinterpret_cast<float4*>(gates0 + i) = o;
    } else if (blk < 704) {
        long i = ((long)(blk - 448) * 256 + tid) * 4;
        int n = (int)(i & (G4H_ - 1));
        float4 o = {bih1[n] + bhh1[n], bih1[n + 1] + bhh1[n + 1],
                    bih1[n + 2] + bhh1[n + 2], bih1[n + 3] + bhh1[n + 3]};
        *reinterpret_cast<float4*>(gates1 + i) = o;
    } else {
        long i = ((long)(blk - 704) * 1024 + tid * 4);
        int col = (int)(i % V_);
        float4 o = {bout[col], bout[col + 1], bout[col + 2], bout[col + 3]};
        *reinterpret_cast<float4*>(out_pred + i) = o;
    }
}

// ===================== global gather =========================================
__global__ void gather_kernel() {
    __shared__ int offs[B_ + 1];
    const int tid = threadIdx.x;
    if (tid == 0) {
        int acc = 0;
        for (int b = 0; b < B_; b++) { offs[b] = acc; acc += g_scnt[b]; }
        offs[B_] = acc;
        g_total = acc;
    }
    __syncthreads();
    for (int b = 0; b < B_; b++) {
        int o = offs[b], cnt = offs[b + 1] - o;
        for (int j = tid; j < cnt; j += 256)
            g_gidx[o + j] = b * S_ + g_sidx[b * S_ + j];
    }
    int total = offs[B_];
    for (int j = total + tid; j < B_ * S_; j += 256) g_gidx[j] = 0;
}

// ===================== fat-B HMMA kernel (bf16 3-term) =======================
#define WO_A_TILE 8192
#define WO_B_TILE 16384
#define WO_STAGE  (2 * WO_A_TILE + 2 * WO_B_TILE)
#define WO_SMEM_BYTES (1024 + 2 * WO_STAGE)

__device__ __forceinline__ void wo_load_A(const __nv_bfloat16* fh, const __nv_bfloat16* fl,
                                          int lda, int c0, uint32_t stg) {
    const int tid = threadIdx.x;
#pragma unroll
    for (int i = 0; i < 2; i++) {
        int idx = tid + i * 256;
        int r = idx >> 3, cc = idx & 7;
        uint32_t off = swz(r, cc);
        long src = (long)r * lda + c0 + cc * 8;
        CP16(stg + off, fh + src);
        CP16(stg + WO_A_TILE + off, fl + src);
    }
}

template<bool ATOMIC>
__global__ __launch_bounds__(256, 2)
void hmma_m64_kernel(const __nv_bfloat16* __restrict__ ah_g,
                     const __nv_bfloat16* __restrict__ al_g,
                     int Ktot,
                     const float* __restrict__ B1, int k1,
                     const float* __restrict__ B2,
                     const float* __restrict__ bias1,
                     float* __restrict__ C, int ldc, int nks) {
    extern __shared__ char smem[];
    uint32_t sb = smem_to_u32(smem);
    uint32_t tiles = (sb + 1023) & ~1023u;

    const int tid = threadIdx.x;
    const int wid = tid >> 5, lane = tid & 31;
    const int warp_m = (wid & 1) * 32;
    const int warp_n = (wid >> 1) * 32;
    const int n0 = blockIdx.x * 128;

    const int br = tid >> 1;
    const int bhalf = tid & 1;
    const int k2 = Ktot - k1;

    const int KT = Ktot / 64;
    const int kt0 = (int)blockIdx.y * (KT / nks);
    const int kt1 = kt0 + KT / nks;

    auto bptr = [&](int c0) -> const float* {
        return (c0 < k1) ? B1 + (long)(n0 + br) * k1 + c0 + bhalf * 32
                         : B2 + (long)(n0 + br) * k2 + (c0 - k1) + bhalf * 32;
    };

    float c[2][4][4];
#pragma unroll
    for (int i = 0; i < 2; i++)
#pragma unroll
        for (int j = 0; j < 4; j++)
#pragma unroll
            for (int k = 0; k < 4; k++) c[i][j][k] = 0.f;

    wo_load_A(ah_g, al_g, Ktot, kt0 * 64, tiles + (kt0 & 1) * WO_STAGE);
    CP_COMMIT();

    for (int kt = kt0; kt < kt1; kt++) {
        uint32_t stg = tiles + (kt & 1) * WO_STAGE;
        if (kt + 1 < kt1) {
            wo_load_A(ah_g, al_g, Ktot, (kt + 1) * 64, tiles + ((kt + 1) & 1) * WO_STAGE);
            CP_COMMIT();
        }
        uint32_t Bh = stg + 2 * WO_A_TILE, Bl = Bh + WO_B_TILE;
        const float* w = bptr(kt * 64);
#pragma unroll
        for (int j = 0; j < 4; j++) {
            float4 v0 = *reinterpret_cast<const float4*>(w + j * 8);
            float4 v1 = *reinterpret_cast<const float4*>(w + j * 8 + 4);
            uint4 Hq, Lq;
            split2(v0.x, v0.y, Hq.x, Lq.x);
            split2(v0.z, v0.w, Hq.y, Lq.y);
            split2(v1.x, v1.y, Hq.z, Lq.z);
            split2(v1.z, v1.w, Hq.w, Lq.w);
            uint32_t off = swz(br, bhalf * 4 + j);
            STS128(Bh + off, Hq.x, Hq.y, Hq.z, Hq.w);
            STS128(Bl + off, Lq.x, Lq.y, Lq.z, Lq.w);
        }
        if (kt + 1 < kt1) cp_wait<1>(); else cp_wait<0>();
        __syncthreads();
        {
            const uint32_t Ah = stg, Al = stg + WO_A_TILE;
            const int lm = lane & 15, lh = lane >> 4;
#pragma unroll
            for (int ks = 0; ks < 4; ks++) {
                const int ch = ks * 2 + lh;
                uint32_t ah[2][4], al[2][4];
#pragma unroll
                for (int mf = 0; mf < 2; mf++) {
                    uint32_t off = swz(warp_m + mf * 16 + lm, ch);
                    ldmx4(Ah + off, ah[mf]);
                    ldmx4(Al + off, al[mf]);
                }
                uint32_t bb[2][4];
#pragma unroll
                for (int nf2 = 0; nf2 < 2; nf2++) {
                    uint32_t off = swz(warp_n + nf2 * 16 + lm, ch);
                    ldmx4(Bh + off, bb[nf2]);
                }
#pragma unroll
                for (int nf2 = 0; nf2 < 2; nf2++)
#pragma unroll
                    for (int mf = 0; mf < 2; mf++) {
                        mma16816(c[mf][nf2 * 2 + 0], ah[mf], bb[nf2][0], bb[nf2][2]);
                        mma16816(c[mf][nf2 * 2 + 1], ah[mf], bb[nf2][1], bb[nf2][3]);
                        mma16816(c[mf][nf2 * 2 + 0], al[mf], bb[nf2][0], bb[nf2][2]);
                        mma16816(c[mf][nf2 * 2 + 1], al[mf], bb[nf2][1], bb[nf2][3]);
                    }
#pragma unroll
                for (int nf2 = 0; nf2 < 2; nf2++) {
                    uint32_t off = swz(warp_n + nf2 * 16 + lm, ch);
                    ldmx4(Bl + off, bb[nf2]);
                }
#pragma unroll
                for (int nf2 = 0; nf2 < 2; nf2++)
#pragma unroll
                    for (int mf = 0; mf < 2; mf++) {
                        mma16816(c[mf][nf2 * 2 + 0], ah[mf], bb[nf2][0], bb[nf2][2]);
                        mma16816(c[mf][nf2 * 2 + 1], ah[mf], bb[nf2][1], bb[nf2][3]);
                    }
            }
        }
        __syncthreads();
    }

#pragma unroll
    for (int mf = 0; mf < 2; mf++)
#pragma unroll
        for (int nf = 0; nf < 4; nf++) {
            int col = n0 + warp_n + nf * 8 + (lane & 3) * 2;
            int r0 = warp_m + mf * 16 + (lane >> 2);
            if (ATOMIC) {
                atomicAdd(&C[(long)r0 * ldc + col],           c[mf][nf][0]);
                atomicAdd(&C[(long)r0 * ldc + col + 1],       c[mf][nf][1]);
                atomicAdd(&C[(long)(r0 + 8) * ldc + col],     c[mf][nf][2]);
                atomicAdd(&C[(long)(r0 + 8) * ldc + col + 1], c[mf][nf][3]);
            } else {
                float b0 = 0.f, b1 = 0.f;
                if (bias1) { b0 = bias1[col]; b1 = bias1[col + 1]; }
                float2 o0 = {c[mf][nf][0] + b0, c[mf][nf][1] + b1};
                float2 o1 = {c[mf][nf][2] + b0, c[mf][nf][3] + b1};
                *reinterpret_cast<float2*>(C + (long)r0 * ldc + col) = o0;
                *reinterpret_cast<float2*>(C + (long)(r0 + 8) * ldc + col) = o1;
            }
        }
}

// ===================== energy: fp16 2-term, 256-row super-tiles ==============
// grid (8 n-blocks, 64 m-super-tiles). Block = 256 gathered rows x 128 h-cols.
// A = enc fp16 (single); B = 2048*Wk fp16 hi/lo. C = A*Bh + A*Bl; keys = C/2048.
#define EN_T 16384                        // one 128x64 fp16 tile
#define EN_STAGE (4 * EN_T)               // A0 A1 Bh Bl = 64KB
#define EN_SMEM_BYTES (2048 + 2 * EN_STAGE)

__global__ __launch_bounds__(256, 1)
void energy_f16_kernel(const __half* __restrict__ ef,
                       const __half* __restrict__ wh,
                       const __half* __restrict__ wl,
                       const float* __restrict__ vvec,
                       const float* __restrict__ query,
                       float* __restrict__ energy) {
    const int total = g_total;
    const int mt = (int)blockIdx.y * 256;
    if (mt >= total) return;

    extern __shared__ char smem[];
    uint32_t sb = smem_to_u32(smem);
    uint32_t tiles = (sb + 2048 + 1023) & ~1023u;

    const int tid = threadIdx.x;
    const int wid = tid >> 5, lane = tid & 31;
    const int warp_m = (wid & 3) * 32;
    const int warp_n = (wid >> 2) * 64;
    const int n0 = blockIdx.x * 128;

    float* vs = (float*)smem;               // 128 floats
    int*   sid = (int*)(vs + 128);          // 256 ints
    if (tid < 128) vs[tid] = vvec[n0 + tid];
    sid[tid] = g_gidx[mt + tid];
    __syncthreads();

    // hoisted per-thread load bases (uint32 element offsets)
    const int rb = tid >> 3, cc8 = (tid & 7) * 8;
    const uint32_t soff = swz(rb, tid & 7);       // same swizzle for r, r+32, ... (rb<32)
    uint32_t a0off[4], a1off[4], boff[4];
    uint32_t soffs[4];
#pragma unroll
    for (int i = 0; i < 4; i++) {
        int r = rb + 32 * i;
        soffs[i]  = swz(r, tid & 7);
        a0off[i] = (uint32_t)sid[r] * ENC_ + cc8;
        a1off[i] = (uint32_t)sid[r + 128] * ENC_ + cc8;
        boff[i]  = (uint32_t)(n0 + r) * ENC_ + cc8;
    }

    float c0[2][8][4], c1[2][8][4];
#pragma unroll
    for (int i = 0; i < 2; i++)
#pragma unroll
        for (int j = 0; j < 8; j++)
#pragma unroll
            for (int k = 0; k < 4; k++) { c0[i][j][k] = 0.f; c1[i][j][k] = 0.f; }

    auto load_stage = [&](int c0v, uint32_t stg) {
#pragma unroll
        for (int i = 0; i < 4; i++) {
            CP16(stg + soffs[i],              ef + a0off[i] + c0v);
            CP16(stg + EN_T + soffs[i],       ef + a1off[i] + c0v);
            CP16(stg + 2 * EN_T + soffs[i],   wh + boff[i] + c0v);
            CP16(stg + 3 * EN_T + soffs[i],   wl + boff[i] + c0v);
        }
    };

    load_stage(0, tiles);
    CP_COMMIT();

    const int KT = ENC_ / 64;   // 16
    for (int kt = 0; kt < KT; kt++) {
        uint32_t stg = tiles + (kt & 1) * EN_STAGE;
        if (kt + 1 < KT) {
            load_stage((kt + 1) * 64, tiles + ((kt + 1) & 1) * EN_STAGE);
            CP_COMMIT();
            cp_wait<1>();
        } else {
            cp_wait<0>();
        }
        __syncthreads();
        {
            const uint32_t A0 = stg, A1 = stg + EN_T;
            const uint32_t Bh = stg + 2 * EN_T, Bl = stg + 3 * EN_T;
            const int lm = lane & 15, lh = lane >> 4;
#pragma unroll
            for (int ks = 0; ks < 4; ks++) {
                const int ch = ks * 2 + lh;
                uint32_t a0[2][4], a1[2][4];
#pragma unroll
                for (int mf = 0; mf < 2; mf++) {
                    uint32_t off = swz(warp_m + mf * 16 + lm, ch);
                    ldmx4(A0 + off, a0[mf]);
                    ldmx4(A1 + off, a1[mf]);
                }
                uint32_t bb[4][4];
#pragma unroll
                for (int nf2 = 0; nf2 < 4; nf2++) {
                    uint32_t off = swz(warp_n + nf2 * 16 + lm, ch);
                    ldmx4(Bh + off, bb[nf2]);
                }
#pragma unroll
                for (int nf2 = 0; nf2 < 4; nf2++)
#pragma unroll
                    for (int mf = 0; mf < 2; mf++) {
                        mma16816h(c0[mf][nf2 * 2 + 0], a0[mf], bb[nf2][0], bb[nf2][2]);
                        mma16816h(c0[mf][nf2 * 2 + 1], a0[mf], bb[nf2][1], bb[nf2][3]);
                        mma16816h(c1[mf][nf2 * 2 + 0], a1[mf], bb[nf2][0], bb[nf2][2]);
                        mma16816h(c1[mf][nf2 * 2 + 1], a1[mf], bb[nf2][1], bb[nf2][3]);
                    }
#pragma unroll
                for (int nf2 = 0; nf2 < 4; nf2++) {
                    uint32_t off = swz(warp_n + nf2 * 16 + lm, ch);
                    ldmx4(Bl + off, bb[nf2]);
                }
#pragma unroll
                for (int nf2 = 0; nf2 < 4; nf2++)
#pragma unroll
                    for (int mf = 0; mf < 2; mf++) {
                        mma16816h(c0[mf][nf2 * 2 + 0], a0[mf], bb[nf2][0], bb[nf2][2]);
                        mma16816h(c0[mf][nf2 * 2 + 1], a0[mf], bb[nf2][1], bb[nf2][3]);
                        mma16816h(c1[mf][nf2 * 2 + 0], a1[mf], bb[nf2][0], bb[nf2][2]);
                        mma16816h(c1[mf][nf2 * 2 + 1], a1[mf], bb[nf2][1], bb[nf2][3]);
                    }
            }
        }
        __syncthreads();
    }

    // epilogue for both m-tiles: keys = c/2048; energy += v*tanh(q+keys)
#pragma unroll
    for (int t = 0; t < 2; t++) {
#pragma unroll
        for (int mf = 0; mf < 2; mf++) {
            int rl = t * 128 + warp_m + mf * 16 + (lane >> 2);
            int rh = rl + 8;
            int gl = sid[rl], gh = sid[rh];
            const float* ql = query + (long)(gl >> 8) * H_ + n0;
            const float* qh = query + (long)(gh >> 8) * H_ + n0;
            float s_lo = 0.f, s_hi = 0.f;
#pragma unroll
            for (int nf = 0; nf < 8; nf++) {
                int col = warp_n + nf * 8 + (lane & 3) * 2;
                float v0 = vs[col], v1 = vs[col + 1];
                float* cc = t ? c1[mf][nf] : c0[mf][nf];
                s_lo += v0 * tanhf(ql[col] + cc[0] * INVWK) + v1 * tanhf(ql[col + 1] + cc[1] * INVWK);
                s_hi += v0 * tanhf(qh[col] + cc[2] * INVWK) + v1 * tanhf(qh[col + 1] + cc[3] * INVWK);
            }
            s_lo += __shfl_xor_sync(0xffffffff, s_lo, 1);
            s_lo += __shfl_xor_sync(0xffffffff, s_lo, 2);
            s_hi += __shfl_xor_sync(0xffffffff, s_hi, 1);
            s_hi += __shfl_xor_sync(0xffffffff, s_hi, 2);
            if ((lane & 3) == 0) {
                if (mt + rl < total) atomicAdd(&energy[gl], s_lo);
                if (mt + rh < total) atomicAdd(&energy[gh], s_hi);
            }
        }
    }
}

// ===================== fused softmax + compacted context =====================
__global__ void softmax_context_kernel(const float* __restrict__ energy,
                                       const float* __restrict__ enc,
                                       float* __restrict__ out_attn) {
    __shared__ float red[256];
    __shared__ float w[256];
    __shared__ int sid[256];
    __shared__ int cnts;
    const int b = blockIdx.x;
    const int tid = threadIdx.x;

    float val = energy[b * S_ + tid];
    red[tid] = val;
    sid[tid] = g_sidx[b * S_ + tid];
    if (tid == 0) cnts = g_scnt[b];
    __syncthreads();
#pragma unroll
    for (int off = 128; off > 0; off >>= 1) {
        if (tid < off) red[tid] = fmaxf(red[tid], red[tid + off]);
        __syncthreads();
    }
    float mx = red[0];
    __syncthreads();
    float ex = expf(val - mx);
    red[tid] = ex;
    __syncthreads();
#pragma unroll
    for (int off = 128; off > 0; off >>= 1) {
        if (tid < off) red[tid] += red[tid + off];
        __syncthreads();
    }
    float aw = ex / red[0];
    if (blockIdx.y == 0) out_attn[b * S_ + tid] = aw;
    w[tid] = aw;
    __syncthreads();

    const int cnt = cnts;
    const int col = blockIdx.y * 256 + tid;
    const float* eb = enc + (long)b * S_ * ENC_;
    float a0 = 0.f, a1 = 0.f, a2 = 0.f, a3 = 0.f;
    int j = 0;
    for (; j + 4 <= cnt; j += 4) {
        a0 = fmaf(w[sid[j]],     eb[(long)sid[j] * ENC_ + col],     a0);
        a1 = fmaf(w[sid[j + 1]], eb[(long)sid[j + 1] * ENC_ + col], a1);
        a2 = fmaf(w[sid[j + 2]], eb[(long)sid[j + 2] * ENC_ + col], a2);
        a3 = fmaf(w[sid[j + 3]], eb[(long)sid[j + 3] * ENC_ + col], a3);
    }
    for (; j < cnt; j++)
        a0 = fmaf(w[sid[j]], eb[(long)sid[j] * ENC_ + col], a0);
    float acc = (a0 + a1) + (a2 + a3);
    __nv_bfloat16 hi, lo;
    split1(acc, hi, lo);
    g_a0_hi[b * KCAT0 + E_ + col] = hi;
    g_a0_lo[b * KCAT0 + E_ + col] = lo;
    g_feat_hi[b * FDIM_ + H_ + col] = hi;
    g_feat_lo[b * FDIM_ + H_ + col] = lo;
}

// ===================== LSTM pointwise ========================================
__global__ void lstm_kernel(const float* __restrict__ gates,
                            const float* __restrict__ c_prev,
                            float* __restrict__ c_out,
                            float* __restrict__ h_out_f32,
                            __nv_bfloat16* __restrict__ hb_hi,
                            __nv_bfloat16* __restrict__ hb_lo,
                            int sb) {
    const int b = blockIdx.x;
    const int idx = blockIdx.y * 256 + threadIdx.x;
    float gi = gates[b * G4H_ + idx];
    float gf = gates[b * G4H_ + H_ + idx];
    float gg = gates[b * G4H_ + 2 * H_ + idx];
    float go = gates[b * G4H_ + 3 * H_ + idx];
    float c  = c_prev[b * H_ + idx];
    float si = 1.f / (1.f + expf(-gi));
    float sf = 1.f / (1.f + expf(-gf));
    float so = 1.f / (1.f + expf(-go));
    float cn = sf * c + si * tanhf(gg);
    float hn = so * tanhf(cn);
    c_out[b * H_ + idx]     = cn;
    h_out_f32[b * H_ + idx] = hn;
    __nv_bfloat16 hi, lo;
    split1(hn, hi, lo);
    hb_hi[b * sb + idx] = hi;
    hb_lo[b * sb + idx] = lo;
}

// ===================== launch ================================================
extern "C" void kernel_launch(void* const* d_in, const int* in_sizes, int n_in,
                              void* d_out, int out_size) {
    const int*   tok    = (const int*)  d_in[0];
    const float* hidden = (const float*)d_in[1];
    const float* cell   = (const float*)d_in[2];
    const float* enc    = (const float*)d_in[3];
    const int*   mask   = (const int*)  d_in[4];
    const float* emb    = (const float*)d_in[5];
    const float* Wq     = (const float*)d_in[6];
    const float* Wk     = (const float*)d_in[7];
    const float* v      = (const float*)d_in[8];
    const float* Wih0   = (const float*)d_in[9];
    const float* Whh0   = (const float*)d_in[10];
    const float* bih0   = (const float*)d_in[11];
    const float* bhh0   = (const float*)d_in[12];
    const float* Wih1   = (const float*)d_in[13];
    const float* Whh1   = (const float*)d_in[14];
    const float* bih1   = (const float*)d_in[15];
    const float* bhh1   = (const float*)d_in[16];
    const float* Wout   = (const float*)d_in[17];
    const float* bout   = (const float*)d_in[18];

    float* out      = (float*)d_out;
    float* out_pred = out;
    float* out_hid  = out + (long)B_ * V_;
    float* out_cell = out_hid + 2 * B_ * H_;
    float* out_attn = out_cell + 2 * B_ * H_;

    void* sp = nullptr;
    cudaGetSymbolAddress(&sp, g_scratch);
    float* scratch = (float*)sp;
    float* query  = scratch + OFF_QUERY;
    float* gates0 = scratch + OFF_GATES0;
    float* gates1 = scratch + OFF_GATES1;
    float* energy = scratch + OFF_ENERGY;

    void *p_ef, *p_wh, *p_wl, *p_h1h, *p_h1l,
         *p_a0h, *p_a0l, *p_a1h, *p_a1l, *p_fh, *p_fl;
    cudaGetSymbolAddress(&p_ef,  g_enc_f16);
    cudaGetSymbolAddress(&p_wh,  g_wk_h);
    cudaGetSymbolAddress(&p_wl,  g_wk_l);
    cudaGetSymbolAddress(&p_h1h, g_h1_hi);
    cudaGetSymbolAddress(&p_h1l, g_h1_lo);
    cudaGetSymbolAddress(&p_a0h, g_a0_hi);
    cudaGetSymbolAddress(&p_a0l, g_a0_lo);
    cudaGetSymbolAddress(&p_a1h, g_a1_hi);
    cudaGetSymbolAddress(&p_a1l, g_a1_lo);
    cudaGetSymbolAddress(&p_fh,  g_feat_hi);
    cudaGetSymbolAddress(&p_fl,  g_feat_lo);

    cudaFuncSetAttribute(hmma_m64_kernel<false>, cudaFuncAttributeMaxDynamicSharedMemorySize, WO_SMEM_BYTES);
    cudaFuncSetAttribute(hmma_m64_kernel<true>,  cudaFuncAttributeMaxDynamicSharedMemorySize, WO_SMEM_BYTES);
    cudaFuncSetAttribute(energy_f16_kernel,      cudaFuncAttributeMaxDynamicSharedMemorySize, EN_SMEM_BYTES);

    // 1. enc fp16 + Wk scaled fp16 hi/lo
    split2src_kernel<<<ENC_BLKS + WK_BLKS, 256>>>(
        enc, (__half*)p_ef, Wk, (__half*)p_wh, (__half*)p_wl);

    // 2. mega-prep
    prep_kernel<<<PREP_BLKS, 256>>>(mask, hidden, tok, emb,
                                    bih0, bhh0, bih1, bhh1, bout,
                                    energy, query, gates0, gates1, out_pred,
                                    (__nv_bfloat16*)p_h1h, (__nv_bfloat16*)p_h1l);

    // 3. global compaction
    gather_kernel<<<1, 256>>>();

    // 4. query = hidden[1] @ Wq^T (bf16 3-term, K-split 4, atomic)
    hmma_m64_kernel<true><<<dim3(H_ / 128, 4), 256, WO_SMEM_BYTES>>>(
        (const __nv_bfloat16*)p_h1h, (const __nv_bfloat16*)p_h1l, H_,
        Wq, H_, Wq, nullptr, query, H_, 4);

    // 5. energy (fp16 2-term, 256-row super-tiles with Wk reuse)
    energy_f16_kernel<<<dim3(H_ / 128, (B_ * S_) / 256), 256, EN_SMEM_BYTES>>>(
        (const __half*)p_ef, (const __half*)p_wh, (const __half*)p_wl,
        v, query, energy);

    // 6. fused masked softmax + compacted context
    softmax_context_kernel<<<dim3(B_, 4), 256>>>(energy, enc, out_attn);

    // 7. layer-0 gates + LSTM
    hmma_m64_kernel<true><<<dim3(G4H_ / 128, 4), 256, WO_SMEM_BYTES>>>(
        (const __nv_bfloat16*)p_a0h, (const __nv_bfloat16*)p_a0l, KCAT0,
        Wih0, E_ + ENC_, Whh0, nullptr, gates0, G4H_, 4);
    lstm_kernel<<<dim3(B_, H_ / 256), 256>>>(gates0, cell, out_cell, out_hid,
                                             (__nv_bfloat16*)p_a1h, (__nv_bfloat16*)p_a1l, KCAT1);

    // 8. layer-1 gates + LSTM
    hmma_m64_kernel<true><<<dim3(G4H_ / 128, 4), 256, WO_SMEM_BYTES>>>(
        (const __nv_bfloat16*)p_a1h, (const __nv_bfloat16*)p_a1l, KCAT1,
        Wih1, H_, Whh1, nullptr, gates1, G4H_, 4);
    lstm_kernel<<<dim3(B_, H_ / 256), 256>>>(gates1, cell + B_ * H_, out_cell + B_ * H_,
                                             out_hid + B_ * H_,
                                             (__nv_bfloat16*)p_fh, (__nv_bfloat16*)p_fl, FDIM_);

    // 9. prediction (bf16 3-term, K-split 2, atomic; bout pre-init)
    hmma_m64_kernel<true><<<dim3(V_ / 128, 2), 256, WO_SMEM_BYTES>>>(
        (const __nv_bfloat16*)p_fh, (const __nv_bfloat16*)p_fl, FDIM_,
        Wout, FDIM_, Wout, nullptr, out_pred, V_, 2);
}

// round 9
// speedup vs baseline: 6.2154x; 1.0836x over previous
#include <cuda_runtime.h>
#include <cuda_bf16.h>
#include <cuda_fp16.h>
#include <math.h>
#include <stdint.h>

#define B_   64
#define S_   256
#define H_   1024
#define ENC_ 1024
#define E_   512
#define V_   32000
#define FDIM_ (H_ + ENC_ + E_)   // 2560
#define G4H_  (4 * H_)           // 4096
#define KCAT0 2560
#define KCAT1 2048
#define WKSCALE 2048.0f
#define INVWK   (1.0f / 2048.0f)

// ---------------- scratch ----------------------------------------------------
#define OFF_QUERY   0
#define OFF_GATES0  (OFF_QUERY + B_ * H_)
#define OFF_GATES1  (OFF_GATES0 + B_ * G4H_)
#define OFF_ENERGY  (OFF_GATES1 + B_ * G4H_)
#define SCRATCH_TOTAL (OFF_ENERGY + B_ * S_)

__device__ __align__(16) float g_scratch[SCRATCH_TOTAL];
__device__ int g_sidx[B_ * S_];
__device__ int g_scnt[B_];
__device__ int g_gidx[B_ * S_];
__device__ int g_total;

// fp16 buffers
__device__ __align__(16) __half g_enc_f16[(long)B_ * S_ * ENC_];
__device__ __align__(16) __half g_wk_h[H_ * ENC_];
__device__ __align__(16) __half g_wk_l[H_ * ENC_];
__device__ __align__(16) __half g_h1f[B_ * H_];
__device__ __align__(16) __half g_a0f[B_ * KCAT0];
__device__ __align__(16) __half g_a1f[B_ * KCAT1];
__device__ __align__(16) __half g_featf[B_ * FDIM_];

// ===================== low-level helpers =====================================
__device__ __forceinline__ uint32_t smem_to_u32(const void* p) {
    uint32_t a;
    asm("{ .reg .u64 t; cvta.to.shared.u64 t, %1; cvt.u32.u64 %0, t; }" : "=r"(a) : "l"(p));
    return a;
}

#define CP16(dst_u32, src_ptr) \
    asm volatile("cp.async.cg.shared.global [%0], [%1], 16;" :: "r"(dst_u32), "l"(src_ptr))
#define CP_COMMIT() asm volatile("cp.async.commit_group;" ::: "memory")
template<int N> __device__ __forceinline__ void cp_wait() {
    asm volatile("cp.async.wait_group %0;" :: "n"(N) : "memory");
}

__device__ __forceinline__ void ldmx4(uint32_t addr, uint32_t r[4]) {
    asm volatile("ldmatrix.sync.aligned.m8n8.x4.shared.b16 {%0,%1,%2,%3}, [%4];"
        : "=r"(r[0]), "=r"(r[1]), "=r"(r[2]), "=r"(r[3]) : "r"(addr));
}

__device__ __forceinline__ void mma16816h(float* c, const uint32_t a[4],
                                          uint32_t b0, uint32_t b1) {
    asm volatile("mma.sync.aligned.m16n8k16.row.col.f32.f16.f16.f32 "
        "{%0,%1,%2,%3}, {%4,%5,%6,%7}, {%8,%9}, {%0,%1,%2,%3};"
        : "+f"(c[0]), "+f"(c[1]), "+f"(c[2]), "+f"(c[3])
        : "r"(a[0]), "r"(a[1]), "r"(a[2]), "r"(a[3]), "r"(b0), "r"(b1));
}

#define STS128(addr, a, b, c, d) \
    asm volatile("st.shared.v4.b32 [%0], {%1,%2,%3,%4};" \
        :: "r"(addr), "r"(a), "r"(b), "r"(c), "r"(d) : "memory")

__device__ __forceinline__ uint32_t swz(int row, int chunk16) {
    return (uint32_t)(row * 128 + ((chunk16 ^ (row & 7)) * 16));
}

// fp16 scaled split: w*2048 = hi + lo
__device__ __forceinline__ void split2h(float a, float b, uint32_t& hi, uint32_t& lo) {
    float as = a * WKSCALE, bs = b * WKSCALE;
    __half2 h2 = __floats2half2_rn(as, bs);
    float ra = as - __half2float(__low2half(h2));
    float rb = bs - __half2float(__high2half(h2));
    __half2 l2 = __floats2half2_rn(ra, rb);
    hi = *reinterpret_cast<uint32_t*>(&h2);
    lo = *reinterpret_cast<uint32_t*>(&l2);
}

// ===================== mega prep+split kernel ================================
// [0, ENC_BLKS): enc -> fp16
// [+WK_BLKS): wk -> scaled fp16 hi/lo
// then: [64) mask/energy/embed/hidden, [64) h1 fp16, [64) query zero,
//       [256) gates0 bias, [256) gates1 bias, [2000) out_pred = bout
#define ENC_BLKS ((B_ * S_ * ENC_) / 1024)   // 16384
#define WK_BLKS  ((H_ * ENC_) / 1024)        // 1024
#define P0 (ENC_BLKS + WK_BLKS)              // 17408
#define PREP_BLKS (P0 + 64 + 64 + 64 + 256 + 256 + 2000)

__global__ void prep_kernel(const float* __restrict__ enc,
                            const float* __restrict__ wk,
                            const int* __restrict__ mask,
                            const float* __restrict__ hidden,
                            const int* __restrict__ tok,
                            const float* __restrict__ emb,
                            const float* __restrict__ bih0,
                            const float* __restrict__ bhh0,
                            const float* __restrict__ bih1,
                            const float* __restrict__ bhh1,
                            const float* __restrict__ bout,
                            float* __restrict__ energy,
                            float* __restrict__ query,
                            float* __restrict__ gates0,
                            float* __restrict__ gates1,
                            float* __restrict__ out_pred) {
    const int tid = threadIdx.x;
    const int blk = blockIdx.x;
    if (blk < ENC_BLKS) {
        long i = ((long)blk * 256 + tid) * 4;
        float4 v = *reinterpret_cast<const float4*>(enc + i);
        __half2 h0 = __floats2half2_rn(v.x, v.y);
        __half2 h1 = __floats2half2_rn(v.z, v.w);
        uint2 o = {*reinterpret_cast<uint32_t*>(&h0), *reinterpret_cast<uint32_t*>(&h1)};
        *reinterpret_cast<uint2*>(g_enc_f16 + i) = o;
    } else if (blk < P0) {
        long i = ((long)(blk - ENC_BLKS) * 256 + tid) * 4;
        float4 v = *reinterpret_cast<const float4*>(wk + i);
        uint2 H, L;
        split2h(v.x, v.y, H.x, L.x);
        split2h(v.z, v.w, H.y, L.y);
        *reinterpret_cast<uint2*>(g_wk_h + i) = H;
        *reinterpret_cast<uint2*>(g_wk_l + i) = L;
    } else if (blk < P0 + 64) {
        const int b = blk - P0;
        __shared__ int sc[256];
        int m = (mask[b * S_ + tid] != 0) ? 1 : 0;
        sc[tid] = m;
        __syncthreads();
#pragma unroll
        for (int off = 1; off < 256; off <<= 1) {
            int t = (tid >= off) ? sc[tid - off] : 0;
            __syncthreads();
            sc[tid] += t;
            __syncthreads();
        }
        int total = sc[255];
        int my = sc[tid] - m;
        if (m) g_sidx[b * S_ + my] = tid;
        if (tid >= total) g_sidx[b * S_ + tid] = 0;
        energy[b * S_ + tid] = m ? 0.f : -1e10f;
        if (tid == 0) g_scnt[b] = total;
        const int t = tok[b];
        for (int j = tid; j < E_; j += 256) {
            __half hv = __float2half_rn(emb[(long)t * E_ + j]);
            g_a0f[b * KCAT0 + j] = hv;
            g_featf[b * FDIM_ + (H_ + ENC_) + j] = hv;
        }
        for (int j = tid; j < H_; j += 256) {
            g_a0f[b * KCAT0 + (E_ + ENC_) + j] = __float2half_rn(hidden[b * H_ + j]);
            g_a1f[b * KCAT1 + H_ + j] = __float2half_rn(hidden[B_ * H_ + b * H_ + j]);
        }
    } else if (blk < P0 + 128) {
        long i = ((long)(blk - P0 - 64) * 256 + tid) * 4;
        float4 v = *reinterpret_cast<const float4*>(hidden + (long)B_ * H_ + i);
        __half2 h0 = __floats2half2_rn(v.x, v.y);
        __half2 h1 = __floats2half2_rn(v.z, v.w);
        uint2 o = {*reinterpret_cast<uint32_t*>(&h0), *reinterpret_cast<uint32_t*>(&h1)};
        *reinterpret_cast<uint2*>(g_h1f + i) = o;
    } else if (blk < P0 + 192) {
        long i = ((long)(blk - P0 - 128) * 256 + tid) * 4;
        float4 z = {0.f, 0.f, 0.f, 0.f};
        *reinterpret_cast<float4*>(query + i) = z;
    } else if (blk < P0 + 448) {
        long i = ((long)(blk - P0 - 192) * 256 + tid) * 4;
        int n = (int)(i & (G4H_ - 1));
        float4 o = {bih0[n] + bhh0[n], bih0[n + 1] + bhh0[n + 1],
                    bih0[n + 2] + bhh0[n + 2], bih0[n + 3] + bhh0[n + 3]};
        *reinterpret_cast<float4*>(gates0 + i) = o;
    } else if (blk < P0 + 704) {
        long i = ((long)(blk - P0 - 448) * 256 + tid) * 4;
        int n = (int)(i & (G4H_ - 1));
        float4 o = {bih1[n] + bhh1[n], bih1[n + 1] + bhh1[n + 1],
                    bih1[n + 2] + bhh1[n + 2], bih1[n + 3] + bhh1[n + 3]};
        *reinterpret_cast<float4*>(gates1 + i) = o;
    } else {
        long i = ((long)(blk - P0 - 704) * 1024 + tid * 4);
        int col = (int)(i % V_);
        float4 o = {bout[col], bout[col + 1], bout[col + 2], bout[col + 3]};
        *reinterpret_cast<float4*>(out_pred + i) = o;
    }
}

// ===================== global gather =========================================
__global__ void gather_kernel() {
    __shared__ int offs[B_ + 1];
    const int tid = threadIdx.x;
    if (tid == 0) {
        int acc = 0;
        for (int b = 0; b < B_; b++) { offs[b] = acc; acc += g_scnt[b]; }
        offs[B_] = acc;
        g_total = acc;
    }
    __syncthreads();
    for (int b = 0; b < B_; b++) {
        int o = offs[b], cnt = offs[b + 1] - o;
        for (int j = tid; j < cnt; j += 256)
            g_gidx[o + j] = b * S_ + g_sidx[b * S_ + j];
    }
    int total = offs[B_];
    for (int j = total + tid; j < B_ * S_; j += 256) g_gidx[j] = 0;
}

// ===================== fat-B HMMA kernel (fp16 2-term) =======================
// C[0:64, n0:n0+128] += (A[64,Ktot] @ (2048*Bcat)^T) / 2048
#define WO_A_TILE 8192
#define WO_B_TILE 16384
#define WO_STAGE  (WO_A_TILE + 2 * WO_B_TILE)   // 40KB
#define WO_SMEM_BYTES (1024 + 2 * WO_STAGE)

__device__ __forceinline__ void wo_load_A(const __half* f, int lda, int c0, uint32_t stg) {
    const int tid = threadIdx.x;
#pragma unroll
    for (int i = 0; i < 2; i++) {
        int idx = tid + i * 256;
        int r = idx >> 3, cc = idx & 7;
        uint32_t off = swz(r, cc);
        CP16(stg + off, f + (long)r * lda + c0 + cc * 8);
    }
}

template<bool ATOMIC>
__global__ __launch_bounds__(256, 2)
void hmma_m64_kernel(const __half* __restrict__ a_g,
                     int Ktot,
                     const float* __restrict__ B1, int k1,
                     const float* __restrict__ B2,
                     const float* __restrict__ bias1,
                     float* __restrict__ C, int ldc, int nks) {
    extern __shared__ char smem[];
    uint32_t sb = smem_to_u32(smem);
    uint32_t tiles = (sb + 1023) & ~1023u;

    const int tid = threadIdx.x;
    const int wid = tid >> 5, lane = tid & 31;
    const int warp_m = (wid & 1) * 32;
    const int warp_n = (wid >> 1) * 32;
    const int n0 = blockIdx.x * 128;

    const int br = tid >> 1;
    const int bhalf = tid & 1;
    const int k2 = Ktot - k1;

    const int KT = Ktot / 64;
    const int kt0 = (int)blockIdx.y * (KT / nks);
    const int kt1 = kt0 + KT / nks;

    auto bptr = [&](int c0) -> const float* {
        return (c0 < k1) ? B1 + (long)(n0 + br) * k1 + c0 + bhalf * 32
                         : B2 + (long)(n0 + br) * k2 + (c0 - k1) + bhalf * 32;
    };

    float c[2][4][4];
#pragma unroll
    for (int i = 0; i < 2; i++)
#pragma unroll
        for (int j = 0; j < 4; j++)
#pragma unroll
            for (int k = 0; k < 4; k++) c[i][j][k] = 0.f;

    wo_load_A(a_g, Ktot, kt0 * 64, tiles + (kt0 & 1) * WO_STAGE);
    CP_COMMIT();

    for (int kt = kt0; kt < kt1; kt++) {
        uint32_t stg = tiles + (kt & 1) * WO_STAGE;
        if (kt + 1 < kt1) {
            wo_load_A(a_g, Ktot, (kt + 1) * 64, tiles + ((kt + 1) & 1) * WO_STAGE);
            CP_COMMIT();
        }
        uint32_t Bh = stg + WO_A_TILE, Bl = Bh + WO_B_TILE;
        const float* w = bptr(kt * 64);
#pragma unroll
        for (int j = 0; j < 4; j++) {
            float4 v0 = *reinterpret_cast<const float4*>(w + j * 8);
            float4 v1 = *reinterpret_cast<const float4*>(w + j * 8 + 4);
            uint4 Hq, Lq;
            split2h(v0.x, v0.y, Hq.x, Lq.x);
            split2h(v0.z, v0.w, Hq.y, Lq.y);
            split2h(v1.x, v1.y, Hq.z, Lq.z);
            split2h(v1.z, v1.w, Hq.w, Lq.w);
            uint32_t off = swz(br, bhalf * 4 + j);
            STS128(Bh + off, Hq.x, Hq.y, Hq.z, Hq.w);
            STS128(Bl + off, Lq.x, Lq.y, Lq.z, Lq.w);
        }
        if (kt + 1 < kt1) cp_wait<1>(); else cp_wait<0>();
        __syncthreads();
        {
            const uint32_t Ah = stg;
            const int lm = lane & 15, lh = lane >> 4;
#pragma unroll
            for (int ks = 0; ks < 4; ks++) {
                const int ch = ks * 2 + lh;
                uint32_t ah[2][4];
#pragma unroll
                for (int mf = 0; mf < 2; mf++) {
                    uint32_t off = swz(warp_m + mf * 16 + lm, ch);
                    ldmx4(Ah + off, ah[mf]);
                }
                uint32_t bb[2][4];
#pragma unroll
                for (int nf2 = 0; nf2 < 2; nf2++) {
                    uint32_t off = swz(warp_n + nf2 * 16 + lm, ch);
                    ldmx4(Bh + off, bb[nf2]);
                }
#pragma unroll
                for (int nf2 = 0; nf2 < 2; nf2++)
#pragma unroll
                    for (int mf = 0; mf < 2; mf++) {
                        mma16816h(c[mf][nf2 * 2 + 0], ah[mf], bb[nf2][0], bb[nf2][2]);
                        mma16816h(c[mf][nf2 * 2 + 1], ah[mf], bb[nf2][1], bb[nf2][3]);
                    }
#pragma unroll
                for (int nf2 = 0; nf2 < 2; nf2++) {
                    uint32_t off = swz(warp_n + nf2 * 16 + lm, ch);
                    ldmx4(Bl + off, bb[nf2]);
                }
#pragma unroll
                for (int nf2 = 0; nf2 < 2; nf2++)
#pragma unroll
                    for (int mf = 0; mf < 2; mf++) {
                        mma16816h(c[mf][nf2 * 2 + 0], ah[mf], bb[nf2][0], bb[nf2][2]);
                        mma16816h(c[mf][nf2 * 2 + 1], ah[mf], bb[nf2][1], bb[nf2][3]);
                    }
            }
        }
        __syncthreads();
    }

#pragma unroll
    for (int mf = 0; mf < 2; mf++)
#pragma unroll
        for (int nf = 0; nf < 4; nf++) {
            int col = n0 + warp_n + nf * 8 + (lane & 3) * 2;
            int r0 = warp_m + mf * 16 + (lane >> 2);
            if (ATOMIC) {
                atomicAdd(&C[(long)r0 * ldc + col],           c[mf][nf][0] * INVWK);
                atomicAdd(&C[(long)r0 * ldc + col + 1],       c[mf][nf][1] * INVWK);
                atomicAdd(&C[(long)(r0 + 8) * ldc + col],     c[mf][nf][2] * INVWK);
                atomicAdd(&C[(long)(r0 + 8) * ldc + col + 1], c[mf][nf][3] * INVWK);
            } else {
                float b0 = 0.f, b1 = 0.f;
                if (bias1) { b0 = bias1[col]; b1 = bias1[col + 1]; }
                float2 o0 = {c[mf][nf][0] * INVWK + b0, c[mf][nf][1] * INVWK + b1};
                float2 o1 = {c[mf][nf][2] * INVWK + b0, c[mf][nf][3] * INVWK + b1};
                *reinterpret_cast<float2*>(C + (long)r0 * ldc + col) = o0;
                *reinterpret_cast<float2*>(C + (long)(r0 + 8) * ldc + col) = o1;
            }
        }
}

// ===================== energy: fp16 2-term, 256-row super-tiles ==============
#define EN_T 16384
#define EN_STAGE (4 * EN_T)
#define EN_SMEM_BYTES (2048 + 2 * EN_STAGE)

__global__ __launch_bounds__(256, 1)
void energy_f16_kernel(const __half* __restrict__ ef,
                       const __half* __restrict__ wh,
                       const __half* __restrict__ wl,
                       const float* __restrict__ vvec,
                       const float* __restrict__ query,
                       float* __restrict__ energy) {
    const int total = g_total;
    const int mt = (int)blockIdx.y * 256;
    if (mt >= total) return;

    extern __shared__ char smem[];
    uint32_t sb = smem_to_u32(smem);
    uint32_t tiles = (sb + 2048 + 1023) & ~1023u;

    const int tid = threadIdx.x;
    const int wid = tid >> 5, lane = tid & 31;
    const int warp_m = (wid & 3) * 32;
    const int warp_n = (wid >> 2) * 64;
    const int n0 = blockIdx.x * 128;

    float* vs = (float*)smem;
    int*   sid = (int*)(vs + 128);
    if (tid < 128) vs[tid] = vvec[n0 + tid];
    sid[tid] = g_gidx[mt + tid];
    __syncthreads();

    const int rb = tid >> 3, cc8 = (tid & 7) * 8;
    uint32_t a0off[4], a1off[4], boff[4], soffs[4];
#pragma unroll
    for (int i = 0; i < 4; i++) {
        int r = rb + 32 * i;
        soffs[i] = swz(r, tid & 7);
        a0off[i] = (uint32_t)sid[r] * ENC_ + cc8;
        a1off[i] = (uint32_t)sid[r + 128] * ENC_ + cc8;
        boff[i]  = (uint32_t)(n0 + r) * ENC_ + cc8;
    }

    float c0[2][8][4], c1[2][8][4];
#pragma unroll
    for (int i = 0; i < 2; i++)
#pragma unroll
        for (int j = 0; j < 8; j++)
#pragma unroll
            for (int k = 0; k < 4; k++) { c0[i][j][k] = 0.f; c1[i][j][k] = 0.f; }

    auto load_stage = [&](int c0v, uint32_t stg) {
#pragma unroll
        for (int i = 0; i < 4; i++) {
            CP16(stg + soffs[i],            ef + a0off[i] + c0v);
            CP16(stg + EN_T + soffs[i],     ef + a1off[i] + c0v);
            CP16(stg + 2 * EN_T + soffs[i], wh + boff[i] + c0v);
            CP16(stg + 3 * EN_T + soffs[i], wl + boff[i] + c0v);
        }
    };

    load_stage(0, tiles);
    CP_COMMIT();

    const int KT = ENC_ / 64;
    for (int kt = 0; kt < KT; kt++) {
        uint32_t stg = tiles + (kt & 1) * EN_STAGE;
        if (kt + 1 < KT) {
            load_stage((kt + 1) * 64, tiles + ((kt + 1) & 1) * EN_STAGE);
            CP_COMMIT();
            cp_wait<1>();
        } else {
            cp_wait<0>();
        }
        __syncthreads();
        {
            const uint32_t A0 = stg, A1 = stg + EN_T;
            const uint32_t Bh = stg + 2 * EN_T, Bl = stg + 3 * EN_T;
            const int lm = lane & 15, lh = lane >> 4;
#pragma unroll
            for (int ks = 0; ks < 4; ks++) {
                const int ch = ks * 2 + lh;
                uint32_t a0[2][4], a1[2][4];
#pragma unroll
                for (int mf = 0; mf < 2; mf++) {
                    uint32_t off = swz(warp_m + mf * 16 + lm, ch);
                    ldmx4(A0 + off, a0[mf]);
                    ldmx4(A1 + off, a1[mf]);
                }
                uint32_t bb[4][4];
#pragma unroll
                for (int nf2 = 0; nf2 < 4; nf2++) {
                    uint32_t off = swz(warp_n + nf2 * 16 + lm, ch);
                    ldmx4(Bh + off, bb[nf2]);
                }
#pragma unroll
                for (int nf2 = 0; nf2 < 4; nf2++)
#pragma unroll
                    for (int mf = 0; mf < 2; mf++) {
                        mma16816h(c0[mf][nf2 * 2 + 0], a0[mf], bb[nf2][0], bb[nf2][2]);
                        mma16816h(c0[mf][nf2 * 2 + 1], a0[mf], bb[nf2][1], bb[nf2][3]);
                        mma16816h(c1[mf][nf2 * 2 + 0], a1[mf], bb[nf2][0], bb[nf2][2]);
                        mma16816h(c1[mf][nf2 * 2 + 1], a1[mf], bb[nf2][1], bb[nf2][3]);
                    }
#pragma unroll
                for (int nf2 = 0; nf2 < 4; nf2++) {
                    uint32_t off = swz(warp_n + nf2 * 16 + lm, ch);
                    ldmx4(Bl + off, bb[nf2]);
                }
#pragma unroll
                for (int nf2 = 0; nf2 < 4; nf2++)
#pragma unroll
                    for (int mf = 0; mf < 2; mf++) {
                        mma16816h(c0[mf][nf2 * 2 + 0], a0[mf], bb[nf2][0], bb[nf2][2]);
                        mma16816h(c0[mf][nf2 * 2 + 1], a0[mf], bb[nf2][1], bb[nf2][3]);
                        mma16816h(c1[mf][nf2 * 2 + 0], a1[mf], bb[nf2][0], bb[nf2][2]);
                        mma16816h(c1[mf][nf2 * 2 + 1], a1[mf], bb[nf2][1], bb[nf2][3]);
                    }
            }
        }
        __syncthreads();
    }

#pragma unroll
    for (int t = 0; t < 2; t++) {
#pragma unroll
        for (int mf = 0; mf < 2; mf++) {
            int rl = t * 128 + warp_m + mf * 16 + (lane >> 2);
            int rh = rl + 8;
            int gl = sid[rl], gh = sid[rh];
            const float* ql = query + (long)(gl >> 8) * H_ + n0;
            const float* qh = query + (long)(gh >> 8) * H_ + n0;
            float s_lo = 0.f, s_hi = 0.f;
#pragma unroll
            for (int nf = 0; nf < 8; nf++) {
                int col = warp_n + nf * 8 + (lane & 3) * 2;
                float v0 = vs[col], v1 = vs[col + 1];
                float* cc = t ? c1[mf][nf] : c0[mf][nf];
                s_lo += v0 * tanhf(ql[col] + cc[0] * INVWK) + v1 * tanhf(ql[col + 1] + cc[1] * INVWK);
                s_hi += v0 * tanhf(qh[col] + cc[2] * INVWK) + v1 * tanhf(qh[col + 1] + cc[3] * INVWK);
            }
            s_lo += __shfl_xor_sync(0xffffffff, s_lo, 1);
            s_lo += __shfl_xor_sync(0xffffffff, s_lo, 2);
            s_hi += __shfl_xor_sync(0xffffffff, s_hi, 1);
            s_hi += __shfl_xor_sync(0xffffffff, s_hi, 2);
            if ((lane & 3) == 0) {
                if (mt + rl < total) atomicAdd(&energy[gl], s_lo);
                if (mt + rh < total) atomicAdd(&energy[gh], s_hi);
            }
        }
    }
}

// ===================== fused softmax + compacted context =====================
__global__ void softmax_context_kernel(const float* __restrict__ energy,
                                       const float* __restrict__ enc,
                                       float* __restrict__ out_attn) {
    __shared__ float red[256];
    __shared__ float w[256];
    __shared__ int sid[256];
    __shared__ int cnts;
    const int b = blockIdx.x;
    const int tid = threadIdx.x;

    float val = energy[b * S_ + tid];
    red[tid] = val;
    sid[tid] = g_sidx[b * S_ + tid];
    if (tid == 0) cnts = g_scnt[b];
    __syncthreads();
#pragma unroll
    for (int off = 128; off > 0; off >>= 1) {
        if (tid < off) red[tid] = fmaxf(red[tid], red[tid + off]);
        __syncthreads();
    }
    float mx = red[0];
    __syncthreads();
    float ex = expf(val - mx);
    red[tid] = ex;
    __syncthreads();
#pragma unroll
    for (int off = 128; off > 0; off >>= 1) {
        if (tid < off) red[tid] += red[tid + off];
        __syncthreads();
    }
    float aw = ex / red[0];
    if (blockIdx.y == 0) out_attn[b * S_ + tid] = aw;
    w[tid] = aw;
    __syncthreads();

    const int cnt = cnts;
    const int col = blockIdx.y * 256 + tid;
    const float* eb = enc + (long)b * S_ * ENC_;
    float a0 = 0.f, a1 = 0.f, a2 = 0.f, a3 = 0.f;
    int j = 0;
    for (; j + 4 <= cnt; j += 4) {
        a0 = fmaf(w[sid[j]],     eb[(long)sid[j] * ENC_ + col],     a0);
        a1 = fmaf(w[sid[j + 1]], eb[(long)sid[j + 1] * ENC_ + col], a1);
        a2 = fmaf(w[sid[j + 2]], eb[(long)sid[j + 2] * ENC_ + col], a2);
        a3 = fmaf(w[sid[j + 3]], eb[(long)sid[j + 3] * ENC_ + col], a3);
    }
    for (; j < cnt; j++)
        a0 = fmaf(w[sid[j]], eb[(long)sid[j] * ENC_ + col], a0);
    float acc = (a0 + a1) + (a2 + a3);
    __half hv = __float2half_rn(acc);
    g_a0f[b * KCAT0 + E_ + col] = hv;
    g_featf[b * FDIM_ + H_ + col] = hv;
}

// ===================== LSTM pointwise ========================================
__global__ void lstm_kernel(const float* __restrict__ gates,
                            const float* __restrict__ c_prev,
                            float* __restrict__ c_out,
                            float* __restrict__ h_out_f32,
                            __half* __restrict__ hb,
                            int sb) {
    const int b = blockIdx.x;
    const int idx = blockIdx.y * 256 + threadIdx.x;
    float gi = gates[b * G4H_ + idx];
    float gf = gates[b * G4H_ + H_ + idx];
    float gg = gates[b * G4H_ + 2 * H_ + idx];
    float go = gates[b * G4H_ + 3 * H_ + idx];
    float c  = c_prev[b * H_ + idx];
    float si = 1.f / (1.f + expf(-gi));
    float sf = 1.f / (1.f + expf(-gf));
    float so = 1.f / (1.f + expf(-go));
    float cn = sf * c + si * tanhf(gg);
    float hn = so * tanhf(cn);
    c_out[b * H_ + idx]     = cn;
    h_out_f32[b * H_ + idx] = hn;
    hb[b * sb + idx] = __float2half_rn(hn);
}

// ===================== launch ================================================
extern "C" void kernel_launch(void* const* d_in, const int* in_sizes, int n_in,
                              void* d_out, int out_size) {
    const int*   tok    = (const int*)  d_in[0];
    const float* hidden = (const float*)d_in[1];
    const float* cell   = (const float*)d_in[2];
    const float* enc    = (const float*)d_in[3];
    const int*   mask   = (const int*)  d_in[4];
    const float* emb    = (const float*)d_in[5];
    const float* Wq     = (const float*)d_in[6];
    const float* Wk     = (const float*)d_in[7];
    const float* v      = (const float*)d_in[8];
    const float* Wih0   = (const float*)d_in[9];
    const float* Whh0   = (const float*)d_in[10];
    const float* bih0   = (const float*)d_in[11];
    const float* bhh0   = (const float*)d_in[12];
    const float* Wih1   = (const float*)d_in[13];
    const float* Whh1   = (const float*)d_in[14];
    const float* bih1   = (const float*)d_in[15];
    const float* bhh1   = (const float*)d_in[16];
    const float* Wout   = (const float*)d_in[17];
    const float* bout   = (const float*)d_in[18];

    float* out      = (float*)d_out;
    float* out_pred = out;
    float* out_hid  = out + (long)B_ * V_;
    float* out_cell = out_hid + 2 * B_ * H_;
    float* out_attn = out_cell + 2 * B_ * H_;

    void* sp = nullptr;
    cudaGetSymbolAddress(&sp, g_scratch);
    float* scratch = (float*)sp;
    float* query  = scratch + OFF_QUERY;
    float* gates0 = scratch + OFF_GATES0;
    float* gates1 = scratch + OFF_GATES1;
    float* energy = scratch + OFF_ENERGY;

    void *p_ef, *p_wh, *p_wl, *p_h1, *p_a0, *p_a1, *p_ft;
    cudaGetSymbolAddress(&p_ef, g_enc_f16);
    cudaGetSymbolAddress(&p_wh, g_wk_h);
    cudaGetSymbolAddress(&p_wl, g_wk_l);
    cudaGetSymbolAddress(&p_h1, g_h1f);
    cudaGetSymbolAddress(&p_a0, g_a0f);
    cudaGetSymbolAddress(&p_a1, g_a1f);
    cudaGetSymbolAddress(&p_ft, g_featf);

    cudaFuncSetAttribute(hmma_m64_kernel<false>, cudaFuncAttributeMaxDynamicSharedMemorySize, WO_SMEM_BYTES);
    cudaFuncSetAttribute(hmma_m64_kernel<true>,  cudaFuncAttributeMaxDynamicSharedMemorySize, WO_SMEM_BYTES);
    cudaFuncSetAttribute(energy_f16_kernel,      cudaFuncAttributeMaxDynamicSharedMemorySize, EN_SMEM_BYTES);

    // 1. fused prep: enc/Wk fp16 conversion + mask compact + inits + scatters
    prep_kernel<<<PREP_BLKS, 256>>>(enc, Wk, mask, hidden, tok, emb,
                                    bih0, bhh0, bih1, bhh1, bout,
                                    energy, query, gates0, gates1, out_pred);

    // 2. global compaction
    gather_kernel<<<1, 256>>>();

    // 3. query = hidden[1] @ Wq^T (fp16 2-term, K-split 4, atomic)
    hmma_m64_kernel<true><<<dim3(H_ / 128, 4), 256, WO_SMEM_BYTES>>>(
        (const __half*)p_h1, H_, Wq, H_, Wq, nullptr, query, H_, 4);

    // 4. energy (fp16 2-term, 256-row super-tiles)
    energy_f16_kernel<<<dim3(H_ / 128, (B_ * S_) / 256), 256, EN_SMEM_BYTES>>>(
        (const __half*)p_ef, (const __half*)p_wh, (const __half*)p_wl,
        v, query, energy);

    // 5. fused masked softmax + compacted context
    softmax_context_kernel<<<dim3(B_, 4), 256>>>(energy, enc, out_attn);

    // 6. layer-0 gates + LSTM
    hmma_m64_kernel<true><<<dim3(G4H_ / 128, 4), 256, WO_SMEM_BYTES>>>(
        (const __half*)p_a0, KCAT0, Wih0, E_ + ENC_, Whh0, nullptr, gates0, G4H_, 4);
    lstm_kernel<<<dim3(B_, H_ / 256), 256>>>(gates0, cell, out_cell, out_hid,
                                             (__half*)p_a1, KCAT1);

    // 7. layer-1 gates + LSTM
    hmma_m64_kernel<true><<<dim3(G4H_ / 128, 4), 256, WO_SMEM_BYTES>>>(
        (const __half*)p_a1, KCAT1, Wih1, H_, Whh1, nullptr, gates1, G4H_, 4);
    lstm_kernel<<<dim3(B_, H_ / 256), 256>>>(gates1, cell + B_ * H_, out_cell + B_ * H_,
                                             out_hid + B_ * H_, (__half*)p_ft, FDIM_);

    // 8. prediction = feat @ Wout^T + bout (fp16 2-term, K-split 2, atomic)
    hmma_m64_kernel<true><<<dim3(V_ / 128, 2), 256, WO_SMEM_BYTES>>>(
        (const __half*)p_ft, FDIM_, Wout, FDIM_, Wout, nullptr, out_pred, V_, 2);
}